// round 2
// baseline (speedup 1.0000x reference)
#include <cuda_runtime.h>
#include <math.h>
#include <stdint.h>

// Problem constants
#define H_HEADS   16
#define KV_HEADS  4
#define DHEAD     128
#define LSEQ      2048
#define BATCH     2
#define HIDDEN    2048
#define QKV_COLS  3072      // 2048 q + 512 k + 512 v
#define WIN       512

// Intermediate scratch (allowed: __device__ globals, zero-init, no alloc)
__device__ float g_qkv [(size_t)BATCH * LSEQ * QKV_COLS];   // [B*L, 3072]
__device__ float g_attn[(size_t)BATCH * LSEQ * HIDDEN];     // [B*L, H*D]

// ---------------------------------------------------------------------------
// SGEMM (NT): C[m, n0+n] = sum_k A[m,k] * Brows[n,k]
// A: [M, K] row-major. Brows points at the 128 weight rows for this tile.
// 128x128 tile, BK=8, 256 threads, 8x8 microtile, register prefetch.
// ---------------------------------------------------------------------------
#define BM  128
#define BN  128
#define BKK 8

__device__ __forceinline__ void sgemm_tile(
    const float* __restrict__ A, const float* __restrict__ Brows,
    float* __restrict__ C, int K, int ldc, int bm, int n0)
{
    __shared__ float As[BKK][BM];
    __shared__ float Bs[BKK][BN];

    const int tid = threadIdx.x;
    const int lr  = tid >> 1;           // 0..127 tile row for loads
    const int lk  = (tid & 1) * 4;      // 0 or 4
    const int tx  = tid & 15;           // 0..15 col group
    const int ty  = tid >> 4;           // 0..15 row group

    const float* Ap = A     + (size_t)(bm + lr) * K + lk;
    const float* Bp = Brows + (size_t)lr * K + lk;

    float acc[8][8];
#pragma unroll
    for (int i = 0; i < 8; i++)
#pragma unroll
        for (int j = 0; j < 8; j++) acc[i][j] = 0.0f;

    const int nk = K / BKK;
    float4 a = *(const float4*)Ap;
    float4 b = *(const float4*)Bp;

    for (int kt = 0; kt < nk; kt++) {
        As[lk + 0][lr] = a.x; As[lk + 1][lr] = a.y;
        As[lk + 2][lr] = a.z; As[lk + 3][lr] = a.w;
        Bs[lk + 0][lr] = b.x; Bs[lk + 1][lr] = b.y;
        Bs[lk + 2][lr] = b.z; Bs[lk + 3][lr] = b.w;
        __syncthreads();

        if (kt + 1 < nk) {
            a = *(const float4*)(Ap + (size_t)(kt + 1) * BKK);
            b = *(const float4*)(Bp + (size_t)(kt + 1) * BKK);
        }

#pragma unroll
        for (int kk = 0; kk < BKK; kk++) {
            float ar[8], br[8];
            *(float4*)&ar[0] = *(const float4*)&As[kk][ty * 4];
            *(float4*)&ar[4] = *(const float4*)&As[kk][64 + ty * 4];
            *(float4*)&br[0] = *(const float4*)&Bs[kk][tx * 4];
            *(float4*)&br[4] = *(const float4*)&Bs[kk][64 + tx * 4];
#pragma unroll
            for (int i = 0; i < 8; i++)
#pragma unroll
                for (int j = 0; j < 8; j++)
                    acc[i][j] += ar[i] * br[j];
        }
        __syncthreads();
    }

#pragma unroll
    for (int i = 0; i < 8; i++) {
        int row = bm + ((i < 4) ? (ty * 4 + i) : (64 + ty * 4 + i - 4));
        float* cp = C + (size_t)row * ldc + n0;
        *(float4*)&cp[tx * 4]      = make_float4(acc[i][0], acc[i][1], acc[i][2], acc[i][3]);
        *(float4*)&cp[64 + tx * 4] = make_float4(acc[i][4], acc[i][5], acc[i][6], acc[i][7]);
    }
}

// Fused QKV projection: one launch, column tile selects Wq/Wk/Wv.
__global__ __launch_bounds__(256, 1)
void gemm_qkv_kernel(const float* __restrict__ x,
                     const float* __restrict__ Wq,
                     const float* __restrict__ Wk,
                     const float* __restrict__ Wv)
{
    int bm = blockIdx.x * BM;
    int n0 = blockIdx.y * BN;
    const float* B;
    if (n0 < 2048)      B = Wq + (size_t)n0 * HIDDEN;
    else if (n0 < 2560) B = Wk + (size_t)(n0 - 2048) * HIDDEN;
    else                B = Wv + (size_t)(n0 - 2560) * HIDDEN;
    sgemm_tile(x, B, g_qkv, HIDDEN, QKV_COLS, bm, n0);
}

// Output projection: d_out = g_attn @ Wo^T
__global__ __launch_bounds__(256, 1)
void gemm_o_kernel(const float* __restrict__ Wo, float* __restrict__ out)
{
    int bm = blockIdx.x * BM;
    int n0 = blockIdx.y * BN;
    sgemm_tile(g_attn, Wo + (size_t)n0 * HIDDEN, out, HIDDEN, HIDDEN, bm, n0);
}

// ---------------------------------------------------------------------------
// RMSNorm + RoPE (in-place on q and k heads of g_qkv)
// grid: (B*L, H+KV), 128 threads = one head vector
// ---------------------------------------------------------------------------
__global__ __launch_bounds__(128)
void normrope_kernel(const float* __restrict__ cosp, const float* __restrict__ sinp,
                     const float* __restrict__ qw,  const float* __restrict__ kw)
{
    int m = blockIdx.x;           // 0..B*L-1
    int e = blockIdx.y;           // 0..19 (16 q heads + 4 kv heads)
    int t = threadIdx.x;          // 0..127
    int l = m & (LSEQ - 1);

    float* p;
    const float* w;
    if (e < H_HEADS) { p = g_qkv + (size_t)m * QKV_COLS + e * DHEAD;        w = qw; }
    else             { p = g_qkv + (size_t)m * QKV_COLS + 2048 + (e - H_HEADS) * DHEAD; w = kw; }

    float v = p[t];
    float ss = v * v;
#pragma unroll
    for (int o = 16; o; o >>= 1) ss += __shfl_xor_sync(0xffffffffu, ss, o);

    __shared__ float sred[4];
    __shared__ float sval[128];
    if ((t & 31) == 0) sred[t >> 5] = ss;
    __syncthreads();
    ss = sred[0] + sred[1] + sred[2] + sred[3];

    float n = v * rsqrtf(ss * (1.0f / 128.0f) + 1e-6f) * w[t];
    sval[t] = n;
    __syncthreads();
    float rot = (t < 64) ? -sval[t + 64] : sval[t - 64];
    p[t] = n * cosp[l * DHEAD + t] + rot * sinp[l * DHEAD + t];
}

// ---------------------------------------------------------------------------
// Flash-style sliding-window attention.
// Block = (q_tile of 64, head, batch). 256 threads.
// Thread t: g = t/16 owns rows 4g..4g+3; u = t%16 owns cols {u, u+16} of each
// 32-key chunk and output dims {u + 16*dd}.
// ---------------------------------------------------------------------------
#define QT   64
#define KCH  32
#define PADQ 132
#define PADK 132
#define PADV 132
#define PADP 66
#define ATT_SMEM ((QT*PADQ + KCH*PADK + KCH*PADV + QT*PADP) * 4)

__global__ __launch_bounds__(256)
void attn_kernel()
{
    extern __shared__ float sm[];
    float* Qs = sm;
    float* Ks = Qs + QT * PADQ;
    float* Vs = Ks + KCH * PADK;
    float* Ps = Vs + KCH * PADV;

    const int qt = blockIdx.x, h = blockIdx.y, b = blockIdx.z;
    const int kvh = h >> 2;                 // H/KV = 4 (repeat_interleave)
    const int tid = threadIdx.x;
    const int g = tid >> 4, u = tid & 15;
    const int q0 = qt * QT;
    const float scale = 0.08838834764831845f;   // 1/sqrt(128)

    // Load Q tile (pre-scaled)
    const float* qbase = g_qkv + (size_t)(b * LSEQ + q0) * QKV_COLS + h * DHEAD;
#pragma unroll
    for (int i = 0; i < 8; i++) {
        int id = tid + i * 256;
        int r = id >> 5, d4 = (id & 31) << 2;
        float4 q = *(const float4*)(qbase + (size_t)r * QKV_COLS + d4);
        q.x *= scale; q.y *= scale; q.z *= scale; q.w *= scale;
        *(float4*)&Qs[r * PADQ + d4] = q;
    }

    float out[4][8];
    float m_i[4], l_i[4];
#pragma unroll
    for (int i = 0; i < 4; i++) {
        m_i[i] = -1e30f; l_i[i] = 0.0f;
#pragma unroll
        for (int d = 0; d < 8; d++) out[i][d] = 0.0f;
    }

    int kstart = q0 - WIN;       if (kstart < 0)    kstart = 0;
    int kend   = q0 + QT + WIN;  if (kend > LSEQ)   kend   = LSEQ;

    const float* kbase = g_qkv + (size_t)b * LSEQ * QKV_COLS + 2048 + kvh * DHEAD;
    const float* vbase = kbase + 512;

    for (int ks = kstart; ks < kend; ks += KCH) {
        __syncthreads();
        // Load K,V chunk (32 x 128)
#pragma unroll
        for (int i = 0; i < 4; i++) {
            int id = tid + i * 256;
            int c = id >> 5, d4 = (id & 31) << 2;
            size_t off = (size_t)(ks + c) * QKV_COLS + d4;
            *(float4*)&Ks[c * PADK + d4] = *(const float4*)(kbase + off);
            *(float4*)&Vs[c * PADV + d4] = *(const float4*)(vbase + off);
        }
        __syncthreads();

        // Scores: s[i][j] = Q[4g+i] . K[u + 16j]
        float s[4][2];
#pragma unroll
        for (int i = 0; i < 4; i++) { s[i][0] = 0.0f; s[i][1] = 0.0f; }
        const float* k0p = &Ks[u * PADK];
        const float* k1p = &Ks[(u + 16) * PADK];
#pragma unroll 8
        for (int kk = 0; kk < DHEAD; kk += 4) {
            float4 k0 = *(const float4*)(k0p + kk);
            float4 k1 = *(const float4*)(k1p + kk);
#pragma unroll
            for (int i = 0; i < 4; i++) {
                float4 q = *(const float4*)&Qs[(4 * g + i) * PADQ + kk];
                s[i][0] += q.x * k0.x + q.y * k0.y + q.z * k0.z + q.w * k0.w;
                s[i][1] += q.x * k1.x + q.y * k1.y + q.z * k1.z + q.w * k1.w;
            }
        }

        // Window mask + online softmax (reduce across the 16 u-lanes)
#pragma unroll
        for (int i = 0; i < 4; i++) {
            int qi  = q0 + 4 * g + i;
            int d0  = qi - (ks + u);      if (d0 < 0) d0 = -d0;
            int d1  = qi - (ks + u + 16); if (d1 < 0) d1 = -d1;
            float s0 = (d0 <= WIN) ? s[i][0] : -1e30f;
            float s1 = (d1 <= WIN) ? s[i][1] : -1e30f;
            float mx = fmaxf(s0, s1);
#pragma unroll
            for (int o = 1; o < 16; o <<= 1)
                mx = fmaxf(mx, __shfl_xor_sync(0xffffffffu, mx, o));
            float mnew = fmaxf(m_i[i], mx);
            float corr = __expf(m_i[i] - mnew);
            float p0 = (s0 > -9e29f) ? __expf(s0 - mnew) : 0.0f;
            float p1 = (s1 > -9e29f) ? __expf(s1 - mnew) : 0.0f;
            float rs = p0 + p1;
#pragma unroll
            for (int o = 1; o < 16; o <<= 1)
                rs += __shfl_xor_sync(0xffffffffu, rs, o);
            l_i[i] = l_i[i] * corr + rs;
            m_i[i] = mnew;
#pragma unroll
            for (int d = 0; d < 8; d++) out[i][d] *= corr;
            Ps[(4 * g + i) * PADP + u]      = p0;
            Ps[(4 * g + i) * PADP + u + 16] = p1;
        }
        __syncthreads();

        // out[r, d] += P[r, :] @ V[:, d]
#pragma unroll 4
        for (int c = 0; c < KCH; c++) {
            float p0 = Ps[(4 * g + 0) * PADP + c];
            float p1 = Ps[(4 * g + 1) * PADP + c];
            float p2 = Ps[(4 * g + 2) * PADP + c];
            float p3 = Ps[(4 * g + 3) * PADP + c];
#pragma unroll
            for (int d = 0; d < 8; d++) {
                float v = Vs[c * PADV + u + 16 * d];
                out[0][d] += p0 * v;
                out[1][d] += p1 * v;
                out[2][d] += p2 * v;
                out[3][d] += p3 * v;
            }
        }
    }

    // Normalize and write to g_attn in [B, L, H*D] layout (ready for O GEMM)
    float* obase = g_attn + (size_t)(b * LSEQ + q0) * HIDDEN + h * DHEAD;
#pragma unroll
    for (int i = 0; i < 4; i++) {
        float inv = 1.0f / l_i[i];
#pragma unroll
        for (int d = 0; d < 8; d++)
            obase[(size_t)(4 * g + i) * HIDDEN + u + 16 * d] = out[i][d] * inv;
    }
}

// ---------------------------------------------------------------------------
// Launch. Inputs (metadata order): x, cos, sin, Wq, Wk, Wv, Wo, q_norm_w, k_norm_w
// ---------------------------------------------------------------------------
extern "C" void kernel_launch(void* const* d_in, const int* in_sizes, int n_in,
                              void* d_out, int out_size)
{
    const float* x    = (const float*)d_in[0];
    const float* cosp = (const float*)d_in[1];
    const float* sinp = (const float*)d_in[2];
    const float* Wq   = (const float*)d_in[3];
    const float* Wk   = (const float*)d_in[4];
    const float* Wv   = (const float*)d_in[5];
    const float* Wo   = (const float*)d_in[6];
    const float* qw   = (const float*)d_in[7];
    const float* kw   = (const float*)d_in[8];
    float* out = (float*)d_out;

    // >48KB dynamic smem opt-in (non-stream API: executes immediately, not
    // captured; also runs during the harness's pre-capture correctness call)
    cudaFuncSetAttribute(attn_kernel, cudaFuncAttributeMaxDynamicSharedMemorySize, ATT_SMEM);

    // 1) Fused QKV projection: [4096,2048] @ [3072,2048]^T -> g_qkv
    gemm_qkv_kernel<<<dim3(BATCH * LSEQ / BM, QKV_COLS / BN), 256>>>(x, Wq, Wk, Wv);

    // 2) RMSNorm + RoPE on q and k heads (in place)
    normrope_kernel<<<dim3(BATCH * LSEQ, H_HEADS + KV_HEADS), 128>>>(cosp, sinp, qw, kw);

    // 3) Sliding-window flash attention -> g_attn
    attn_kernel<<<dim3(LSEQ / QT, H_HEADS, BATCH), 256, ATT_SMEM>>>();

    // 4) Output projection: g_attn @ Wo^T -> d_out
    gemm_o_kernel<<<dim3(BATCH * LSEQ / BM, HIDDEN / BN), 256>>>(Wo, out);
}

// round 7
// speedup vs baseline: 1.7398x; 1.7398x over previous
#include <cuda_runtime.h>
#include <cuda_bf16.h>
#include <math.h>
#include <stdint.h>

// Problem constants
#define H_HEADS   16
#define KV_HEADS  4
#define DHEAD     128
#define LSEQ      2048
#define BATCH     2
#define HIDDEN    2048
#define QKV_COLS  3072      // 2048 q + 512 k + 512 v
#define WIN       512
#define KDIM      2048      // GEMM K for both projections

// ---------------------------------------------------------------------------
// Scratch (device globals; no allocation)
// ---------------------------------------------------------------------------
__device__ float         g_qkv[(size_t)BATCH * LSEQ * QKV_COLS];   // fp32 [B*L, 3072]
__device__ __nv_bfloat16 g_xh [(size_t)BATCH * LSEQ * HIDDEN];     // x hi
__device__ __nv_bfloat16 g_xl [(size_t)BATCH * LSEQ * HIDDEN];     // x lo
__device__ __nv_bfloat16 g_wh [(size_t)QKV_COLS * HIDDEN];         // packed Wq|Wk|Wv hi
__device__ __nv_bfloat16 g_wl [(size_t)QKV_COLS * HIDDEN];
__device__ __nv_bfloat16 g_woh[(size_t)HIDDEN * HIDDEN];           // Wo hi
__device__ __nv_bfloat16 g_wol[(size_t)HIDDEN * HIDDEN];
__device__ __nv_bfloat16 g_ah [(size_t)BATCH * LSEQ * HIDDEN];     // attn out hi
__device__ __nv_bfloat16 g_al [(size_t)BATCH * LSEQ * HIDDEN];     // attn out lo

// ---------------------------------------------------------------------------
// Base-ISA PTX helpers (valid in compute_103: no 'a'-suffix features)
// ---------------------------------------------------------------------------
__device__ __forceinline__ uint32_t smem_u32(const void* p) {
    uint32_t r;
    asm("{ .reg .u64 t; cvta.to.shared.u64 t, %1; cvt.u32.u64 %0, t; }" : "=r"(r) : "l"(p));
    return r;
}
__device__ __forceinline__ void cpa16(uint32_t s, const void* g) {
    asm volatile("cp.async.cg.shared.global [%0], [%1], 16;" :: "r"(s), "l"(g));
}
#define CPA_COMMIT() asm volatile("cp.async.commit_group;" ::: "memory")
#define CPA_WAIT(n)  asm volatile("cp.async.wait_group %0;" :: "n"(n) : "memory")

__device__ __forceinline__ uint32_t swz(uint32_t o) { return o ^ ((o >> 3) & 0x70); }

__device__ __forceinline__ void ldmx4(uint32_t* r, uint32_t a) {
    asm volatile("ldmatrix.sync.aligned.m8n8.x4.shared.b16 {%0,%1,%2,%3}, [%4];"
        : "=r"(r[0]), "=r"(r[1]), "=r"(r[2]), "=r"(r[3]) : "r"(a));
}
__device__ __forceinline__ void mma_bf16(float* c, const uint32_t* a, const uint32_t* b) {
    asm volatile("mma.sync.aligned.m16n8k16.row.col.f32.bf16.bf16.f32 "
        "{%0,%1,%2,%3}, {%4,%5,%6,%7}, {%8,%9}, {%0,%1,%2,%3};"
        : "+f"(c[0]), "+f"(c[1]), "+f"(c[2]), "+f"(c[3])
        : "r"(a[0]), "r"(a[1]), "r"(a[2]), "r"(a[3]), "r"(b[0]), "r"(b[1]));
}

// ---------------------------------------------------------------------------
// Split-bf16 HMMA GEMM: C[m0..+127, n0..+127] = sum_k A[m,k]*B[n,k]
// D = Ah*Bh + Ah*Bl + Al*Bh, fp32 accumulate. K = 2048, BK = 64 bf16
// (128B SW128-swizzled rows), double-buffered cp.async.
// 8 warps (4x2); warp tile 32x64 = 2x8 m16n8k16 atoms.
// ---------------------------------------------------------------------------
#define GMT 128
#define GNT 128
#define GKC 64
#define GNKC (KDIM / GKC)            // 32
#define G_OFF_AH 0
#define G_OFF_AL 16384
#define G_OFF_BH 32768
#define G_OFF_BL 49152
#define G_STAGE  65536
#define GEMM_SMEM (2 * G_STAGE)

__global__ __launch_bounds__(256, 1)
void gemm_mma(const __nv_bfloat16* __restrict__ Ah, const __nv_bfloat16* __restrict__ Al,
              const __nv_bfloat16* __restrict__ Bh, const __nv_bfloat16* __restrict__ Bl,
              float* __restrict__ C, int ldc)
{
    extern __shared__ __align__(128) char dsm[];
    const uint32_t base = smem_u32(dsm);
    const int tid = threadIdx.x, lane = tid & 31, wid = tid >> 5;
    const int wm = wid & 3, wn = wid >> 2;
    const int m0 = blockIdx.x * GMT, n0 = blockIdx.y * GNT;

    // ldmatrix per-lane parameters (PTX ISA m16n8k16 fragment layouts)
    const int a_row = wm * 32 + (lane & 15);           // + i*16
    const int a_k   = (lane >> 4) * 8;                 // + ks*16
    const int b_rowg = (lane >> 4) * 8 + (lane & 7);   // row within n-pair
    const int b_k    = ((lane >> 3) & 1) * 8;          // + ks*16

    float acc[2][8][4];
#pragma unroll
    for (int i = 0; i < 2; i++)
#pragma unroll
        for (int j = 0; j < 8; j++)
#pragma unroll
            for (int q = 0; q < 4; q++) acc[i][j][q] = 0.0f;

    auto load_stage = [&](int kc, int s) {
        const uint32_t sb = base + s * G_STAGE;
#pragma unroll
        for (int i = 0; i < 4; i++) {
            int u = tid + 256 * i;
            int r = u >> 3, cu = u & 7;
            uint32_t so = swz((uint32_t)(r * 128 + cu * 16));
            size_t ga = ((size_t)(m0 + r) << 11) + (kc << 6) + (cu << 3);
            size_t gb = ((size_t)(n0 + r) << 11) + (kc << 6) + (cu << 3);
            cpa16(sb + G_OFF_AH + so, Ah + ga);
            cpa16(sb + G_OFF_AL + so, Al + ga);
            cpa16(sb + G_OFF_BH + so, Bh + gb);
            cpa16(sb + G_OFF_BL + so, Bl + gb);
        }
        CPA_COMMIT();
    };

    load_stage(0, 0);

    for (int kc = 0; kc < GNKC; kc++) {
        if (kc + 1 < GNKC) { load_stage(kc + 1, (kc + 1) & 1); CPA_WAIT(1); }
        else               { CPA_WAIT(0); }
        __syncthreads();

        const uint32_t sb = base + (kc & 1) * G_STAGE;
        const uint32_t ah_b = sb + G_OFF_AH, al_b = sb + G_OFF_AL;
        const uint32_t bh_b = sb + G_OFF_BH, bl_b = sb + G_OFF_BL;

#pragma unroll
        for (int ks = 0; ks < 4; ks++) {
            uint32_t afh[2][4], afl[2][4];
#pragma unroll
            for (int i = 0; i < 2; i++) {
                uint32_t off = swz((uint32_t)((a_row + i * 16) * 128 + (a_k + ks * 16) * 2));
                ldmx4(afh[i], ah_b + off);
                ldmx4(afl[i], al_b + off);
            }
            uint32_t bfh[4][4], bfl[4][4];   // [jp][4] = {b0(j=2jp), b1(2jp), b0(2jp+1), b1(2jp+1)}
#pragma unroll
            for (int jp = 0; jp < 4; jp++) {
                int nrow = wn * 64 + jp * 16 + b_rowg;
                uint32_t off = swz((uint32_t)(nrow * 128 + (b_k + ks * 16) * 2));
                ldmx4(bfh[jp], bh_b + off);
                ldmx4(bfl[jp], bl_b + off);
            }
#pragma unroll
            for (int i = 0; i < 2; i++)
#pragma unroll
                for (int j = 0; j < 8; j++) {
                    const uint32_t* bh = &bfh[j >> 1][(j & 1) * 2];
                    const uint32_t* bl = &bfl[j >> 1][(j & 1) * 2];
                    mma_bf16(acc[i][j], afh[i], bh);   // Ah*Bh
                    mma_bf16(acc[i][j], afh[i], bl);   // Ah*Bl
                    mma_bf16(acc[i][j], afl[i], bh);   // Al*Bh
                }
        }
        __syncthreads();
    }

    // Epilogue: C fragment layout c0,c1 = (row t/4, col 2(t%4)+{0,1}); c2,c3 row+8
#pragma unroll
    for (int i = 0; i < 2; i++) {
        int row = m0 + wm * 32 + i * 16 + (lane >> 2);
#pragma unroll
        for (int j = 0; j < 8; j++) {
            int col = n0 + wn * 64 + j * 8 + 2 * (lane & 3);
            *(float2*)&C[(size_t)row * ldc + col]       = make_float2(acc[i][j][0], acc[i][j][1]);
            *(float2*)&C[(size_t)(row + 8) * ldc + col] = make_float2(acc[i][j][2], acc[i][j][3]);
        }
    }
}

// ---------------------------------------------------------------------------
// fp32 -> (bf16 hi, bf16 lo) split conversion, 4 elements/thread
// ---------------------------------------------------------------------------
__device__ __forceinline__ unsigned pk2(__nv_bfloat16 a, __nv_bfloat16 b) {
    __nv_bfloat162 t = __halves2bfloat162(a, b);
    return *reinterpret_cast<unsigned*>(&t);
}
__global__ __launch_bounds__(256)
void cvt_split(const float4* __restrict__ src, uint2* __restrict__ hi,
               uint2* __restrict__ lo, int n4)
{
    int i = blockIdx.x * 256 + threadIdx.x;
    if (i >= n4) return;
    float4 v = src[i];
    __nv_bfloat16 h0 = __float2bfloat16(v.x), h1 = __float2bfloat16(v.y);
    __nv_bfloat16 h2 = __float2bfloat16(v.z), h3 = __float2bfloat16(v.w);
    __nv_bfloat16 l0 = __float2bfloat16(v.x - __bfloat162float(h0));
    __nv_bfloat16 l1 = __float2bfloat16(v.y - __bfloat162float(h1));
    __nv_bfloat16 l2 = __float2bfloat16(v.z - __bfloat162float(h2));
    __nv_bfloat16 l3 = __float2bfloat16(v.w - __bfloat162float(h3));
    hi[i] = make_uint2(pk2(h0, h1), pk2(h2, h3));
    lo[i] = make_uint2(pk2(l0, l1), pk2(l2, l3));
}

// ---------------------------------------------------------------------------
// RMSNorm + RoPE (in-place on q and k heads of g_qkv)
// ---------------------------------------------------------------------------
__global__ __launch_bounds__(128)
void normrope_kernel(const float* __restrict__ cosp, const float* __restrict__ sinp,
                     const float* __restrict__ qw,  const float* __restrict__ kw)
{
    int m = blockIdx.x;
    int e = blockIdx.y;
    int t = threadIdx.x;
    int l = m & (LSEQ - 1);

    float* p;
    const float* w;
    if (e < H_HEADS) { p = g_qkv + (size_t)m * QKV_COLS + e * DHEAD; w = qw; }
    else { p = g_qkv + (size_t)m * QKV_COLS + 2048 + (e - H_HEADS) * DHEAD; w = kw; }

    float v = p[t];
    float ss = v * v;
#pragma unroll
    for (int o = 16; o; o >>= 1) ss += __shfl_xor_sync(0xffffffffu, ss, o);

    __shared__ float sred[4];
    __shared__ float sval[128];
    if ((t & 31) == 0) sred[t >> 5] = ss;
    __syncthreads();
    ss = sred[0] + sred[1] + sred[2] + sred[3];

    float n = v * rsqrtf(ss * (1.0f / 128.0f) + 1e-6f) * w[t];
    sval[t] = n;
    __syncthreads();
    float rot = (t < 64) ? -sval[t + 64] : sval[t - 64];
    p[t] = n * cosp[l * DHEAD + t] + rot * sinp[l * DHEAD + t];
}

// ---------------------------------------------------------------------------
// Sliding-window flash attention (fp32 SIMT), writes bf16 hi/lo for O-GEMM
// ---------------------------------------------------------------------------
#define QT   64
#define KCH  32
#define PADQ 132
#define PADK 132
#define PADV 132
#define PADP 66
#define ATT_SMEM ((QT*PADQ + KCH*PADK + KCH*PADV + QT*PADP) * 4)

__global__ __launch_bounds__(256)
void attn_kernel()
{
    extern __shared__ float sm[];
    float* Qs = sm;
    float* Ks = Qs + QT * PADQ;
    float* Vs = Ks + KCH * PADK;
    float* Ps = Vs + KCH * PADV;

    const int qt = blockIdx.x, h = blockIdx.y, b = blockIdx.z;
    const int kvh = h >> 2;
    const int tid = threadIdx.x;
    const int g = tid >> 4, u = tid & 15;
    const int q0 = qt * QT;
    const float scale = 0.08838834764831845f;

    const float* qbase = g_qkv + (size_t)(b * LSEQ + q0) * QKV_COLS + h * DHEAD;
#pragma unroll
    for (int i = 0; i < 8; i++) {
        int id = tid + i * 256;
        int r = id >> 5, d4 = (id & 31) << 2;
        float4 q = *(const float4*)(qbase + (size_t)r * QKV_COLS + d4);
        q.x *= scale; q.y *= scale; q.z *= scale; q.w *= scale;
        *(float4*)&Qs[r * PADQ + d4] = q;
    }

    float out[4][8];
    float m_i[4], l_i[4];
#pragma unroll
    for (int i = 0; i < 4; i++) {
        m_i[i] = -1e30f; l_i[i] = 0.0f;
#pragma unroll
        for (int d = 0; d < 8; d++) out[i][d] = 0.0f;
    }

    int kstart = q0 - WIN;      if (kstart < 0)  kstart = 0;
    int kend   = q0 + QT + WIN; if (kend > LSEQ) kend = LSEQ;

    const float* kbase = g_qkv + (size_t)b * LSEQ * QKV_COLS + 2048 + kvh * DHEAD;
    const float* vbase = kbase + 512;

    for (int ks = kstart; ks < kend; ks += KCH) {
        __syncthreads();
#pragma unroll
        for (int i = 0; i < 4; i++) {
            int id = tid + i * 256;
            int c = id >> 5, d4 = (id & 31) << 2;
            size_t off = (size_t)(ks + c) * QKV_COLS + d4;
            *(float4*)&Ks[c * PADK + d4] = *(const float4*)(kbase + off);
            *(float4*)&Vs[c * PADV + d4] = *(const float4*)(vbase + off);
        }
        __syncthreads();

        float s[4][2];
#pragma unroll
        for (int i = 0; i < 4; i++) { s[i][0] = 0.0f; s[i][1] = 0.0f; }
        const float* k0p = &Ks[u * PADK];
        const float* k1p = &Ks[(u + 16) * PADK];
#pragma unroll 8
        for (int kk = 0; kk < DHEAD; kk += 4) {
            float4 k0 = *(const float4*)(k0p + kk);
            float4 k1 = *(const float4*)(k1p + kk);
#pragma unroll
            for (int i = 0; i < 4; i++) {
                float4 q = *(const float4*)&Qs[(4 * g + i) * PADQ + kk];
                s[i][0] += q.x * k0.x + q.y * k0.y + q.z * k0.z + q.w * k0.w;
                s[i][1] += q.x * k1.x + q.y * k1.y + q.z * k1.z + q.w * k1.w;
            }
        }

#pragma unroll
        for (int i = 0; i < 4; i++) {
            int qi = q0 + 4 * g + i;
            int d0 = qi - (ks + u);      if (d0 < 0) d0 = -d0;
            int d1 = qi - (ks + u + 16); if (d1 < 0) d1 = -d1;
            float s0 = (d0 <= WIN) ? s[i][0] : -1e30f;
            float s1 = (d1 <= WIN) ? s[i][1] : -1e30f;
            float mx = fmaxf(s0, s1);
#pragma unroll
            for (int o = 1; o < 16; o <<= 1)
                mx = fmaxf(mx, __shfl_xor_sync(0xffffffffu, mx, o));
            float mnew = fmaxf(m_i[i], mx);
            float corr = __expf(m_i[i] - mnew);
            float p0 = (s0 > -9e29f) ? __expf(s0 - mnew) : 0.0f;
            float p1 = (s1 > -9e29f) ? __expf(s1 - mnew) : 0.0f;
            float rs = p0 + p1;
#pragma unroll
            for (int o = 1; o < 16; o <<= 1)
                rs += __shfl_xor_sync(0xffffffffu, rs, o);
            l_i[i] = l_i[i] * corr + rs;
            m_i[i] = mnew;
#pragma unroll
            for (int d = 0; d < 8; d++) out[i][d] *= corr;
            Ps[(4 * g + i) * PADP + u]      = p0;
            Ps[(4 * g + i) * PADP + u + 16] = p1;
        }
        __syncthreads();

#pragma unroll 4
        for (int c = 0; c < KCH; c++) {
            float p0 = Ps[(4 * g + 0) * PADP + c];
            float p1 = Ps[(4 * g + 1) * PADP + c];
            float p2 = Ps[(4 * g + 2) * PADP + c];
            float p3 = Ps[(4 * g + 3) * PADP + c];
#pragma unroll
            for (int d = 0; d < 8; d++) {
                float v = Vs[c * PADV + u + 16 * d];
                out[0][d] += p0 * v;
                out[1][d] += p1 * v;
                out[2][d] += p2 * v;
                out[3][d] += p3 * v;
            }
        }
    }

    // Split-bf16 epilogue straight into the O-GEMM A-operand
#pragma unroll
    for (int i = 0; i < 4; i++) {
        float inv = 1.0f / l_i[i];
        size_t rb = (size_t)(b * LSEQ + q0 + 4 * g + i) * HIDDEN + h * DHEAD;
#pragma unroll
        for (int d = 0; d < 8; d++) {
            float o = out[i][d] * inv;
            __nv_bfloat16 hh = __float2bfloat16(o);
            g_ah[rb + u + 16 * d] = hh;
            g_al[rb + u + 16 * d] = __float2bfloat16(o - __bfloat162float(hh));
        }
    }
}

// ---------------------------------------------------------------------------
// Launch. Inputs: x, cos, sin, Wq, Wk, Wv, Wo, q_norm_w, k_norm_w
// ---------------------------------------------------------------------------
extern "C" void kernel_launch(void* const* d_in, const int* in_sizes, int n_in,
                              void* d_out, int out_size)
{
    const float* x    = (const float*)d_in[0];
    const float* cosp = (const float*)d_in[1];
    const float* sinp = (const float*)d_in[2];
    const float* Wq   = (const float*)d_in[3];
    const float* Wk   = (const float*)d_in[4];
    const float* Wv   = (const float*)d_in[5];
    const float* Wo   = (const float*)d_in[6];
    const float* qw   = (const float*)d_in[7];
    const float* kw   = (const float*)d_in[8];
    float* out = (float*)d_out;

    // Resolve device-global addresses (host API; capture-safe, no allocation)
    void *p_qkv, *p_xh, *p_xl, *p_wh, *p_wl, *p_woh, *p_wol, *p_ah, *p_al;
    cudaGetSymbolAddress(&p_qkv, g_qkv);
    cudaGetSymbolAddress(&p_xh,  g_xh);  cudaGetSymbolAddress(&p_xl,  g_xl);
    cudaGetSymbolAddress(&p_wh,  g_wh);  cudaGetSymbolAddress(&p_wl,  g_wl);
    cudaGetSymbolAddress(&p_woh, g_woh); cudaGetSymbolAddress(&p_wol, g_wol);
    cudaGetSymbolAddress(&p_ah,  g_ah);  cudaGetSymbolAddress(&p_al,  g_al);

    cudaFuncSetAttribute(gemm_mma, cudaFuncAttributeMaxDynamicSharedMemorySize, GEMM_SMEM);
    cudaFuncSetAttribute(attn_kernel, cudaFuncAttributeMaxDynamicSharedMemorySize, ATT_SMEM);

    // 1) split conversions (x and weights)
    // NOTE: hi/lo pointers are uint2*; one uint2 = 4 bf16 elements, so a
    // region starting at element row*HIDDEN begins at uint2 offset row*HIDDEN/4.
    {
        int n4 = BATCH * LSEQ * HIDDEN / 4;
        cvt_split<<<(n4 + 255) / 256, 256>>>((const float4*)x, (uint2*)p_xh, (uint2*)p_xl, n4);
    }
    {
        int n4 = 2048 * HIDDEN / 4;   // Wq rows 0..2047
        cvt_split<<<(n4 + 255) / 256, 256>>>((const float4*)Wq, (uint2*)p_wh, (uint2*)p_wl, n4);
    }
    {
        int n4 = 512 * HIDDEN / 4;    // Wk rows 2048..2559
        size_t off = (size_t)2048 * HIDDEN / 4;  // uint2 units (4 bf16 each)
        cvt_split<<<(n4 + 255) / 256, 256>>>((const float4*)Wk, (uint2*)p_wh + off, (uint2*)p_wl + off, n4);
    }
    {
        int n4 = 512 * HIDDEN / 4;    // Wv rows 2560..3071
        size_t off = (size_t)2560 * HIDDEN / 4;  // uint2 units (4 bf16 each)
        cvt_split<<<(n4 + 255) / 256, 256>>>((const float4*)Wv, (uint2*)p_wh + off, (uint2*)p_wl + off, n4);
    }
    {
        int n4 = HIDDEN * HIDDEN / 4; // Wo
        cvt_split<<<(n4 + 255) / 256, 256>>>((const float4*)Wo, (uint2*)p_woh, (uint2*)p_wol, n4);
    }

    // 2) QKV projection on HMMA tensor cores -> g_qkv (fp32)
    gemm_mma<<<dim3(BATCH * LSEQ / GMT, QKV_COLS / GNT), 256, GEMM_SMEM>>>(
        (const __nv_bfloat16*)p_xh, (const __nv_bfloat16*)p_xl,
        (const __nv_bfloat16*)p_wh, (const __nv_bfloat16*)p_wl,
        (float*)p_qkv, QKV_COLS);

    // 3) RMSNorm + RoPE (in place, fp32)
    normrope_kernel<<<dim3(BATCH * LSEQ, H_HEADS + KV_HEADS), 128>>>(cosp, sinp, qw, kw);

    // 4) Sliding-window flash attention -> g_ah/g_al (split bf16)
    attn_kernel<<<dim3(LSEQ / QT, H_HEADS, BATCH), 256, ATT_SMEM>>>();

    // 5) Output projection on HMMA tensor cores -> d_out
    gemm_mma<<<dim3(BATCH * LSEQ / GMT, HIDDEN / GNT), 256, GEMM_SMEM>>>(
        (const __nv_bfloat16*)p_ah, (const __nv_bfloat16*)p_al,
        (const __nv_bfloat16*)p_woh, (const __nv_bfloat16*)p_wol,
        out, HIDDEN);
}

// round 8
// speedup vs baseline: 2.9987x; 1.7236x over previous
#include <cuda_runtime.h>
#include <cuda_bf16.h>
#include <math.h>
#include <stdint.h>

// Problem constants
#define H_HEADS   16
#define KV_HEADS  4
#define DHEAD     128
#define LSEQ      2048
#define BATCH     2
#define HIDDEN    2048
#define QKV_COLS  3072      // 2048 q + 512 k + 512 v
#define WIN       512
#define KDIM      2048

// ---------------------------------------------------------------------------
// Scratch (device globals; no allocation)
// ---------------------------------------------------------------------------
__device__ float         g_qkv[(size_t)BATCH * LSEQ * QKV_COLS];   // fp32 [B*L, 3072]
__device__ __nv_bfloat16 g_xh [(size_t)BATCH * LSEQ * HIDDEN];
__device__ __nv_bfloat16 g_xl [(size_t)BATCH * LSEQ * HIDDEN];
__device__ __nv_bfloat16 g_wh [(size_t)QKV_COLS * HIDDEN];
__device__ __nv_bfloat16 g_wl [(size_t)QKV_COLS * HIDDEN];
__device__ __nv_bfloat16 g_woh[(size_t)HIDDEN * HIDDEN];
__device__ __nv_bfloat16 g_wol[(size_t)HIDDEN * HIDDEN];
__device__ __nv_bfloat16 g_ah [(size_t)BATCH * LSEQ * HIDDEN];
__device__ __nv_bfloat16 g_al [(size_t)BATCH * LSEQ * HIDDEN];
// Attention operands (bf16 hi/lo)
__device__ __nv_bfloat16 g_qh [(size_t)BATCH * H_HEADS  * LSEQ * DHEAD];  // [b][h][l][d], pre-scaled
__device__ __nv_bfloat16 g_ql [(size_t)BATCH * H_HEADS  * LSEQ * DHEAD];
__device__ __nv_bfloat16 g_kh [(size_t)BATCH * KV_HEADS * LSEQ * DHEAD];  // [b][kvh][l][d]
__device__ __nv_bfloat16 g_kl [(size_t)BATCH * KV_HEADS * LSEQ * DHEAD];
__device__ __nv_bfloat16 g_vth[(size_t)BATCH * KV_HEADS * DHEAD * LSEQ];  // [b][kvh][d][l]  (transposed)
__device__ __nv_bfloat16 g_vtl[(size_t)BATCH * KV_HEADS * DHEAD * LSEQ];

// ---------------------------------------------------------------------------
// Base-ISA PTX helpers
// ---------------------------------------------------------------------------
__device__ __forceinline__ uint32_t smem_u32(const void* p) {
    uint32_t r;
    asm("{ .reg .u64 t; cvta.to.shared.u64 t, %1; cvt.u32.u64 %0, t; }" : "=r"(r) : "l"(p));
    return r;
}
__device__ __forceinline__ void cpa16(uint32_t s, const void* g) {
    asm volatile("cp.async.cg.shared.global [%0], [%1], 16;" :: "r"(s), "l"(g));
}
#define CPA_COMMIT() asm volatile("cp.async.commit_group;" ::: "memory")
#define CPA_WAIT(n)  asm volatile("cp.async.wait_group %0;" :: "n"(n) : "memory")

__device__ __forceinline__ uint32_t swz(uint32_t o) { return o ^ ((o >> 3) & 0x70); }

__device__ __forceinline__ void ldmx4(uint32_t* r, uint32_t a) {
    asm volatile("ldmatrix.sync.aligned.m8n8.x4.shared.b16 {%0,%1,%2,%3}, [%4];"
        : "=r"(r[0]), "=r"(r[1]), "=r"(r[2]), "=r"(r[3]) : "r"(a));
}
__device__ __forceinline__ void mma_bf16(float* c, const uint32_t* a, const uint32_t* b) {
    asm volatile("mma.sync.aligned.m16n8k16.row.col.f32.bf16.bf16.f32 "
        "{%0,%1,%2,%3}, {%4,%5,%6,%7}, {%8,%9}, {%0,%1,%2,%3};"
        : "+f"(c[0]), "+f"(c[1]), "+f"(c[2]), "+f"(c[3])
        : "r"(a[0]), "r"(a[1]), "r"(a[2]), "r"(a[3]), "r"(b[0]), "r"(b[1]));
}
__device__ __forceinline__ unsigned pk2(__nv_bfloat16 a, __nv_bfloat16 b) {
    __nv_bfloat162 t = __halves2bfloat162(a, b);
    return *reinterpret_cast<unsigned*>(&t);
}

// ---------------------------------------------------------------------------
// Split-bf16 HMMA GEMM (proven R7): C = A*B^T, D = Ah*Bh + Ah*Bl + Al*Bh
// ---------------------------------------------------------------------------
#define GMT 128
#define GNT 128
#define GNKC (KDIM / 64)
#define G_OFF_AH 0
#define G_OFF_AL 16384
#define G_OFF_BH 32768
#define G_OFF_BL 49152
#define G_STAGE  65536
#define GEMM_SMEM (2 * G_STAGE)

__global__ __launch_bounds__(256, 1)
void gemm_mma(const __nv_bfloat16* __restrict__ Ah, const __nv_bfloat16* __restrict__ Al,
              const __nv_bfloat16* __restrict__ Bh, const __nv_bfloat16* __restrict__ Bl,
              float* __restrict__ C, int ldc)
{
    extern __shared__ __align__(128) char dsm[];
    const uint32_t base = smem_u32(dsm);
    const int tid = threadIdx.x, lane = tid & 31, wid = tid >> 5;
    const int wm = wid & 3, wn = wid >> 2;
    const int m0 = blockIdx.x * GMT, n0 = blockIdx.y * GNT;

    const int a_row = wm * 32 + (lane & 15);
    const int a_k   = (lane >> 4) * 8;
    const int b_rowg = (lane >> 4) * 8 + (lane & 7);
    const int b_k    = ((lane >> 3) & 1) * 8;

    float acc[2][8][4];
#pragma unroll
    for (int i = 0; i < 2; i++)
#pragma unroll
        for (int j = 0; j < 8; j++)
#pragma unroll
            for (int q = 0; q < 4; q++) acc[i][j][q] = 0.0f;

    auto load_stage = [&](int kc, int s) {
        const uint32_t sb = base + s * G_STAGE;
#pragma unroll
        for (int i = 0; i < 4; i++) {
            int u = tid + 256 * i;
            int r = u >> 3, cu = u & 7;
            uint32_t so = swz((uint32_t)(r * 128 + cu * 16));
            size_t ga = ((size_t)(m0 + r) << 11) + (kc << 6) + (cu << 3);
            size_t gb = ((size_t)(n0 + r) << 11) + (kc << 6) + (cu << 3);
            cpa16(sb + G_OFF_AH + so, Ah + ga);
            cpa16(sb + G_OFF_AL + so, Al + ga);
            cpa16(sb + G_OFF_BH + so, Bh + gb);
            cpa16(sb + G_OFF_BL + so, Bl + gb);
        }
        CPA_COMMIT();
    };

    load_stage(0, 0);

    for (int kc = 0; kc < GNKC; kc++) {
        if (kc + 1 < GNKC) { load_stage(kc + 1, (kc + 1) & 1); CPA_WAIT(1); }
        else               { CPA_WAIT(0); }
        __syncthreads();

        const uint32_t sb = base + (kc & 1) * G_STAGE;
        const uint32_t ah_b = sb + G_OFF_AH, al_b = sb + G_OFF_AL;
        const uint32_t bh_b = sb + G_OFF_BH, bl_b = sb + G_OFF_BL;

#pragma unroll
        for (int ks = 0; ks < 4; ks++) {
            uint32_t afh[2][4], afl[2][4];
#pragma unroll
            for (int i = 0; i < 2; i++) {
                uint32_t off = swz((uint32_t)((a_row + i * 16) * 128 + (a_k + ks * 16) * 2));
                ldmx4(afh[i], ah_b + off);
                ldmx4(afl[i], al_b + off);
            }
            uint32_t bfh[4][4], bfl[4][4];
#pragma unroll
            for (int jp = 0; jp < 4; jp++) {
                int nrow = wn * 64 + jp * 16 + b_rowg;
                uint32_t off = swz((uint32_t)(nrow * 128 + (b_k + ks * 16) * 2));
                ldmx4(bfh[jp], bh_b + off);
                ldmx4(bfl[jp], bl_b + off);
            }
#pragma unroll
            for (int i = 0; i < 2; i++)
#pragma unroll
                for (int j = 0; j < 8; j++) {
                    const uint32_t* bh = &bfh[j >> 1][(j & 1) * 2];
                    const uint32_t* bl = &bfl[j >> 1][(j & 1) * 2];
                    mma_bf16(acc[i][j], afh[i], bh);
                    mma_bf16(acc[i][j], afh[i], bl);
                    mma_bf16(acc[i][j], afl[i], bh);
                }
        }
        __syncthreads();
    }

#pragma unroll
    for (int i = 0; i < 2; i++) {
        int row = m0 + wm * 32 + i * 16 + (lane >> 2);
#pragma unroll
        for (int j = 0; j < 8; j++) {
            int col = n0 + wn * 64 + j * 8 + 2 * (lane & 3);
            *(float2*)&C[(size_t)row * ldc + col]       = make_float2(acc[i][j][0], acc[i][j][1]);
            *(float2*)&C[(size_t)(row + 8) * ldc + col] = make_float2(acc[i][j][2], acc[i][j][3]);
        }
    }
}

// ---------------------------------------------------------------------------
// fp32 -> (bf16 hi, lo) split conversion
// ---------------------------------------------------------------------------
__global__ __launch_bounds__(256)
void cvt_split(const float4* __restrict__ src, uint2* __restrict__ hi,
               uint2* __restrict__ lo, int n4)
{
    int i = blockIdx.x * 256 + threadIdx.x;
    if (i >= n4) return;
    float4 v = src[i];
    __nv_bfloat16 h0 = __float2bfloat16(v.x), h1 = __float2bfloat16(v.y);
    __nv_bfloat16 h2 = __float2bfloat16(v.z), h3 = __float2bfloat16(v.w);
    __nv_bfloat16 l0 = __float2bfloat16(v.x - __bfloat162float(h0));
    __nv_bfloat16 l1 = __float2bfloat16(v.y - __bfloat162float(h1));
    __nv_bfloat16 l2 = __float2bfloat16(v.z - __bfloat162float(h2));
    __nv_bfloat16 l3 = __float2bfloat16(v.w - __bfloat162float(h3));
    hi[i] = make_uint2(pk2(h0, h1), pk2(h2, h3));
    lo[i] = make_uint2(pk2(l0, l1), pk2(l2, l3));
}

// ---------------------------------------------------------------------------
// RMSNorm + RoPE -> split-bf16 Q (pre-scaled) and K, [b][head][l][d] layout
// ---------------------------------------------------------------------------
__global__ __launch_bounds__(128)
void normrope_split(const float* __restrict__ cosp, const float* __restrict__ sinp,
                    const float* __restrict__ qw,  const float* __restrict__ kw)
{
    int m = blockIdx.x;           // b*L + l
    int e = blockIdx.y;           // 0..19
    int t = threadIdx.x;
    int l = m & (LSEQ - 1);
    int b = m >> 11;

    const float* p;
    const float* w;
    __nv_bfloat16 *dh, *dl;
    float sc;
    if (e < H_HEADS) {
        p = g_qkv + (size_t)m * QKV_COLS + e * DHEAD; w = qw;
        size_t o = ((size_t)(b * H_HEADS + e) * LSEQ + l) * DHEAD;
        dh = g_qh + o; dl = g_ql + o;
        sc = 0.08838834764831845f;   // 1/sqrt(128)
    } else {
        int kvh = e - H_HEADS;
        p = g_qkv + (size_t)m * QKV_COLS + 2048 + kvh * DHEAD; w = kw;
        size_t o = ((size_t)(b * KV_HEADS + kvh) * LSEQ + l) * DHEAD;
        dh = g_kh + o; dl = g_kl + o;
        sc = 1.0f;
    }

    float v = p[t];
    float ss = v * v;
#pragma unroll
    for (int o = 16; o; o >>= 1) ss += __shfl_xor_sync(0xffffffffu, ss, o);

    __shared__ float sred[4];
    __shared__ float sval[128];
    if ((t & 31) == 0) sred[t >> 5] = ss;
    __syncthreads();
    ss = sred[0] + sred[1] + sred[2] + sred[3];

    float n = v * rsqrtf(ss * (1.0f / 128.0f) + 1e-6f) * w[t];
    sval[t] = n;
    __syncthreads();
    float rot = (t < 64) ? -sval[t + 64] : sval[t - 64];
    float val = (n * cosp[l * DHEAD + t] + rot * sinp[l * DHEAD + t]) * sc;
    __nv_bfloat16 hh = __float2bfloat16(val);
    dh[t] = hh;
    dl[t] = __float2bfloat16(val - __bfloat162float(hh));
}

// ---------------------------------------------------------------------------
// V transpose + split: g_qkv v cols -> g_vth/g_vtl [b][kvh][d][l]
// 32x32 tiles, block (32,8)
// ---------------------------------------------------------------------------
__global__ __launch_bounds__(256)
void vtrans()
{
    __shared__ float tile[32][33];
    int tx = threadIdx.x, ty = threadIdx.y;
    int l0 = blockIdx.x * 32, d0 = blockIdx.y * 32, bk = blockIdx.z;  // bk = b*KV+kvh
    int b = bk >> 2, kvh = bk & 3;

#pragma unroll
    for (int i = 0; i < 4; i++) {
        int l = l0 + ty + 8 * i;
        tile[ty + 8 * i][tx] =
            g_qkv[((size_t)(b * LSEQ + l)) * QKV_COLS + 2560 + kvh * DHEAD + d0 + tx];
    }
    __syncthreads();
#pragma unroll
    for (int i = 0; i < 4; i++) {
        int d = d0 + ty + 8 * i;
        float v = tile[tx][ty + 8 * i];
        __nv_bfloat16 hh = __float2bfloat16(v);
        size_t o = ((size_t)bk * DHEAD + d) * LSEQ + l0 + tx;
        g_vth[o] = hh;
        g_vtl[o] = __float2bfloat16(v - __bfloat162float(hh));
    }
}

// ---------------------------------------------------------------------------
// HMMA flash attention with sliding window.
// CTA: 128 q rows x head x batch, 8 warps (16 rows each). KCH=64 keys/chunk.
// QK: split-bf16 (3 products). PV: P split hi/lo x V split (3 products).
// ---------------------------------------------------------------------------
#define AQT 128
#define AKC 64
#define A_QH 0
#define A_QL 32768
#define A_STG0 65536
#define A_STG_SZ 65536
#define AS_KH 0
#define AS_KL 16384
#define AS_VH 32768
#define AS_VL 49152
#define ATT_SMEM2 196608

__global__ __launch_bounds__(256, 1)
void attn_mma()
{
    extern __shared__ __align__(128) char asmem[];
    const uint32_t base = smem_u32(asmem);
    const int tid = threadIdx.x, lane = tid & 31, w = tid >> 5;
    const int qt = blockIdx.x, h = blockIdx.y, b = blockIdx.z;
    const int kvh = h >> 2;
    const int q0 = qt * AQT;

    // Q tile load (two 64-d panels per array)
    {
        const __nv_bfloat16* qh = g_qh + ((size_t)(b * H_HEADS + h) * LSEQ + q0) * DHEAD;
        const __nv_bfloat16* ql = g_ql + ((size_t)(b * H_HEADS + h) * LSEQ + q0) * DHEAD;
#pragma unroll
        for (int i = 0; i < 8; i++) {
            int u = tid + 256 * i;
            int r = u >> 4, cu = u & 15;
            uint32_t so = (uint32_t)(cu >> 3) * 16384 + swz((uint32_t)(r * 128 + (cu & 7) * 16));
            cpa16(base + A_QH + so, qh + (size_t)r * DHEAD + cu * 8);
            cpa16(base + A_QL + so, ql + (size_t)r * DHEAD + cu * 8);
        }
        CPA_COMMIT();
    }

    int kstart = q0 - WIN;       if (kstart < 0)  kstart = 0;
    int kend   = q0 + AQT + WIN; if (kend > LSEQ) kend = LSEQ;
    const int nc = (kend - kstart) / AKC;

    const __nv_bfloat16* kh  = g_kh  + (size_t)(b * KV_HEADS + kvh) * LSEQ * DHEAD;
    const __nv_bfloat16* kl  = g_kl  + (size_t)(b * KV_HEADS + kvh) * LSEQ * DHEAD;
    const __nv_bfloat16* vth = g_vth + (size_t)(b * KV_HEADS + kvh) * DHEAD * LSEQ;
    const __nv_bfloat16* vtl = g_vtl + (size_t)(b * KV_HEADS + kvh) * DHEAD * LSEQ;

    auto load_kv = [&](int c, int s) {
        const uint32_t sb = base + A_STG0 + (uint32_t)s * A_STG_SZ;
        const int ks = kstart + c * AKC;
#pragma unroll
        for (int i = 0; i < 4; i++) {
            int u = tid + 256 * i;
            int r = u >> 4, cu = u & 15;
            uint32_t so = (uint32_t)(cu >> 3) * 8192 + swz((uint32_t)(r * 128 + (cu & 7) * 16));
            size_t g = (size_t)(ks + r) * DHEAD + cu * 8;
            cpa16(sb + AS_KH + so, kh + g);
            cpa16(sb + AS_KL + so, kl + g);
        }
#pragma unroll
        for (int i = 0; i < 4; i++) {
            int u = tid + 256 * i;
            int d = u >> 3, cu = u & 7;
            uint32_t so = swz((uint32_t)(d * 128 + cu * 16));
            size_t g = (size_t)d * LSEQ + ks + cu * 8;
            cpa16(sb + AS_VH + so, vth + g);
            cpa16(sb + AS_VL + so, vtl + g);
        }
        CPA_COMMIT();
    };

    load_kv(0, 0);

    const int a_row  = w * 16 + (lane & 15);
    const int a_k    = (lane >> 4) * 8;
    const int b_rowg = (lane >> 4) * 8 + (lane & 7);
    const int b_k    = ((lane >> 3) & 1) * 8;
    const int r0     = lane >> 2, colb = 2 * (lane & 3);
    const int qrow0  = q0 + w * 16 + r0;
    const int qrow1  = qrow0 + 8;

    float out[16][4];
#pragma unroll
    for (int na = 0; na < 16; na++)
#pragma unroll
        for (int q = 0; q < 4; q++) out[na][q] = 0.0f;
    float m0 = -1e30f, m1 = -1e30f, l0s = 0.0f, l1s = 0.0f;

    for (int c = 0; c < nc; c++) {
        if (c + 1 < nc) { load_kv(c + 1, (c + 1) & 1); CPA_WAIT(1); }
        else            { CPA_WAIT(0); }
        __syncthreads();
        const uint32_t sb = base + A_STG0 + (uint32_t)(c & 1) * A_STG_SZ;

        // ---- S = Q K^T (16 x 64 per warp) ----
        float sacc[8][4];
#pragma unroll
        for (int j = 0; j < 8; j++)
#pragma unroll
            for (int q = 0; q < 4; q++) sacc[j][q] = 0.0f;

#pragma unroll
        for (int ks = 0; ks < 8; ks++) {
            int pnl = ks >> 2, kk = (ks & 3) * 16;
            uint32_t aoff = (uint32_t)pnl * 16384 + swz((uint32_t)(a_row * 128 + (kk + a_k) * 2));
            uint32_t aqh[4], aql[4];
            ldmx4(aqh, base + A_QH + aoff);
            ldmx4(aql, base + A_QL + aoff);
#pragma unroll
            for (int jp = 0; jp < 4; jp++) {
                uint32_t boff = (uint32_t)pnl * 8192 +
                    swz((uint32_t)((jp * 16 + b_rowg) * 128 + (kk + b_k) * 2));
                uint32_t bkh[4], bkl[4];
                ldmx4(bkh, sb + AS_KH + boff);
                ldmx4(bkl, sb + AS_KL + boff);
                mma_bf16(sacc[2 * jp],     aqh, &bkh[0]);
                mma_bf16(sacc[2 * jp + 1], aqh, &bkh[2]);
                mma_bf16(sacc[2 * jp],     aqh, &bkl[0]);
                mma_bf16(sacc[2 * jp + 1], aqh, &bkl[2]);
                mma_bf16(sacc[2 * jp],     aql, &bkh[0]);
                mma_bf16(sacc[2 * jp + 1], aql, &bkh[2]);
            }
        }

        // ---- mask + online softmax (in registers, quad reductions) ----
        const int ks0 = kstart + c * AKC;
        float mx0 = -1e30f, mx1 = -1e30f;
#pragma unroll
        for (int j = 0; j < 8; j++) {
            int k0 = ks0 + j * 8 + colb, k1 = k0 + 1;
            int d00 = qrow0 - k0; if (d00 < 0) d00 = -d00;
            int d01 = qrow0 - k1; if (d01 < 0) d01 = -d01;
            int d10 = qrow1 - k0; if (d10 < 0) d10 = -d10;
            int d11 = qrow1 - k1; if (d11 < 0) d11 = -d11;
            if (d00 > WIN) sacc[j][0] = -1e30f;
            if (d01 > WIN) sacc[j][1] = -1e30f;
            if (d10 > WIN) sacc[j][2] = -1e30f;
            if (d11 > WIN) sacc[j][3] = -1e30f;
            mx0 = fmaxf(mx0, fmaxf(sacc[j][0], sacc[j][1]));
            mx1 = fmaxf(mx1, fmaxf(sacc[j][2], sacc[j][3]));
        }
        mx0 = fmaxf(mx0, __shfl_xor_sync(0xffffffffu, mx0, 1));
        mx0 = fmaxf(mx0, __shfl_xor_sync(0xffffffffu, mx0, 2));
        mx1 = fmaxf(mx1, __shfl_xor_sync(0xffffffffu, mx1, 1));
        mx1 = fmaxf(mx1, __shfl_xor_sync(0xffffffffu, mx1, 2));

        float mn0 = fmaxf(m0, mx0), mn1 = fmaxf(m1, mx1);
        float c0f = __expf(m0 - mn0), c1f = __expf(m1 - mn1);
        m0 = mn0; m1 = mn1;

        float rs0 = 0.0f, rs1 = 0.0f;
        uint32_t ph[8], ph2[8], pl[8], pl2[8];
#pragma unroll
        for (int j = 0; j < 8; j++) {
            float p0 = (sacc[j][0] > -9e29f) ? __expf(sacc[j][0] - mn0) : 0.0f;
            float p1 = (sacc[j][1] > -9e29f) ? __expf(sacc[j][1] - mn0) : 0.0f;
            float p2 = (sacc[j][2] > -9e29f) ? __expf(sacc[j][2] - mn1) : 0.0f;
            float p3 = (sacc[j][3] > -9e29f) ? __expf(sacc[j][3] - mn1) : 0.0f;
            rs0 += p0 + p1; rs1 += p2 + p3;
            __nv_bfloat16 h0 = __float2bfloat16(p0), h1v = __float2bfloat16(p1);
            __nv_bfloat16 h2 = __float2bfloat16(p2), h3v = __float2bfloat16(p3);
            ph[j]  = pk2(h0, h1v);
            ph2[j] = pk2(h2, h3v);
            pl[j]  = pk2(__float2bfloat16(p0 - __bfloat162float(h0)),
                         __float2bfloat16(p1 - __bfloat162float(h1v)));
            pl2[j] = pk2(__float2bfloat16(p2 - __bfloat162float(h2)),
                         __float2bfloat16(p3 - __bfloat162float(h3v)));
        }
        rs0 += __shfl_xor_sync(0xffffffffu, rs0, 1);
        rs0 += __shfl_xor_sync(0xffffffffu, rs0, 2);
        rs1 += __shfl_xor_sync(0xffffffffu, rs1, 1);
        rs1 += __shfl_xor_sync(0xffffffffu, rs1, 2);
        l0s = l0s * c0f + rs0;
        l1s = l1s * c1f + rs1;
#pragma unroll
        for (int na = 0; na < 16; na++) {
            out[na][0] *= c0f; out[na][1] *= c0f;
            out[na][2] *= c1f; out[na][3] *= c1f;
        }

        // ---- O += P V  (16 x 128 per warp) ----
#pragma unroll
        for (int ks2 = 0; ks2 < 4; ks2++) {
            uint32_t Ahf[4] = { ph[2 * ks2], ph2[2 * ks2], ph[2 * ks2 + 1], ph2[2 * ks2 + 1] };
            uint32_t Alf[4] = { pl[2 * ks2], pl2[2 * ks2], pl[2 * ks2 + 1], pl2[2 * ks2 + 1] };
#pragma unroll
            for (int jp = 0; jp < 8; jp++) {
                uint32_t voff = swz((uint32_t)((jp * 16 + b_rowg) * 128 + (ks2 * 16 + b_k) * 2));
                uint32_t vh[4], vl[4];
                ldmx4(vh, sb + AS_VH + voff);
                ldmx4(vl, sb + AS_VL + voff);
                mma_bf16(out[2 * jp],     Ahf, &vh[0]);
                mma_bf16(out[2 * jp + 1], Ahf, &vh[2]);
                mma_bf16(out[2 * jp],     Ahf, &vl[0]);
                mma_bf16(out[2 * jp + 1], Ahf, &vl[2]);
                mma_bf16(out[2 * jp],     Alf, &vh[0]);
                mma_bf16(out[2 * jp + 1], Alf, &vh[2]);
            }
        }
        __syncthreads();
    }

    // ---- epilogue: normalize, split-bf16 store to g_ah/g_al ----
    float inv0 = 1.0f / l0s, inv1 = 1.0f / l1s;
    size_t rb0 = ((size_t)b * LSEQ + qrow0) * HIDDEN + h * DHEAD;
    size_t rb1 = rb0 + (size_t)8 * HIDDEN;
#pragma unroll
    for (int na = 0; na < 16; na++) {
        int d = na * 8 + colb;
        float o0 = out[na][0] * inv0, o1 = out[na][1] * inv0;
        float o2 = out[na][2] * inv1, o3 = out[na][3] * inv1;
        __nv_bfloat16 a0 = __float2bfloat16(o0), a1 = __float2bfloat16(o1);
        __nv_bfloat16 a2 = __float2bfloat16(o2), a3 = __float2bfloat16(o3);
        *(uint32_t*)(g_ah + rb0 + d) = pk2(a0, a1);
        *(uint32_t*)(g_ah + rb1 + d) = pk2(a2, a3);
        *(uint32_t*)(g_al + rb0 + d) = pk2(__float2bfloat16(o0 - __bfloat162float(a0)),
                                           __float2bfloat16(o1 - __bfloat162float(a1)));
        *(uint32_t*)(g_al + rb1 + d) = pk2(__float2bfloat16(o2 - __bfloat162float(a2)),
                                           __float2bfloat16(o3 - __bfloat162float(a3)));
    }
}

// ---------------------------------------------------------------------------
// Launch. Inputs: x, cos, sin, Wq, Wk, Wv, Wo, q_norm_w, k_norm_w
// ---------------------------------------------------------------------------
extern "C" void kernel_launch(void* const* d_in, const int* in_sizes, int n_in,
                              void* d_out, int out_size)
{
    const float* x    = (const float*)d_in[0];
    const float* cosp = (const float*)d_in[1];
    const float* sinp = (const float*)d_in[2];
    const float* Wq   = (const float*)d_in[3];
    const float* Wk   = (const float*)d_in[4];
    const float* Wv   = (const float*)d_in[5];
    const float* Wo   = (const float*)d_in[6];
    const float* qw   = (const float*)d_in[7];
    const float* kw   = (const float*)d_in[8];
    float* out = (float*)d_out;

    void *p_qkv, *p_xh, *p_xl, *p_wh, *p_wl, *p_woh, *p_wol, *p_ah, *p_al;
    cudaGetSymbolAddress(&p_qkv, g_qkv);
    cudaGetSymbolAddress(&p_xh,  g_xh);  cudaGetSymbolAddress(&p_xl,  g_xl);
    cudaGetSymbolAddress(&p_wh,  g_wh);  cudaGetSymbolAddress(&p_wl,  g_wl);
    cudaGetSymbolAddress(&p_woh, g_woh); cudaGetSymbolAddress(&p_wol, g_wol);
    cudaGetSymbolAddress(&p_ah,  g_ah);  cudaGetSymbolAddress(&p_al,  g_al);

    cudaFuncSetAttribute(gemm_mma, cudaFuncAttributeMaxDynamicSharedMemorySize, GEMM_SMEM);
    cudaFuncSetAttribute(attn_mma, cudaFuncAttributeMaxDynamicSharedMemorySize, ATT_SMEM2);

    // 1) split conversions (uint2 = 4 bf16 -> element offset / 4)
    {
        int n4 = BATCH * LSEQ * HIDDEN / 4;
        cvt_split<<<(n4 + 255) / 256, 256>>>((const float4*)x, (uint2*)p_xh, (uint2*)p_xl, n4);
    }
    {
        int n4 = 2048 * HIDDEN / 4;
        cvt_split<<<(n4 + 255) / 256, 256>>>((const float4*)Wq, (uint2*)p_wh, (uint2*)p_wl, n4);
    }
    {
        int n4 = 512 * HIDDEN / 4;
        size_t off = (size_t)2048 * HIDDEN / 4;
        cvt_split<<<(n4 + 255) / 256, 256>>>((const float4*)Wk, (uint2*)p_wh + off, (uint2*)p_wl + off, n4);
    }
    {
        int n4 = 512 * HIDDEN / 4;
        size_t off = (size_t)2560 * HIDDEN / 4;
        cvt_split<<<(n4 + 255) / 256, 256>>>((const float4*)Wv, (uint2*)p_wh + off, (uint2*)p_wl + off, n4);
    }
    {
        int n4 = HIDDEN * HIDDEN / 4;
        cvt_split<<<(n4 + 255) / 256, 256>>>((const float4*)Wo, (uint2*)p_woh, (uint2*)p_wol, n4);
    }

    // 2) QKV projection (HMMA) -> g_qkv fp32
    gemm_mma<<<dim3(BATCH * LSEQ / GMT, QKV_COLS / GNT), 256, GEMM_SMEM>>>(
        (const __nv_bfloat16*)p_xh, (const __nv_bfloat16*)p_xl,
        (const __nv_bfloat16*)p_wh, (const __nv_bfloat16*)p_wl,
        (float*)p_qkv, QKV_COLS);

    // 3) RMSNorm + RoPE -> split-bf16 Q (scaled) / K
    normrope_split<<<dim3(BATCH * LSEQ, H_HEADS + KV_HEADS), 128>>>(cosp, sinp, qw, kw);

    // 4) V transpose + split -> g_vth/g_vtl
    vtrans<<<dim3(LSEQ / 32, DHEAD / 32, BATCH * KV_HEADS), dim3(32, 8)>>>();

    // 5) HMMA sliding-window flash attention -> g_ah/g_al
    attn_mma<<<dim3(LSEQ / AQT, H_HEADS, BATCH), 256, ATT_SMEM2>>>();

    // 6) Output projection (HMMA) -> d_out
    gemm_mma<<<dim3(BATCH * LSEQ / GMT, HIDDEN / GNT), 256, GEMM_SMEM>>>(
        (const __nv_bfloat16*)p_ah, (const __nv_bfloat16*)p_al,
        (const __nv_bfloat16*)p_woh, (const __nv_bfloat16*)p_wol,
        out, HIDDEN);
}

// round 9
// speedup vs baseline: 3.1360x; 1.0458x over previous
#include <cuda_runtime.h>
#include <cuda_bf16.h>
#include <math.h>
#include <stdint.h>

// Problem constants
#define H_HEADS   16
#define KV_HEADS  4
#define DHEAD     128
#define LSEQ      2048
#define BATCH     2
#define HIDDEN    2048
#define QKV_COLS  3072      // 2048 q + 512 k + 512 v
#define WIN       512
#define KDIM      2048

// ---------------------------------------------------------------------------
// Scratch (device globals; no allocation)
// ---------------------------------------------------------------------------
__device__ float         g_qkv[(size_t)BATCH * LSEQ * QKV_COLS];   // fp32 [B*L, 3072]
__device__ __nv_bfloat16 g_xh [(size_t)BATCH * LSEQ * HIDDEN];
__device__ __nv_bfloat16 g_xl [(size_t)BATCH * LSEQ * HIDDEN];
__device__ __nv_bfloat16 g_wh [(size_t)QKV_COLS * HIDDEN];
__device__ __nv_bfloat16 g_wl [(size_t)QKV_COLS * HIDDEN];
__device__ __nv_bfloat16 g_woh[(size_t)HIDDEN * HIDDEN];
__device__ __nv_bfloat16 g_wol[(size_t)HIDDEN * HIDDEN];
__device__ __nv_bfloat16 g_ah [(size_t)BATCH * LSEQ * HIDDEN];
__device__ __nv_bfloat16 g_al [(size_t)BATCH * LSEQ * HIDDEN];
// Attention operands (bf16 hi/lo)
__device__ __nv_bfloat16 g_qh [(size_t)BATCH * H_HEADS  * LSEQ * DHEAD];  // [b][h][l][d], pre-scaled
__device__ __nv_bfloat16 g_ql [(size_t)BATCH * H_HEADS  * LSEQ * DHEAD];
__device__ __nv_bfloat16 g_kh [(size_t)BATCH * KV_HEADS * LSEQ * DHEAD];  // [b][kvh][l][d]
__device__ __nv_bfloat16 g_kl [(size_t)BATCH * KV_HEADS * LSEQ * DHEAD];
__device__ __nv_bfloat16 g_vth[(size_t)BATCH * KV_HEADS * DHEAD * LSEQ];  // [b][kvh][d][l]
__device__ __nv_bfloat16 g_vtl[(size_t)BATCH * KV_HEADS * DHEAD * LSEQ];

// ---------------------------------------------------------------------------
// Base-ISA PTX helpers
// ---------------------------------------------------------------------------
__device__ __forceinline__ uint32_t smem_u32(const void* p) {
    uint32_t r;
    asm("{ .reg .u64 t; cvta.to.shared.u64 t, %1; cvt.u32.u64 %0, t; }" : "=r"(r) : "l"(p));
    return r;
}
__device__ __forceinline__ void cpa16(uint32_t s, const void* g) {
    asm volatile("cp.async.cg.shared.global [%0], [%1], 16;" :: "r"(s), "l"(g));
}
#define CPA_COMMIT() asm volatile("cp.async.commit_group;" ::: "memory")
#define CPA_WAIT(n)  asm volatile("cp.async.wait_group %0;" :: "n"(n) : "memory")

__device__ __forceinline__ uint32_t swz(uint32_t o) { return o ^ ((o >> 3) & 0x70); }

__device__ __forceinline__ void ldmx4(uint32_t* r, uint32_t a) {
    asm volatile("ldmatrix.sync.aligned.m8n8.x4.shared.b16 {%0,%1,%2,%3}, [%4];"
        : "=r"(r[0]), "=r"(r[1]), "=r"(r[2]), "=r"(r[3]) : "r"(a));
}
__device__ __forceinline__ void mma_bf16(float* c, const uint32_t* a, const uint32_t* b) {
    asm volatile("mma.sync.aligned.m16n8k16.row.col.f32.bf16.bf16.f32 "
        "{%0,%1,%2,%3}, {%4,%5,%6,%7}, {%8,%9}, {%0,%1,%2,%3};"
        : "+f"(c[0]), "+f"(c[1]), "+f"(c[2]), "+f"(c[3])
        : "r"(a[0]), "r"(a[1]), "r"(a[2]), "r"(a[3]), "r"(b[0]), "r"(b[1]));
}
__device__ __forceinline__ unsigned pk2(__nv_bfloat16 a, __nv_bfloat16 b) {
    __nv_bfloat162 t = __halves2bfloat162(a, b);
    return *reinterpret_cast<unsigned*>(&t);
}

// ---------------------------------------------------------------------------
// Split-bf16 HMMA GEMM, 128x256 CTA tile: C = A*B^T, D = Ah*Bh + Ah*Bl + Al*Bh
// 8 warps (4x2); warp tile 32x128. K chunks of 64, double-buffered cp.async.
// ---------------------------------------------------------------------------
#define GMT 128
#define GNT 256
#define GNKC (KDIM / 64)
#define G_OFF_AH 0
#define G_OFF_AL 16384
#define G_OFF_BH 32768
#define G_OFF_BL 65536
#define G_STAGE  98304
#define GEMM_SMEM (2 * G_STAGE)      // 192 KB

__global__ __launch_bounds__(256, 1)
void gemm_mma(const __nv_bfloat16* __restrict__ Ah, const __nv_bfloat16* __restrict__ Al,
              const __nv_bfloat16* __restrict__ Bh, const __nv_bfloat16* __restrict__ Bl,
              float* __restrict__ C, int ldc)
{
    extern __shared__ __align__(128) char dsm[];
    const uint32_t base = smem_u32(dsm);
    const int tid = threadIdx.x, lane = tid & 31, wid = tid >> 5;
    const int wm = wid & 3, wn = wid >> 2;          // 4 x 2 warp grid
    const int m0 = blockIdx.x * GMT, n0 = blockIdx.y * GNT;

    const int a_row  = wm * 32 + (lane & 15);
    const int a_k    = (lane >> 4) * 8;
    const int b_rowg = (lane >> 4) * 8 + (lane & 7);
    const int b_k    = ((lane >> 3) & 1) * 8;

    float acc[2][16][4];
#pragma unroll
    for (int i = 0; i < 2; i++)
#pragma unroll
        for (int j = 0; j < 16; j++)
#pragma unroll
            for (int q = 0; q < 4; q++) acc[i][j][q] = 0.0f;

    auto load_stage = [&](int kc, int s) {
        const uint32_t sb = base + (uint32_t)s * G_STAGE;
#pragma unroll
        for (int i = 0; i < 4; i++) {             // A: 128 rows x 8 units
            int u = tid + 256 * i;
            int r = u >> 3, cu = u & 7;
            uint32_t so = swz((uint32_t)(r * 128 + cu * 16));
            size_t ga = ((size_t)(m0 + r) << 11) + (kc << 6) + (cu << 3);
            cpa16(sb + G_OFF_AH + so, Ah + ga);
            cpa16(sb + G_OFF_AL + so, Al + ga);
        }
#pragma unroll
        for (int i = 0; i < 8; i++) {             // B: 256 rows x 8 units
            int u = tid + 256 * i;
            int r = u >> 3, cu = u & 7;
            uint32_t so = swz((uint32_t)(r * 128 + cu * 16));
            size_t gb = ((size_t)(n0 + r) << 11) + (kc << 6) + (cu << 3);
            cpa16(sb + G_OFF_BH + so, Bh + gb);
            cpa16(sb + G_OFF_BL + so, Bl + gb);
        }
        CPA_COMMIT();
    };

    load_stage(0, 0);

    for (int kc = 0; kc < GNKC; kc++) {
        if (kc + 1 < GNKC) { load_stage(kc + 1, (kc + 1) & 1); CPA_WAIT(1); }
        else               { CPA_WAIT(0); }
        __syncthreads();

        const uint32_t sb = base + (uint32_t)(kc & 1) * G_STAGE;
        const uint32_t ah_b = sb + G_OFF_AH, al_b = sb + G_OFF_AL;
        const uint32_t bh_b = sb + G_OFF_BH, bl_b = sb + G_OFF_BL;

#pragma unroll
        for (int ks = 0; ks < 4; ks++) {
            uint32_t afh[2][4], afl[2][4];
#pragma unroll
            for (int i = 0; i < 2; i++) {
                uint32_t off = swz((uint32_t)((a_row + i * 16) * 128 + (a_k + ks * 16) * 2));
                ldmx4(afh[i], ah_b + off);
                ldmx4(afl[i], al_b + off);
            }
            // B fragments loaded per-jp and consumed immediately (low live set)
#pragma unroll
            for (int jp = 0; jp < 8; jp++) {
                int nrow = wn * 128 + jp * 16 + b_rowg;
                uint32_t off = swz((uint32_t)(nrow * 128 + (b_k + ks * 16) * 2));
                uint32_t bh[4], bl[4];
                ldmx4(bh, bh_b + off);
                ldmx4(bl, bl_b + off);
#pragma unroll
                for (int i = 0; i < 2; i++) {
                    mma_bf16(acc[i][2 * jp],     afh[i], &bh[0]);
                    mma_bf16(acc[i][2 * jp + 1], afh[i], &bh[2]);
                    mma_bf16(acc[i][2 * jp],     afh[i], &bl[0]);
                    mma_bf16(acc[i][2 * jp + 1], afh[i], &bl[2]);
                    mma_bf16(acc[i][2 * jp],     afl[i], &bh[0]);
                    mma_bf16(acc[i][2 * jp + 1], afl[i], &bh[2]);
                }
            }
        }
        __syncthreads();
    }

#pragma unroll
    for (int i = 0; i < 2; i++) {
        int row = m0 + wm * 32 + i * 16 + (lane >> 2);
#pragma unroll
        for (int j = 0; j < 16; j++) {
            int col = n0 + wn * 128 + j * 8 + 2 * (lane & 3);
            *(float2*)&C[(size_t)row * ldc + col]       = make_float2(acc[i][j][0], acc[i][j][1]);
            *(float2*)&C[(size_t)(row + 8) * ldc + col] = make_float2(acc[i][j][2], acc[i][j][3]);
        }
    }
}

// ---------------------------------------------------------------------------
// fp32 -> (bf16 hi, lo) split conversion
// ---------------------------------------------------------------------------
__global__ __launch_bounds__(256)
void cvt_split(const float4* __restrict__ src, uint2* __restrict__ hi,
               uint2* __restrict__ lo, int n4)
{
    int i = blockIdx.x * 256 + threadIdx.x;
    if (i >= n4) return;
    float4 v = src[i];
    __nv_bfloat16 h0 = __float2bfloat16(v.x), h1 = __float2bfloat16(v.y);
    __nv_bfloat16 h2 = __float2bfloat16(v.z), h3 = __float2bfloat16(v.w);
    __nv_bfloat16 l0 = __float2bfloat16(v.x - __bfloat162float(h0));
    __nv_bfloat16 l1 = __float2bfloat16(v.y - __bfloat162float(h1));
    __nv_bfloat16 l2 = __float2bfloat16(v.z - __bfloat162float(h2));
    __nv_bfloat16 l3 = __float2bfloat16(v.w - __bfloat162float(h3));
    hi[i] = make_uint2(pk2(h0, h1), pk2(h2, h3));
    lo[i] = make_uint2(pk2(l0, l1), pk2(l2, l3));
}

// ---------------------------------------------------------------------------
// RMSNorm + RoPE -> split-bf16 Q (pre-scaled) and K
// ---------------------------------------------------------------------------
__global__ __launch_bounds__(128)
void normrope_split(const float* __restrict__ cosp, const float* __restrict__ sinp,
                    const float* __restrict__ qw,  const float* __restrict__ kw)
{
    int m = blockIdx.x;
    int e = blockIdx.y;
    int t = threadIdx.x;
    int l = m & (LSEQ - 1);
    int b = m >> 11;

    const float* p;
    const float* w;
    __nv_bfloat16 *dh, *dl;
    float sc;
    if (e < H_HEADS) {
        p = g_qkv + (size_t)m * QKV_COLS + e * DHEAD; w = qw;
        size_t o = ((size_t)(b * H_HEADS + e) * LSEQ + l) * DHEAD;
        dh = g_qh + o; dl = g_ql + o;
        sc = 0.08838834764831845f;
    } else {
        int kvh = e - H_HEADS;
        p = g_qkv + (size_t)m * QKV_COLS + 2048 + kvh * DHEAD; w = kw;
        size_t o = ((size_t)(b * KV_HEADS + kvh) * LSEQ + l) * DHEAD;
        dh = g_kh + o; dl = g_kl + o;
        sc = 1.0f;
    }

    float v = p[t];
    float ss = v * v;
#pragma unroll
    for (int o = 16; o; o >>= 1) ss += __shfl_xor_sync(0xffffffffu, ss, o);

    __shared__ float sred[4];
    __shared__ float sval[128];
    if ((t & 31) == 0) sred[t >> 5] = ss;
    __syncthreads();
    ss = sred[0] + sred[1] + sred[2] + sred[3];

    float n = v * rsqrtf(ss * (1.0f / 128.0f) + 1e-6f) * w[t];
    sval[t] = n;
    __syncthreads();
    float rot = (t < 64) ? -sval[t + 64] : sval[t - 64];
    float val = (n * cosp[l * DHEAD + t] + rot * sinp[l * DHEAD + t]) * sc;
    __nv_bfloat16 hh = __float2bfloat16(val);
    dh[t] = hh;
    dl[t] = __float2bfloat16(val - __bfloat162float(hh));
}

// ---------------------------------------------------------------------------
// V transpose + split: g_qkv v cols -> g_vth/g_vtl [b][kvh][d][l]
// ---------------------------------------------------------------------------
__global__ __launch_bounds__(256)
void vtrans()
{
    __shared__ float tile[32][33];
    int tx = threadIdx.x, ty = threadIdx.y;
    int l0 = blockIdx.x * 32, d0 = blockIdx.y * 32, bk = blockIdx.z;
    int b = bk >> 2, kvh = bk & 3;

#pragma unroll
    for (int i = 0; i < 4; i++) {
        int l = l0 + ty + 8 * i;
        tile[ty + 8 * i][tx] =
            g_qkv[((size_t)(b * LSEQ + l)) * QKV_COLS + 2560 + kvh * DHEAD + d0 + tx];
    }
    __syncthreads();
#pragma unroll
    for (int i = 0; i < 4; i++) {
        int d = d0 + ty + 8 * i;
        float v = tile[tx][ty + 8 * i];
        __nv_bfloat16 hh = __float2bfloat16(v);
        size_t o = ((size_t)bk * DHEAD + d) * LSEQ + l0 + tx;
        g_vth[o] = hh;
        g_vtl[o] = __float2bfloat16(v - __bfloat162float(hh));
    }
}

// ---------------------------------------------------------------------------
// HMMA flash attention with sliding window (proven R8).
// ---------------------------------------------------------------------------
#define AQT 128
#define AKC 64
#define A_QH 0
#define A_QL 32768
#define A_STG0 65536
#define A_STG_SZ 65536
#define AS_KH 0
#define AS_KL 16384
#define AS_VH 32768
#define AS_VL 49152
#define ATT_SMEM2 196608

__global__ __launch_bounds__(256, 1)
void attn_mma()
{
    extern __shared__ __align__(128) char asmem[];
    const uint32_t base = smem_u32(asmem);
    const int tid = threadIdx.x, lane = tid & 31, w = tid >> 5;
    const int qt = blockIdx.x, h = blockIdx.y, b = blockIdx.z;
    const int kvh = h >> 2;
    const int q0 = qt * AQT;

    {
        const __nv_bfloat16* qh = g_qh + ((size_t)(b * H_HEADS + h) * LSEQ + q0) * DHEAD;
        const __nv_bfloat16* ql = g_ql + ((size_t)(b * H_HEADS + h) * LSEQ + q0) * DHEAD;
#pragma unroll
        for (int i = 0; i < 8; i++) {
            int u = tid + 256 * i;
            int r = u >> 4, cu = u & 15;
            uint32_t so = (uint32_t)(cu >> 3) * 16384 + swz((uint32_t)(r * 128 + (cu & 7) * 16));
            cpa16(base + A_QH + so, qh + (size_t)r * DHEAD + cu * 8);
            cpa16(base + A_QL + so, ql + (size_t)r * DHEAD + cu * 8);
        }
        CPA_COMMIT();
    }

    int kstart = q0 - WIN;       if (kstart < 0)  kstart = 0;
    int kend   = q0 + AQT + WIN; if (kend > LSEQ) kend = LSEQ;
    const int nc = (kend - kstart) / AKC;

    const __nv_bfloat16* kh  = g_kh  + (size_t)(b * KV_HEADS + kvh) * LSEQ * DHEAD;
    const __nv_bfloat16* kl  = g_kl  + (size_t)(b * KV_HEADS + kvh) * LSEQ * DHEAD;
    const __nv_bfloat16* vth = g_vth + (size_t)(b * KV_HEADS + kvh) * DHEAD * LSEQ;
    const __nv_bfloat16* vtl = g_vtl + (size_t)(b * KV_HEADS + kvh) * DHEAD * LSEQ;

    auto load_kv = [&](int c, int s) {
        const uint32_t sb = base + A_STG0 + (uint32_t)s * A_STG_SZ;
        const int ks = kstart + c * AKC;
#pragma unroll
        for (int i = 0; i < 4; i++) {
            int u = tid + 256 * i;
            int r = u >> 4, cu = u & 15;
            uint32_t so = (uint32_t)(cu >> 3) * 8192 + swz((uint32_t)(r * 128 + (cu & 7) * 16));
            size_t g = (size_t)(ks + r) * DHEAD + cu * 8;
            cpa16(sb + AS_KH + so, kh + g);
            cpa16(sb + AS_KL + so, kl + g);
        }
#pragma unroll
        for (int i = 0; i < 4; i++) {
            int u = tid + 256 * i;
            int d = u >> 3, cu = u & 7;
            uint32_t so = swz((uint32_t)(d * 128 + cu * 16));
            size_t g = (size_t)d * LSEQ + ks + cu * 8;
            cpa16(sb + AS_VH + so, vth + g);
            cpa16(sb + AS_VL + so, vtl + g);
        }
        CPA_COMMIT();
    };

    load_kv(0, 0);

    const int a_row  = w * 16 + (lane & 15);
    const int a_k    = (lane >> 4) * 8;
    const int b_rowg = (lane >> 4) * 8 + (lane & 7);
    const int b_k    = ((lane >> 3) & 1) * 8;
    const int r0     = lane >> 2, colb = 2 * (lane & 3);
    const int qrow0  = q0 + w * 16 + r0;
    const int qrow1  = qrow0 + 8;

    float out[16][4];
#pragma unroll
    for (int na = 0; na < 16; na++)
#pragma unroll
        for (int q = 0; q < 4; q++) out[na][q] = 0.0f;
    float m0 = -1e30f, m1 = -1e30f, l0s = 0.0f, l1s = 0.0f;

    for (int c = 0; c < nc; c++) {
        if (c + 1 < nc) { load_kv(c + 1, (c + 1) & 1); CPA_WAIT(1); }
        else            { CPA_WAIT(0); }
        __syncthreads();
        const uint32_t sb = base + A_STG0 + (uint32_t)(c & 1) * A_STG_SZ;

        float sacc[8][4];
#pragma unroll
        for (int j = 0; j < 8; j++)
#pragma unroll
            for (int q = 0; q < 4; q++) sacc[j][q] = 0.0f;

#pragma unroll
        for (int ks = 0; ks < 8; ks++) {
            int pnl = ks >> 2, kk = (ks & 3) * 16;
            uint32_t aoff = (uint32_t)pnl * 16384 + swz((uint32_t)(a_row * 128 + (kk + a_k) * 2));
            uint32_t aqh[4], aql[4];
            ldmx4(aqh, base + A_QH + aoff);
            ldmx4(aql, base + A_QL + aoff);
#pragma unroll
            for (int jp = 0; jp < 4; jp++) {
                uint32_t boff = (uint32_t)pnl * 8192 +
                    swz((uint32_t)((jp * 16 + b_rowg) * 128 + (kk + b_k) * 2));
                uint32_t bkh[4], bkl[4];
                ldmx4(bkh, sb + AS_KH + boff);
                ldmx4(bkl, sb + AS_KL + boff);
                mma_bf16(sacc[2 * jp],     aqh, &bkh[0]);
                mma_bf16(sacc[2 * jp + 1], aqh, &bkh[2]);
                mma_bf16(sacc[2 * jp],     aqh, &bkl[0]);
                mma_bf16(sacc[2 * jp + 1], aqh, &bkl[2]);
                mma_bf16(sacc[2 * jp],     aql, &bkh[0]);
                mma_bf16(sacc[2 * jp + 1], aql, &bkh[2]);
            }
        }

        const int ks0 = kstart + c * AKC;
        float mx0 = -1e30f, mx1 = -1e30f;
#pragma unroll
        for (int j = 0; j < 8; j++) {
            int k0 = ks0 + j * 8 + colb, k1 = k0 + 1;
            int d00 = qrow0 - k0; if (d00 < 0) d00 = -d00;
            int d01 = qrow0 - k1; if (d01 < 0) d01 = -d01;
            int d10 = qrow1 - k0; if (d10 < 0) d10 = -d10;
            int d11 = qrow1 - k1; if (d11 < 0) d11 = -d11;
            if (d00 > WIN) sacc[j][0] = -1e30f;
            if (d01 > WIN) sacc[j][1] = -1e30f;
            if (d10 > WIN) sacc[j][2] = -1e30f;
            if (d11 > WIN) sacc[j][3] = -1e30f;
            mx0 = fmaxf(mx0, fmaxf(sacc[j][0], sacc[j][1]));
            mx1 = fmaxf(mx1, fmaxf(sacc[j][2], sacc[j][3]));
        }
        mx0 = fmaxf(mx0, __shfl_xor_sync(0xffffffffu, mx0, 1));
        mx0 = fmaxf(mx0, __shfl_xor_sync(0xffffffffu, mx0, 2));
        mx1 = fmaxf(mx1, __shfl_xor_sync(0xffffffffu, mx1, 1));
        mx1 = fmaxf(mx1, __shfl_xor_sync(0xffffffffu, mx1, 2));

        float mn0 = fmaxf(m0, mx0), mn1 = fmaxf(m1, mx1);
        float c0f = __expf(m0 - mn0), c1f = __expf(m1 - mn1);
        m0 = mn0; m1 = mn1;

        float rs0 = 0.0f, rs1 = 0.0f;
        uint32_t ph[8], ph2[8], pl[8], pl2[8];
#pragma unroll
        for (int j = 0; j < 8; j++) {
            float p0 = (sacc[j][0] > -9e29f) ? __expf(sacc[j][0] - mn0) : 0.0f;
            float p1 = (sacc[j][1] > -9e29f) ? __expf(sacc[j][1] - mn0) : 0.0f;
            float p2 = (sacc[j][2] > -9e29f) ? __expf(sacc[j][2] - mn1) : 0.0f;
            float p3 = (sacc[j][3] > -9e29f) ? __expf(sacc[j][3] - mn1) : 0.0f;
            rs0 += p0 + p1; rs1 += p2 + p3;
            __nv_bfloat16 h0 = __float2bfloat16(p0), h1v = __float2bfloat16(p1);
            __nv_bfloat16 h2 = __float2bfloat16(p2), h3v = __float2bfloat16(p3);
            ph[j]  = pk2(h0, h1v);
            ph2[j] = pk2(h2, h3v);
            pl[j]  = pk2(__float2bfloat16(p0 - __bfloat162float(h0)),
                         __float2bfloat16(p1 - __bfloat162float(h1v)));
            pl2[j] = pk2(__float2bfloat16(p2 - __bfloat162float(h2)),
                         __float2bfloat16(p3 - __bfloat162float(h3v)));
        }
        rs0 += __shfl_xor_sync(0xffffffffu, rs0, 1);
        rs0 += __shfl_xor_sync(0xffffffffu, rs0, 2);
        rs1 += __shfl_xor_sync(0xffffffffu, rs1, 1);
        rs1 += __shfl_xor_sync(0xffffffffu, rs1, 2);
        l0s = l0s * c0f + rs0;
        l1s = l1s * c1f + rs1;
#pragma unroll
        for (int na = 0; na < 16; na++) {
            out[na][0] *= c0f; out[na][1] *= c0f;
            out[na][2] *= c1f; out[na][3] *= c1f;
        }

#pragma unroll
        for (int ks2 = 0; ks2 < 4; ks2++) {
            uint32_t Ahf[4] = { ph[2 * ks2], ph2[2 * ks2], ph[2 * ks2 + 1], ph2[2 * ks2 + 1] };
            uint32_t Alf[4] = { pl[2 * ks2], pl2[2 * ks2], pl[2 * ks2 + 1], pl2[2 * ks2 + 1] };
#pragma unroll
            for (int jp = 0; jp < 8; jp++) {
                uint32_t voff = swz((uint32_t)((jp * 16 + b_rowg) * 128 + (ks2 * 16 + b_k) * 2));
                uint32_t vh[4], vl[4];
                ldmx4(vh, sb + AS_VH + voff);
                ldmx4(vl, sb + AS_VL + voff);
                mma_bf16(out[2 * jp],     Ahf, &vh[0]);
                mma_bf16(out[2 * jp + 1], Ahf, &vh[2]);
                mma_bf16(out[2 * jp],     Ahf, &vl[0]);
                mma_bf16(out[2 * jp + 1], Ahf, &vl[2]);
                mma_bf16(out[2 * jp],     Alf, &vh[0]);
                mma_bf16(out[2 * jp + 1], Alf, &vh[2]);
            }
        }
        __syncthreads();
    }

    float inv0 = 1.0f / l0s, inv1 = 1.0f / l1s;
    size_t rb0 = ((size_t)b * LSEQ + qrow0) * HIDDEN + h * DHEAD;
    size_t rb1 = rb0 + (size_t)8 * HIDDEN;
#pragma unroll
    for (int na = 0; na < 16; na++) {
        int d = na * 8 + colb;
        float o0 = out[na][0] * inv0, o1 = out[na][1] * inv0;
        float o2 = out[na][2] * inv1, o3 = out[na][3] * inv1;
        __nv_bfloat16 a0 = __float2bfloat16(o0), a1 = __float2bfloat16(o1);
        __nv_bfloat16 a2 = __float2bfloat16(o2), a3 = __float2bfloat16(o3);
        *(uint32_t*)(g_ah + rb0 + d) = pk2(a0, a1);
        *(uint32_t*)(g_ah + rb1 + d) = pk2(a2, a3);
        *(uint32_t*)(g_al + rb0 + d) = pk2(__float2bfloat16(o0 - __bfloat162float(a0)),
                                           __float2bfloat16(o1 - __bfloat162float(a1)));
        *(uint32_t*)(g_al + rb1 + d) = pk2(__float2bfloat16(o2 - __bfloat162float(a2)),
                                           __float2bfloat16(o3 - __bfloat162float(a3)));
    }
}

// ---------------------------------------------------------------------------
// Launch. Inputs: x, cos, sin, Wq, Wk, Wv, Wo, q_norm_w, k_norm_w
// ---------------------------------------------------------------------------
extern "C" void kernel_launch(void* const* d_in, const int* in_sizes, int n_in,
                              void* d_out, int out_size)
{
    const float* x    = (const float*)d_in[0];
    const float* cosp = (const float*)d_in[1];
    const float* sinp = (const float*)d_in[2];
    const float* Wq   = (const float*)d_in[3];
    const float* Wk   = (const float*)d_in[4];
    const float* Wv   = (const float*)d_in[5];
    const float* Wo   = (const float*)d_in[6];
    const float* qw   = (const float*)d_in[7];
    const float* kw   = (const float*)d_in[8];
    float* out = (float*)d_out;

    void *p_qkv, *p_xh, *p_xl, *p_wh, *p_wl, *p_woh, *p_wol, *p_ah, *p_al;
    cudaGetSymbolAddress(&p_qkv, g_qkv);
    cudaGetSymbolAddress(&p_xh,  g_xh);  cudaGetSymbolAddress(&p_xl,  g_xl);
    cudaGetSymbolAddress(&p_wh,  g_wh);  cudaGetSymbolAddress(&p_wl,  g_wl);
    cudaGetSymbolAddress(&p_woh, g_woh); cudaGetSymbolAddress(&p_wol, g_wol);
    cudaGetSymbolAddress(&p_ah,  g_ah);  cudaGetSymbolAddress(&p_al,  g_al);

    cudaFuncSetAttribute(gemm_mma, cudaFuncAttributeMaxDynamicSharedMemorySize, GEMM_SMEM);
    cudaFuncSetAttribute(attn_mma, cudaFuncAttributeMaxDynamicSharedMemorySize, ATT_SMEM2);

    // 1) split conversions (uint2 = 4 bf16 -> element offset / 4)
    {
        int n4 = BATCH * LSEQ * HIDDEN / 4;
        cvt_split<<<(n4 + 255) / 256, 256>>>((const float4*)x, (uint2*)p_xh, (uint2*)p_xl, n4);
    }
    {
        int n4 = 2048 * HIDDEN / 4;
        cvt_split<<<(n4 + 255) / 256, 256>>>((const float4*)Wq, (uint2*)p_wh, (uint2*)p_wl, n4);
    }
    {
        int n4 = 512 * HIDDEN / 4;
        size_t off = (size_t)2048 * HIDDEN / 4;
        cvt_split<<<(n4 + 255) / 256, 256>>>((const float4*)Wk, (uint2*)p_wh + off, (uint2*)p_wl + off, n4);
    }
    {
        int n4 = 512 * HIDDEN / 4;
        size_t off = (size_t)2560 * HIDDEN / 4;
        cvt_split<<<(n4 + 255) / 256, 256>>>((const float4*)Wv, (uint2*)p_wh + off, (uint2*)p_wl + off, n4);
    }
    {
        int n4 = HIDDEN * HIDDEN / 4;
        cvt_split<<<(n4 + 255) / 256, 256>>>((const float4*)Wo, (uint2*)p_woh, (uint2*)p_wol, n4);
    }

    // 2) QKV projection (HMMA, 128x256 tiles) -> g_qkv fp32
    gemm_mma<<<dim3(BATCH * LSEQ / GMT, QKV_COLS / GNT), 256, GEMM_SMEM>>>(
        (const __nv_bfloat16*)p_xh, (const __nv_bfloat16*)p_xl,
        (const __nv_bfloat16*)p_wh, (const __nv_bfloat16*)p_wl,
        (float*)p_qkv, QKV_COLS);

    // 3) RMSNorm + RoPE -> split-bf16 Q (scaled) / K
    normrope_split<<<dim3(BATCH * LSEQ, H_HEADS + KV_HEADS), 128>>>(cosp, sinp, qw, kw);

    // 4) V transpose + split -> g_vth/g_vtl
    vtrans<<<dim3(LSEQ / 32, DHEAD / 32, BATCH * KV_HEADS), dim3(32, 8)>>>();

    // 5) HMMA sliding-window flash attention -> g_ah/g_al
    attn_mma<<<dim3(LSEQ / AQT, H_HEADS, BATCH), 256, ATT_SMEM2>>>();

    // 6) Output projection (HMMA, 128x256 tiles) -> d_out
    gemm_mma<<<dim3(BATCH * LSEQ / GMT, HIDDEN / GNT), 256, GEMM_SMEM>>>(
        (const __nv_bfloat16*)p_ah, (const __nv_bfloat16*)p_al,
        (const __nv_bfloat16*)p_woh, (const __nv_bfloat16*)p_wol,
        out, HIDDEN);
}

// round 10
// speedup vs baseline: 3.7231x; 1.1872x over previous
#include <cuda_runtime.h>
#include <cuda_bf16.h>
#include <cuda_fp16.h>
#include <math.h>
#include <stdint.h>

// Problem constants
#define H_HEADS   16
#define KV_HEADS  4
#define DHEAD     128
#define LSEQ      2048
#define BATCH     2
#define HIDDEN    2048
#define QKV_COLS  3072      // 2048 q + 512 k + 512 v
#define WIN       512
#define KDIM      2048

// ---------------------------------------------------------------------------
// Scratch (device globals; no allocation)
// ---------------------------------------------------------------------------
__device__ float         g_qkv[(size_t)BATCH * LSEQ * QKV_COLS];   // fp32 [B*L, 3072]
__device__ __nv_bfloat16 g_xh [(size_t)BATCH * LSEQ * HIDDEN];     // x hi (bf16, QKV 3p)
__device__ __nv_bfloat16 g_xl [(size_t)BATCH * LSEQ * HIDDEN];
__device__ __nv_bfloat16 g_wh [(size_t)QKV_COLS * HIDDEN];         // Wq|Wk|Wv hi (bf16)
__device__ __nv_bfloat16 g_wl [(size_t)QKV_COLS * HIDDEN];
// fp16 operands for attention + O projection (2-product path)
__device__ __half g_wo16[(size_t)HIDDEN * HIDDEN];                 // Wo single fp16
__device__ __half g_ah16[(size_t)BATCH * LSEQ * HIDDEN];           // attn out hi
__device__ __half g_al16[(size_t)BATCH * LSEQ * HIDDEN];           // attn out lo
__device__ __half g_q16h[(size_t)BATCH * H_HEADS  * LSEQ * DHEAD]; // Q hi (pre-scaled)
__device__ __half g_q16l[(size_t)BATCH * H_HEADS  * LSEQ * DHEAD]; // Q lo
__device__ __half g_k16 [(size_t)BATCH * KV_HEADS * LSEQ * DHEAD]; // K single
__device__ __half g_vt16[(size_t)BATCH * KV_HEADS * DHEAD * LSEQ]; // V^T single [d][l]

// ---------------------------------------------------------------------------
// Base-ISA PTX helpers
// ---------------------------------------------------------------------------
__device__ __forceinline__ uint32_t smem_u32(const void* p) {
    uint32_t r;
    asm("{ .reg .u64 t; cvta.to.shared.u64 t, %1; cvt.u32.u64 %0, t; }" : "=r"(r) : "l"(p));
    return r;
}
__device__ __forceinline__ void cpa16(uint32_t s, const void* g) {
    asm volatile("cp.async.cg.shared.global [%0], [%1], 16;" :: "r"(s), "l"(g));
}
#define CPA_COMMIT() asm volatile("cp.async.commit_group;" ::: "memory")
#define CPA_WAIT(n)  asm volatile("cp.async.wait_group %0;" :: "n"(n) : "memory")

__device__ __forceinline__ uint32_t swz(uint32_t o) { return o ^ ((o >> 3) & 0x70); }

__device__ __forceinline__ void ldmx4(uint32_t* r, uint32_t a) {
    asm volatile("ldmatrix.sync.aligned.m8n8.x4.shared.b16 {%0,%1,%2,%3}, [%4];"
        : "=r"(r[0]), "=r"(r[1]), "=r"(r[2]), "=r"(r[3]) : "r"(a));
}
__device__ __forceinline__ void mma_bf16(float* c, const uint32_t* a, const uint32_t* b) {
    asm volatile("mma.sync.aligned.m16n8k16.row.col.f32.bf16.bf16.f32 "
        "{%0,%1,%2,%3}, {%4,%5,%6,%7}, {%8,%9}, {%0,%1,%2,%3};"
        : "+f"(c[0]), "+f"(c[1]), "+f"(c[2]), "+f"(c[3])
        : "r"(a[0]), "r"(a[1]), "r"(a[2]), "r"(a[3]), "r"(b[0]), "r"(b[1]));
}
__device__ __forceinline__ void mma_f16(float* c, const uint32_t* a, const uint32_t* b) {
    asm volatile("mma.sync.aligned.m16n8k16.row.col.f32.f16.f16.f32 "
        "{%0,%1,%2,%3}, {%4,%5,%6,%7}, {%8,%9}, {%0,%1,%2,%3};"
        : "+f"(c[0]), "+f"(c[1]), "+f"(c[2]), "+f"(c[3])
        : "r"(a[0]), "r"(a[1]), "r"(a[2]), "r"(a[3]), "r"(b[0]), "r"(b[1]));
}
__device__ __forceinline__ unsigned pk2(__nv_bfloat16 a, __nv_bfloat16 b) {
    __nv_bfloat162 t = __halves2bfloat162(a, b);
    return *reinterpret_cast<unsigned*>(&t);
}
__device__ __forceinline__ unsigned pk2h(__half a, __half b) {
    __half2 t = __halves2half2(a, b);
    return *reinterpret_cast<unsigned*>(&t);
}

// ---------------------------------------------------------------------------
// Split-bf16 HMMA GEMM (proven, 3-product), 128x256 tile — used for QKV
// ---------------------------------------------------------------------------
#define GMT 128
#define GNT 256
#define GNKC (KDIM / 64)
#define G_OFF_AH 0
#define G_OFF_AL 16384
#define G_OFF_BH 32768
#define G_OFF_BL 65536
#define G_STAGE  98304
#define GEMM_SMEM (2 * G_STAGE)

__global__ __launch_bounds__(256, 1)
void gemm_mma(const __nv_bfloat16* __restrict__ Ah, const __nv_bfloat16* __restrict__ Al,
              const __nv_bfloat16* __restrict__ Bh, const __nv_bfloat16* __restrict__ Bl,
              float* __restrict__ C, int ldc)
{
    extern __shared__ __align__(128) char dsm[];
    const uint32_t base = smem_u32(dsm);
    const int tid = threadIdx.x, lane = tid & 31, wid = tid >> 5;
    const int wm = wid & 3, wn = wid >> 2;
    const int m0 = blockIdx.x * GMT, n0 = blockIdx.y * GNT;

    const int a_row  = wm * 32 + (lane & 15);
    const int a_k    = (lane >> 4) * 8;
    const int b_rowg = (lane >> 4) * 8 + (lane & 7);
    const int b_k    = ((lane >> 3) & 1) * 8;

    float acc[2][16][4];
#pragma unroll
    for (int i = 0; i < 2; i++)
#pragma unroll
        for (int j = 0; j < 16; j++)
#pragma unroll
            for (int q = 0; q < 4; q++) acc[i][j][q] = 0.0f;

    auto load_stage = [&](int kc, int s) {
        const uint32_t sb = base + (uint32_t)s * G_STAGE;
#pragma unroll
        for (int i = 0; i < 4; i++) {
            int u = tid + 256 * i;
            int r = u >> 3, cu = u & 7;
            uint32_t so = swz((uint32_t)(r * 128 + cu * 16));
            size_t ga = ((size_t)(m0 + r) << 11) + (kc << 6) + (cu << 3);
            cpa16(sb + G_OFF_AH + so, Ah + ga);
            cpa16(sb + G_OFF_AL + so, Al + ga);
        }
#pragma unroll
        for (int i = 0; i < 8; i++) {
            int u = tid + 256 * i;
            int r = u >> 3, cu = u & 7;
            uint32_t so = swz((uint32_t)(r * 128 + cu * 16));
            size_t gb = ((size_t)(n0 + r) << 11) + (kc << 6) + (cu << 3);
            cpa16(sb + G_OFF_BH + so, Bh + gb);
            cpa16(sb + G_OFF_BL + so, Bl + gb);
        }
        CPA_COMMIT();
    };

    load_stage(0, 0);

    for (int kc = 0; kc < GNKC; kc++) {
        if (kc + 1 < GNKC) { load_stage(kc + 1, (kc + 1) & 1); CPA_WAIT(1); }
        else               { CPA_WAIT(0); }
        __syncthreads();

        const uint32_t sb = base + (uint32_t)(kc & 1) * G_STAGE;
        const uint32_t ah_b = sb + G_OFF_AH, al_b = sb + G_OFF_AL;
        const uint32_t bh_b = sb + G_OFF_BH, bl_b = sb + G_OFF_BL;

#pragma unroll
        for (int ks = 0; ks < 4; ks++) {
            uint32_t afh[2][4], afl[2][4];
#pragma unroll
            for (int i = 0; i < 2; i++) {
                uint32_t off = swz((uint32_t)((a_row + i * 16) * 128 + (a_k + ks * 16) * 2));
                ldmx4(afh[i], ah_b + off);
                ldmx4(afl[i], al_b + off);
            }
#pragma unroll
            for (int jp = 0; jp < 8; jp++) {
                int nrow = wn * 128 + jp * 16 + b_rowg;
                uint32_t off = swz((uint32_t)(nrow * 128 + (b_k + ks * 16) * 2));
                uint32_t bh[4], bl[4];
                ldmx4(bh, bh_b + off);
                ldmx4(bl, bl_b + off);
#pragma unroll
                for (int i = 0; i < 2; i++) {
                    mma_bf16(acc[i][2 * jp],     afh[i], &bh[0]);
                    mma_bf16(acc[i][2 * jp + 1], afh[i], &bh[2]);
                    mma_bf16(acc[i][2 * jp],     afh[i], &bl[0]);
                    mma_bf16(acc[i][2 * jp + 1], afh[i], &bl[2]);
                    mma_bf16(acc[i][2 * jp],     afl[i], &bh[0]);
                    mma_bf16(acc[i][2 * jp + 1], afl[i], &bh[2]);
                }
            }
        }
        __syncthreads();
    }

#pragma unroll
    for (int i = 0; i < 2; i++) {
        int row = m0 + wm * 32 + i * 16 + (lane >> 2);
#pragma unroll
        for (int j = 0; j < 16; j++) {
            int col = n0 + wn * 128 + j * 8 + 2 * (lane & 3);
            *(float2*)&C[(size_t)row * ldc + col]       = make_float2(acc[i][j][0], acc[i][j][1]);
            *(float2*)&C[(size_t)(row + 8) * ldc + col] = make_float2(acc[i][j][2], acc[i][j][3]);
        }
    }
}

// ---------------------------------------------------------------------------
// fp16 2-product HMMA GEMM, 128x256 tile: D = Ah*Bh + Al*Bh — used for O proj
// ---------------------------------------------------------------------------
#define F_OFF_AH 0
#define F_OFF_AL 16384
#define F_OFF_BH 32768
#define F_STAGE  65536
#define GEMMF_SMEM (2 * F_STAGE)     // 128 KB

__global__ __launch_bounds__(256, 1)
void gemm_f16(const __half* __restrict__ Ah, const __half* __restrict__ Al,
              const __half* __restrict__ Bh, float* __restrict__ C, int ldc)
{
    extern __shared__ __align__(128) char dsm[];
    const uint32_t base = smem_u32(dsm);
    const int tid = threadIdx.x, lane = tid & 31, wid = tid >> 5;
    const int wm = wid & 3, wn = wid >> 2;
    const int m0 = blockIdx.x * GMT, n0 = blockIdx.y * GNT;

    const int a_row  = wm * 32 + (lane & 15);
    const int a_k    = (lane >> 4) * 8;
    const int b_rowg = (lane >> 4) * 8 + (lane & 7);
    const int b_k    = ((lane >> 3) & 1) * 8;

    float acc[2][16][4];
#pragma unroll
    for (int i = 0; i < 2; i++)
#pragma unroll
        for (int j = 0; j < 16; j++)
#pragma unroll
            for (int q = 0; q < 4; q++) acc[i][j][q] = 0.0f;

    auto load_stage = [&](int kc, int s) {
        const uint32_t sb = base + (uint32_t)s * F_STAGE;
#pragma unroll
        for (int i = 0; i < 4; i++) {
            int u = tid + 256 * i;
            int r = u >> 3, cu = u & 7;
            uint32_t so = swz((uint32_t)(r * 128 + cu * 16));
            size_t ga = ((size_t)(m0 + r) << 11) + (kc << 6) + (cu << 3);
            cpa16(sb + F_OFF_AH + so, Ah + ga);
            cpa16(sb + F_OFF_AL + so, Al + ga);
        }
#pragma unroll
        for (int i = 0; i < 8; i++) {
            int u = tid + 256 * i;
            int r = u >> 3, cu = u & 7;
            uint32_t so = swz((uint32_t)(r * 128 + cu * 16));
            size_t gb = ((size_t)(n0 + r) << 11) + (kc << 6) + (cu << 3);
            cpa16(sb + F_OFF_BH + so, Bh + gb);
        }
        CPA_COMMIT();
    };

    load_stage(0, 0);

    for (int kc = 0; kc < GNKC; kc++) {
        if (kc + 1 < GNKC) { load_stage(kc + 1, (kc + 1) & 1); CPA_WAIT(1); }
        else               { CPA_WAIT(0); }
        __syncthreads();

        const uint32_t sb = base + (uint32_t)(kc & 1) * F_STAGE;
        const uint32_t ah_b = sb + F_OFF_AH, al_b = sb + F_OFF_AL, bh_b = sb + F_OFF_BH;

#pragma unroll
        for (int ks = 0; ks < 4; ks++) {
            uint32_t afh[2][4], afl[2][4];
#pragma unroll
            for (int i = 0; i < 2; i++) {
                uint32_t off = swz((uint32_t)((a_row + i * 16) * 128 + (a_k + ks * 16) * 2));
                ldmx4(afh[i], ah_b + off);
                ldmx4(afl[i], al_b + off);
            }
#pragma unroll
            for (int jp = 0; jp < 8; jp++) {
                int nrow = wn * 128 + jp * 16 + b_rowg;
                uint32_t off = swz((uint32_t)(nrow * 128 + (b_k + ks * 16) * 2));
                uint32_t bh[4];
                ldmx4(bh, bh_b + off);
#pragma unroll
                for (int i = 0; i < 2; i++) {
                    mma_f16(acc[i][2 * jp],     afh[i], &bh[0]);
                    mma_f16(acc[i][2 * jp + 1], afh[i], &bh[2]);
                    mma_f16(acc[i][2 * jp],     afl[i], &bh[0]);
                    mma_f16(acc[i][2 * jp + 1], afl[i], &bh[2]);
                }
            }
        }
        __syncthreads();
    }

#pragma unroll
    for (int i = 0; i < 2; i++) {
        int row = m0 + wm * 32 + i * 16 + (lane >> 2);
#pragma unroll
        for (int j = 0; j < 16; j++) {
            int col = n0 + wn * 128 + j * 8 + 2 * (lane & 3);
            *(float2*)&C[(size_t)row * ldc + col]       = make_float2(acc[i][j][0], acc[i][j][1]);
            *(float2*)&C[(size_t)(row + 8) * ldc + col] = make_float2(acc[i][j][2], acc[i][j][3]);
        }
    }
}

// ---------------------------------------------------------------------------
// Conversions
// ---------------------------------------------------------------------------
__global__ __launch_bounds__(256)
void cvt_split(const float4* __restrict__ src, uint2* __restrict__ hi,
               uint2* __restrict__ lo, int n4)
{
    int i = blockIdx.x * 256 + threadIdx.x;
    if (i >= n4) return;
    float4 v = src[i];
    __nv_bfloat16 h0 = __float2bfloat16(v.x), h1 = __float2bfloat16(v.y);
    __nv_bfloat16 h2 = __float2bfloat16(v.z), h3 = __float2bfloat16(v.w);
    __nv_bfloat16 l0 = __float2bfloat16(v.x - __bfloat162float(h0));
    __nv_bfloat16 l1 = __float2bfloat16(v.y - __bfloat162float(h1));
    __nv_bfloat16 l2 = __float2bfloat16(v.z - __bfloat162float(h2));
    __nv_bfloat16 l3 = __float2bfloat16(v.w - __bfloat162float(h3));
    hi[i] = make_uint2(pk2(h0, h1), pk2(h2, h3));
    lo[i] = make_uint2(pk2(l0, l1), pk2(l2, l3));
}

__global__ __launch_bounds__(256)
void cvt_half(const float4* __restrict__ src, uint2* __restrict__ dst, int n4)
{
    int i = blockIdx.x * 256 + threadIdx.x;
    if (i >= n4) return;
    float4 v = src[i];
    dst[i] = make_uint2(pk2h(__float2half_rn(v.x), __float2half_rn(v.y)),
                        pk2h(__float2half_rn(v.z), __float2half_rn(v.w)));
}

// ---------------------------------------------------------------------------
// RMSNorm + RoPE -> fp16: Q split hi/lo (pre-scaled), K single
// ---------------------------------------------------------------------------
__global__ __launch_bounds__(128)
void normrope_split(const float* __restrict__ cosp, const float* __restrict__ sinp,
                    const float* __restrict__ qw,  const float* __restrict__ kw)
{
    int m = blockIdx.x;
    int e = blockIdx.y;
    int t = threadIdx.x;
    int l = m & (LSEQ - 1);
    int b = m >> 11;

    const float* p;
    const float* w;
    float sc;
    bool isq = (e < H_HEADS);
    size_t o;
    if (isq) {
        p = g_qkv + (size_t)m * QKV_COLS + e * DHEAD; w = qw;
        o = ((size_t)(b * H_HEADS + e) * LSEQ + l) * DHEAD;
        sc = 0.08838834764831845f;
    } else {
        int kvh = e - H_HEADS;
        p = g_qkv + (size_t)m * QKV_COLS + 2048 + kvh * DHEAD; w = kw;
        o = ((size_t)(b * KV_HEADS + kvh) * LSEQ + l) * DHEAD;
        sc = 1.0f;
    }

    float v = p[t];
    float ss = v * v;
#pragma unroll
    for (int off = 16; off; off >>= 1) ss += __shfl_xor_sync(0xffffffffu, ss, off);

    __shared__ float sred[4];
    __shared__ float sval[128];
    if ((t & 31) == 0) sred[t >> 5] = ss;
    __syncthreads();
    ss = sred[0] + sred[1] + sred[2] + sred[3];

    float n = v * rsqrtf(ss * (1.0f / 128.0f) + 1e-6f) * w[t];
    sval[t] = n;
    __syncthreads();
    float rot = (t < 64) ? -sval[t + 64] : sval[t - 64];
    float val = (n * cosp[l * DHEAD + t] + rot * sinp[l * DHEAD + t]) * sc;
    if (isq) {
        __half hh = __float2half_rn(val);
        g_q16h[o + t] = hh;
        g_q16l[o + t] = __float2half_rn(val - __half2float(hh));
    } else {
        g_k16[o + t] = __float2half_rn(val);
    }
}

// ---------------------------------------------------------------------------
// V transpose: g_qkv v cols -> g_vt16 [b][kvh][d][l] (fp16 single)
// ---------------------------------------------------------------------------
__global__ __launch_bounds__(256)
void vtrans()
{
    __shared__ float tile[32][33];
    int tx = threadIdx.x, ty = threadIdx.y;
    int l0 = blockIdx.x * 32, d0 = blockIdx.y * 32, bk = blockIdx.z;
    int b = bk >> 2, kvh = bk & 3;

#pragma unroll
    for (int i = 0; i < 4; i++) {
        int l = l0 + ty + 8 * i;
        tile[ty + 8 * i][tx] =
            g_qkv[((size_t)(b * LSEQ + l)) * QKV_COLS + 2560 + kvh * DHEAD + d0 + tx];
    }
    __syncthreads();
#pragma unroll
    for (int i = 0; i < 4; i++) {
        int d = d0 + ty + 8 * i;
        size_t o = ((size_t)bk * DHEAD + d) * LSEQ + l0 + tx;
        g_vt16[o] = __float2half_rn(tile[tx][ty + 8 * i]);
    }
}

// ---------------------------------------------------------------------------
// fp16 HMMA flash attention: QK = Qh*Kh + Ql*Kh; PV = Ph*Vh + Pl*Vh
// CTA: 128 q rows x head x batch, 8 warps. KCH=64 keys/chunk, double-buffered.
// ---------------------------------------------------------------------------
#define AQT 128
#define AKC 64
#define A_QH 0
#define A_QL 32768
#define A_STG0 65536
#define A_STG_SZ 32768
#define AS_KH 0
#define AS_VH 16384
#define ATT_SMEM2 131072

__global__ __launch_bounds__(256, 1)
void attn_mma()
{
    extern __shared__ __align__(128) char asmem[];
    const uint32_t base = smem_u32(asmem);
    const int tid = threadIdx.x, lane = tid & 31, w = tid >> 5;
    const int qt = blockIdx.x, h = blockIdx.y, b = blockIdx.z;
    const int kvh = h >> 2;
    const int q0 = qt * AQT;

    {
        const __half* qh = g_q16h + ((size_t)(b * H_HEADS + h) * LSEQ + q0) * DHEAD;
        const __half* ql = g_q16l + ((size_t)(b * H_HEADS + h) * LSEQ + q0) * DHEAD;
#pragma unroll
        for (int i = 0; i < 8; i++) {
            int u = tid + 256 * i;
            int r = u >> 4, cu = u & 15;
            uint32_t so = (uint32_t)(cu >> 3) * 16384 + swz((uint32_t)(r * 128 + (cu & 7) * 16));
            cpa16(base + A_QH + so, qh + (size_t)r * DHEAD + cu * 8);
            cpa16(base + A_QL + so, ql + (size_t)r * DHEAD + cu * 8);
        }
        CPA_COMMIT();
    }

    int kstart = q0 - WIN;       if (kstart < 0)  kstart = 0;
    int kend   = q0 + AQT + WIN; if (kend > LSEQ) kend = LSEQ;
    const int nc = (kend - kstart) / AKC;

    const __half* kh  = g_k16  + (size_t)(b * KV_HEADS + kvh) * LSEQ * DHEAD;
    const __half* vth = g_vt16 + (size_t)(b * KV_HEADS + kvh) * DHEAD * LSEQ;

    auto load_kv = [&](int c, int s) {
        const uint32_t sb = base + A_STG0 + (uint32_t)s * A_STG_SZ;
        const int ks = kstart + c * AKC;
#pragma unroll
        for (int i = 0; i < 4; i++) {
            int u = tid + 256 * i;
            int r = u >> 4, cu = u & 15;
            uint32_t so = (uint32_t)(cu >> 3) * 8192 + swz((uint32_t)(r * 128 + (cu & 7) * 16));
            cpa16(sb + AS_KH + so, kh + (size_t)(ks + r) * DHEAD + cu * 8);
        }
#pragma unroll
        for (int i = 0; i < 4; i++) {
            int u = tid + 256 * i;
            int d = u >> 3, cu = u & 7;
            uint32_t so = swz((uint32_t)(d * 128 + cu * 16));
            cpa16(sb + AS_VH + so, vth + (size_t)d * LSEQ + ks + cu * 8);
        }
        CPA_COMMIT();
    };

    load_kv(0, 0);

    const int a_row  = w * 16 + (lane & 15);
    const int a_k    = (lane >> 4) * 8;
    const int b_rowg = (lane >> 4) * 8 + (lane & 7);
    const int b_k    = ((lane >> 3) & 1) * 8;
    const int r0     = lane >> 2, colb = 2 * (lane & 3);
    const int qrow0  = q0 + w * 16 + r0;
    const int qrow1  = qrow0 + 8;

    float out[16][4];
#pragma unroll
    for (int na = 0; na < 16; na++)
#pragma unroll
        for (int q = 0; q < 4; q++) out[na][q] = 0.0f;
    float m0 = -1e30f, m1 = -1e30f, l0s = 0.0f, l1s = 0.0f;

    for (int c = 0; c < nc; c++) {
        if (c + 1 < nc) { load_kv(c + 1, (c + 1) & 1); CPA_WAIT(1); }
        else            { CPA_WAIT(0); }
        __syncthreads();
        const uint32_t sb = base + A_STG0 + (uint32_t)(c & 1) * A_STG_SZ;

        float sacc[8][4];
#pragma unroll
        for (int j = 0; j < 8; j++)
#pragma unroll
            for (int q = 0; q < 4; q++) sacc[j][q] = 0.0f;

#pragma unroll
        for (int ks = 0; ks < 8; ks++) {
            int pnl = ks >> 2, kk = (ks & 3) * 16;
            uint32_t aoff = (uint32_t)pnl * 16384 + swz((uint32_t)(a_row * 128 + (kk + a_k) * 2));
            uint32_t aqh[4], aql[4];
            ldmx4(aqh, base + A_QH + aoff);
            ldmx4(aql, base + A_QL + aoff);
#pragma unroll
            for (int jp = 0; jp < 4; jp++) {
                uint32_t boff = (uint32_t)pnl * 8192 +
                    swz((uint32_t)((jp * 16 + b_rowg) * 128 + (kk + b_k) * 2));
                uint32_t bkh[4];
                ldmx4(bkh, sb + AS_KH + boff);
                mma_f16(sacc[2 * jp],     aqh, &bkh[0]);
                mma_f16(sacc[2 * jp + 1], aqh, &bkh[2]);
                mma_f16(sacc[2 * jp],     aql, &bkh[0]);
                mma_f16(sacc[2 * jp + 1], aql, &bkh[2]);
            }
        }

        const int ks0 = kstart + c * AKC;
        float mx0 = -1e30f, mx1 = -1e30f;
#pragma unroll
        for (int j = 0; j < 8; j++) {
            int k0 = ks0 + j * 8 + colb, k1 = k0 + 1;
            int d00 = qrow0 - k0; if (d00 < 0) d00 = -d00;
            int d01 = qrow0 - k1; if (d01 < 0) d01 = -d01;
            int d10 = qrow1 - k0; if (d10 < 0) d10 = -d10;
            int d11 = qrow1 - k1; if (d11 < 0) d11 = -d11;
            if (d00 > WIN) sacc[j][0] = -1e30f;
            if (d01 > WIN) sacc[j][1] = -1e30f;
            if (d10 > WIN) sacc[j][2] = -1e30f;
            if (d11 > WIN) sacc[j][3] = -1e30f;
            mx0 = fmaxf(mx0, fmaxf(sacc[j][0], sacc[j][1]));
            mx1 = fmaxf(mx1, fmaxf(sacc[j][2], sacc[j][3]));
        }
        mx0 = fmaxf(mx0, __shfl_xor_sync(0xffffffffu, mx0, 1));
        mx0 = fmaxf(mx0, __shfl_xor_sync(0xffffffffu, mx0, 2));
        mx1 = fmaxf(mx1, __shfl_xor_sync(0xffffffffu, mx1, 1));
        mx1 = fmaxf(mx1, __shfl_xor_sync(0xffffffffu, mx1, 2));

        float mn0 = fmaxf(m0, mx0), mn1 = fmaxf(m1, mx1);
        float c0f = __expf(m0 - mn0), c1f = __expf(m1 - mn1);
        m0 = mn0; m1 = mn1;

        float rs0 = 0.0f, rs1 = 0.0f;
        uint32_t ph[8], ph2[8], pl[8], pl2[8];
#pragma unroll
        for (int j = 0; j < 8; j++) {
            float p0 = (sacc[j][0] > -9e29f) ? __expf(sacc[j][0] - mn0) : 0.0f;
            float p1 = (sacc[j][1] > -9e29f) ? __expf(sacc[j][1] - mn0) : 0.0f;
            float p2 = (sacc[j][2] > -9e29f) ? __expf(sacc[j][2] - mn1) : 0.0f;
            float p3 = (sacc[j][3] > -9e29f) ? __expf(sacc[j][3] - mn1) : 0.0f;
            rs0 += p0 + p1; rs1 += p2 + p3;
            __half h0 = __float2half_rn(p0), h1v = __float2half_rn(p1);
            __half h2 = __float2half_rn(p2), h3v = __float2half_rn(p3);
            ph[j]  = pk2h(h0, h1v);
            ph2[j] = pk2h(h2, h3v);
            pl[j]  = pk2h(__float2half_rn(p0 - __half2float(h0)),
                          __float2half_rn(p1 - __half2float(h1v)));
            pl2[j] = pk2h(__float2half_rn(p2 - __half2float(h2)),
                          __float2half_rn(p3 - __half2float(h3v)));
        }
        rs0 += __shfl_xor_sync(0xffffffffu, rs0, 1);
        rs0 += __shfl_xor_sync(0xffffffffu, rs0, 2);
        rs1 += __shfl_xor_sync(0xffffffffu, rs1, 1);
        rs1 += __shfl_xor_sync(0xffffffffu, rs1, 2);
        l0s = l0s * c0f + rs0;
        l1s = l1s * c1f + rs1;
#pragma unroll
        for (int na = 0; na < 16; na++) {
            out[na][0] *= c0f; out[na][1] *= c0f;
            out[na][2] *= c1f; out[na][3] *= c1f;
        }

#pragma unroll
        for (int ks2 = 0; ks2 < 4; ks2++) {
            uint32_t Ahf[4] = { ph[2 * ks2], ph2[2 * ks2], ph[2 * ks2 + 1], ph2[2 * ks2 + 1] };
            uint32_t Alf[4] = { pl[2 * ks2], pl2[2 * ks2], pl[2 * ks2 + 1], pl2[2 * ks2 + 1] };
#pragma unroll
            for (int jp = 0; jp < 8; jp++) {
                uint32_t voff = swz((uint32_t)((jp * 16 + b_rowg) * 128 + (ks2 * 16 + b_k) * 2));
                uint32_t vh[4];
                ldmx4(vh, sb + AS_VH + voff);
                mma_f16(out[2 * jp],     Ahf, &vh[0]);
                mma_f16(out[2 * jp + 1], Ahf, &vh[2]);
                mma_f16(out[2 * jp],     Alf, &vh[0]);
                mma_f16(out[2 * jp + 1], Alf, &vh[2]);
            }
        }
        __syncthreads();
    }

    // epilogue: normalize, split-fp16 store for O-GEMM A operand
    float inv0 = 1.0f / l0s, inv1 = 1.0f / l1s;
    size_t rb0 = ((size_t)b * LSEQ + qrow0) * HIDDEN + h * DHEAD;
    size_t rb1 = rb0 + (size_t)8 * HIDDEN;
#pragma unroll
    for (int na = 0; na < 16; na++) {
        int d = na * 8 + colb;
        float o0 = out[na][0] * inv0, o1 = out[na][1] * inv0;
        float o2 = out[na][2] * inv1, o3 = out[na][3] * inv1;
        __half a0 = __float2half_rn(o0), a1 = __float2half_rn(o1);
        __half a2 = __float2half_rn(o2), a3 = __float2half_rn(o3);
        *(uint32_t*)(g_ah16 + rb0 + d) = pk2h(a0, a1);
        *(uint32_t*)(g_ah16 + rb1 + d) = pk2h(a2, a3);
        *(uint32_t*)(g_al16 + rb0 + d) = pk2h(__float2half_rn(o0 - __half2float(a0)),
                                              __float2half_rn(o1 - __half2float(a1)));
        *(uint32_t*)(g_al16 + rb1 + d) = pk2h(__float2half_rn(o2 - __half2float(a2)),
                                              __float2half_rn(o3 - __half2float(a3)));
    }
}

// ---------------------------------------------------------------------------
// Launch. Inputs: x, cos, sin, Wq, Wk, Wv, Wo, q_norm_w, k_norm_w
// ---------------------------------------------------------------------------
extern "C" void kernel_launch(void* const* d_in, const int* in_sizes, int n_in,
                              void* d_out, int out_size)
{
    const float* x    = (const float*)d_in[0];
    const float* cosp = (const float*)d_in[1];
    const float* sinp = (const float*)d_in[2];
    const float* Wq   = (const float*)d_in[3];
    const float* Wk   = (const float*)d_in[4];
    const float* Wv   = (const float*)d_in[5];
    const float* Wo   = (const float*)d_in[6];
    const float* qw   = (const float*)d_in[7];
    const float* kw   = (const float*)d_in[8];
    float* out = (float*)d_out;

    void *p_qkv, *p_xh, *p_xl, *p_wh, *p_wl, *p_wo16, *p_ah, *p_al;
    cudaGetSymbolAddress(&p_qkv,  g_qkv);
    cudaGetSymbolAddress(&p_xh,   g_xh);  cudaGetSymbolAddress(&p_xl, g_xl);
    cudaGetSymbolAddress(&p_wh,   g_wh);  cudaGetSymbolAddress(&p_wl, g_wl);
    cudaGetSymbolAddress(&p_wo16, g_wo16);
    cudaGetSymbolAddress(&p_ah,   g_ah16); cudaGetSymbolAddress(&p_al, g_al16);

    cudaFuncSetAttribute(gemm_mma, cudaFuncAttributeMaxDynamicSharedMemorySize, GEMM_SMEM);
    cudaFuncSetAttribute(gemm_f16, cudaFuncAttributeMaxDynamicSharedMemorySize, GEMMF_SMEM);
    cudaFuncSetAttribute(attn_mma, cudaFuncAttributeMaxDynamicSharedMemorySize, ATT_SMEM2);

    // 1) conversions (uint2 = 4 elements -> element offset / 4)
    {
        int n4 = BATCH * LSEQ * HIDDEN / 4;
        cvt_split<<<(n4 + 255) / 256, 256>>>((const float4*)x, (uint2*)p_xh, (uint2*)p_xl, n4);
    }
    {
        int n4 = 2048 * HIDDEN / 4;
        cvt_split<<<(n4 + 255) / 256, 256>>>((const float4*)Wq, (uint2*)p_wh, (uint2*)p_wl, n4);
    }
    {
        int n4 = 512 * HIDDEN / 4;
        size_t off = (size_t)2048 * HIDDEN / 4;
        cvt_split<<<(n4 + 255) / 256, 256>>>((const float4*)Wk, (uint2*)p_wh + off, (uint2*)p_wl + off, n4);
    }
    {
        int n4 = 512 * HIDDEN / 4;
        size_t off = (size_t)2560 * HIDDEN / 4;
        cvt_split<<<(n4 + 255) / 256, 256>>>((const float4*)Wv, (uint2*)p_wh + off, (uint2*)p_wl + off, n4);
    }
    {
        int n4 = HIDDEN * HIDDEN / 4;
        cvt_half<<<(n4 + 255) / 256, 256>>>((const float4*)Wo, (uint2*)p_wo16, n4);
    }

    // 2) QKV projection (bf16 3-product HMMA) -> g_qkv fp32
    gemm_mma<<<dim3(BATCH * LSEQ / GMT, QKV_COLS / GNT), 256, GEMM_SMEM>>>(
        (const __nv_bfloat16*)p_xh, (const __nv_bfloat16*)p_xl,
        (const __nv_bfloat16*)p_wh, (const __nv_bfloat16*)p_wl,
        (float*)p_qkv, QKV_COLS);

    // 3) RMSNorm + RoPE -> fp16 Q split (scaled) / K single
    normrope_split<<<dim3(BATCH * LSEQ, H_HEADS + KV_HEADS), 128>>>(cosp, sinp, qw, kw);

    // 4) V transpose -> fp16 single
    vtrans<<<dim3(LSEQ / 32, DHEAD / 32, BATCH * KV_HEADS), dim3(32, 8)>>>();

    // 5) fp16 HMMA sliding-window flash attention -> g_ah16/g_al16
    attn_mma<<<dim3(LSEQ / AQT, H_HEADS, BATCH), 256, ATT_SMEM2>>>();

    // 6) Output projection (fp16 2-product HMMA) -> d_out
    gemm_f16<<<dim3(BATCH * LSEQ / GMT, HIDDEN / GNT), 256, GEMMF_SMEM>>>(
        (const __half*)p_ah, (const __half*)p_al,
        (const __half*)p_wo16, out, HIDDEN);
}

// round 11
// speedup vs baseline: 4.3097x; 1.1576x over previous
#include <cuda_runtime.h>
#include <cuda_fp16.h>
#include <math.h>
#include <stdint.h>

// Problem constants
#define H_HEADS   16
#define KV_HEADS  4
#define DHEAD     128
#define LSEQ      2048
#define BATCH     2
#define HIDDEN    2048
#define QKV_COLS  3072      // 2048 q + 512 k + 512 v
#define WIN       512
#define KDIM      2048

// ---------------------------------------------------------------------------
// Scratch (device globals; no allocation)
// ---------------------------------------------------------------------------
__device__ float  g_qkv[(size_t)BATCH * LSEQ * QKV_COLS];          // fp32 [B*L, 3072]
__device__ __half g_x16h[(size_t)BATCH * LSEQ * HIDDEN];           // x hi (fp16)
__device__ __half g_x16l[(size_t)BATCH * LSEQ * HIDDEN];           // x lo
__device__ __half g_w16 [(size_t)QKV_COLS * HIDDEN];               // Wq|Wk|Wv single fp16
__device__ __half g_wo16[(size_t)HIDDEN * HIDDEN];                 // Wo single fp16
__device__ __half g_ah16[(size_t)BATCH * LSEQ * HIDDEN];           // attn out hi
__device__ __half g_al16[(size_t)BATCH * LSEQ * HIDDEN];           // attn out lo
__device__ __half g_q16h[(size_t)BATCH * H_HEADS  * LSEQ * DHEAD]; // Q hi (pre-scaled)
__device__ __half g_q16l[(size_t)BATCH * H_HEADS  * LSEQ * DHEAD]; // Q lo
__device__ __half g_k16 [(size_t)BATCH * KV_HEADS * LSEQ * DHEAD]; // K single
__device__ __half g_vt16[(size_t)BATCH * KV_HEADS * DHEAD * LSEQ]; // V^T single [d][l]

// ---------------------------------------------------------------------------
// Base-ISA PTX helpers
// ---------------------------------------------------------------------------
__device__ __forceinline__ uint32_t smem_u32(const void* p) {
    uint32_t r;
    asm("{ .reg .u64 t; cvta.to.shared.u64 t, %1; cvt.u32.u64 %0, t; }" : "=r"(r) : "l"(p));
    return r;
}
__device__ __forceinline__ void cpa16(uint32_t s, const void* g) {
    asm volatile("cp.async.cg.shared.global [%0], [%1], 16;" :: "r"(s), "l"(g));
}
#define CPA_COMMIT() asm volatile("cp.async.commit_group;" ::: "memory")
#define CPA_WAIT(n)  asm volatile("cp.async.wait_group %0;" :: "n"(n) : "memory")

__device__ __forceinline__ uint32_t swz(uint32_t o) { return o ^ ((o >> 3) & 0x70); }

__device__ __forceinline__ void ldmx4(uint32_t* r, uint32_t a) {
    asm volatile("ldmatrix.sync.aligned.m8n8.x4.shared.b16 {%0,%1,%2,%3}, [%4];"
        : "=r"(r[0]), "=r"(r[1]), "=r"(r[2]), "=r"(r[3]) : "r"(a));
}
__device__ __forceinline__ void mma_f16(float* c, const uint32_t* a, const uint32_t* b) {
    asm volatile("mma.sync.aligned.m16n8k16.row.col.f32.f16.f16.f32 "
        "{%0,%1,%2,%3}, {%4,%5,%6,%7}, {%8,%9}, {%0,%1,%2,%3};"
        : "+f"(c[0]), "+f"(c[1]), "+f"(c[2]), "+f"(c[3])
        : "r"(a[0]), "r"(a[1]), "r"(a[2]), "r"(a[3]), "r"(b[0]), "r"(b[1]));
}
__device__ __forceinline__ unsigned pk2h(__half a, __half b) {
    __half2 t = __halves2half2(a, b);
    return *reinterpret_cast<unsigned*>(&t);
}

// ---------------------------------------------------------------------------
// fp16 2-product HMMA GEMM, 128x256 tile: D = Ah*Bh + Al*Bh
// Used for BOTH the QKV projection and the O projection (proven R10).
// ---------------------------------------------------------------------------
#define GMT 128
#define GNT 256
#define GNKC (KDIM / 64)
#define F_OFF_AH 0
#define F_OFF_AL 16384
#define F_OFF_BH 32768
#define F_STAGE  65536
#define GEMMF_SMEM (2 * F_STAGE)     // 128 KB

__global__ __launch_bounds__(256, 1)
void gemm_f16(const __half* __restrict__ Ah, const __half* __restrict__ Al,
              const __half* __restrict__ Bh, float* __restrict__ C, int ldc)
{
    extern __shared__ __align__(128) char dsm[];
    const uint32_t base = smem_u32(dsm);
    const int tid = threadIdx.x, lane = tid & 31, wid = tid >> 5;
    const int wm = wid & 3, wn = wid >> 2;
    const int m0 = blockIdx.x * GMT, n0 = blockIdx.y * GNT;

    const int a_row  = wm * 32 + (lane & 15);
    const int a_k    = (lane >> 4) * 8;
    const int b_rowg = (lane >> 4) * 8 + (lane & 7);
    const int b_k    = ((lane >> 3) & 1) * 8;

    float acc[2][16][4];
#pragma unroll
    for (int i = 0; i < 2; i++)
#pragma unroll
        for (int j = 0; j < 16; j++)
#pragma unroll
            for (int q = 0; q < 4; q++) acc[i][j][q] = 0.0f;

    auto load_stage = [&](int kc, int s) {
        const uint32_t sb = base + (uint32_t)s * F_STAGE;
#pragma unroll
        for (int i = 0; i < 4; i++) {
            int u = tid + 256 * i;
            int r = u >> 3, cu = u & 7;
            uint32_t so = swz((uint32_t)(r * 128 + cu * 16));
            size_t ga = ((size_t)(m0 + r) << 11) + (kc << 6) + (cu << 3);
            cpa16(sb + F_OFF_AH + so, Ah + ga);
            cpa16(sb + F_OFF_AL + so, Al + ga);
        }
#pragma unroll
        for (int i = 0; i < 8; i++) {
            int u = tid + 256 * i;
            int r = u >> 3, cu = u & 7;
            uint32_t so = swz((uint32_t)(r * 128 + cu * 16));
            size_t gb = ((size_t)(n0 + r) << 11) + (kc << 6) + (cu << 3);
            cpa16(sb + F_OFF_BH + so, Bh + gb);
        }
        CPA_COMMIT();
    };

    load_stage(0, 0);

    for (int kc = 0; kc < GNKC; kc++) {
        if (kc + 1 < GNKC) { load_stage(kc + 1, (kc + 1) & 1); CPA_WAIT(1); }
        else               { CPA_WAIT(0); }
        __syncthreads();

        const uint32_t sb = base + (uint32_t)(kc & 1) * F_STAGE;
        const uint32_t ah_b = sb + F_OFF_AH, al_b = sb + F_OFF_AL, bh_b = sb + F_OFF_BH;

#pragma unroll
        for (int ks = 0; ks < 4; ks++) {
            uint32_t afh[2][4], afl[2][4];
#pragma unroll
            for (int i = 0; i < 2; i++) {
                uint32_t off = swz((uint32_t)((a_row + i * 16) * 128 + (a_k + ks * 16) * 2));
                ldmx4(afh[i], ah_b + off);
                ldmx4(afl[i], al_b + off);
            }
#pragma unroll
            for (int jp = 0; jp < 8; jp++) {
                int nrow = wn * 128 + jp * 16 + b_rowg;
                uint32_t off = swz((uint32_t)(nrow * 128 + (b_k + ks * 16) * 2));
                uint32_t bh[4];
                ldmx4(bh, bh_b + off);
#pragma unroll
                for (int i = 0; i < 2; i++) {
                    mma_f16(acc[i][2 * jp],     afh[i], &bh[0]);
                    mma_f16(acc[i][2 * jp + 1], afh[i], &bh[2]);
                    mma_f16(acc[i][2 * jp],     afl[i], &bh[0]);
                    mma_f16(acc[i][2 * jp + 1], afl[i], &bh[2]);
                }
            }
        }
        __syncthreads();
    }

#pragma unroll
    for (int i = 0; i < 2; i++) {
        int row = m0 + wm * 32 + i * 16 + (lane >> 2);
#pragma unroll
        for (int j = 0; j < 16; j++) {
            int col = n0 + wn * 128 + j * 8 + 2 * (lane & 3);
            *(float2*)&C[(size_t)row * ldc + col]       = make_float2(acc[i][j][0], acc[i][j][1]);
            *(float2*)&C[(size_t)(row + 8) * ldc + col] = make_float2(acc[i][j][2], acc[i][j][3]);
        }
    }
}

// ---------------------------------------------------------------------------
// Conversions: fp32 -> fp16 split (hi/lo) and fp32 -> fp16 single
// ---------------------------------------------------------------------------
__global__ __launch_bounds__(256)
void cvt_split_h(const float4* __restrict__ src, uint2* __restrict__ hi,
                 uint2* __restrict__ lo, int n4)
{
    int i = blockIdx.x * 256 + threadIdx.x;
    if (i >= n4) return;
    float4 v = src[i];
    __half h0 = __float2half_rn(v.x), h1 = __float2half_rn(v.y);
    __half h2 = __float2half_rn(v.z), h3 = __float2half_rn(v.w);
    hi[i] = make_uint2(pk2h(h0, h1), pk2h(h2, h3));
    lo[i] = make_uint2(pk2h(__float2half_rn(v.x - __half2float(h0)),
                            __float2half_rn(v.y - __half2float(h1))),
                       pk2h(__float2half_rn(v.z - __half2float(h2)),
                            __float2half_rn(v.w - __half2float(h3))));
}

__global__ __launch_bounds__(256)
void cvt_half(const float4* __restrict__ src, uint2* __restrict__ dst, int n4)
{
    int i = blockIdx.x * 256 + threadIdx.x;
    if (i >= n4) return;
    float4 v = src[i];
    dst[i] = make_uint2(pk2h(__float2half_rn(v.x), __float2half_rn(v.y)),
                        pk2h(__float2half_rn(v.z), __float2half_rn(v.w)));
}

// ---------------------------------------------------------------------------
// RMSNorm + RoPE -> fp16: Q split hi/lo (pre-scaled), K single
// ---------------------------------------------------------------------------
__global__ __launch_bounds__(128)
void normrope_split(const float* __restrict__ cosp, const float* __restrict__ sinp,
                    const float* __restrict__ qw,  const float* __restrict__ kw)
{
    int m = blockIdx.x;
    int e = blockIdx.y;
    int t = threadIdx.x;
    int l = m & (LSEQ - 1);
    int b = m >> 11;

    const float* p;
    const float* w;
    float sc;
    bool isq = (e < H_HEADS);
    size_t o;
    if (isq) {
        p = g_qkv + (size_t)m * QKV_COLS + e * DHEAD; w = qw;
        o = ((size_t)(b * H_HEADS + e) * LSEQ + l) * DHEAD;
        sc = 0.08838834764831845f;
    } else {
        int kvh = e - H_HEADS;
        p = g_qkv + (size_t)m * QKV_COLS + 2048 + kvh * DHEAD; w = kw;
        o = ((size_t)(b * KV_HEADS + kvh) * LSEQ + l) * DHEAD;
        sc = 1.0f;
    }

    float v = p[t];
    float ss = v * v;
#pragma unroll
    for (int off = 16; off; off >>= 1) ss += __shfl_xor_sync(0xffffffffu, ss, off);

    __shared__ float sred[4];
    __shared__ float sval[128];
    if ((t & 31) == 0) sred[t >> 5] = ss;
    __syncthreads();
    ss = sred[0] + sred[1] + sred[2] + sred[3];

    float n = v * rsqrtf(ss * (1.0f / 128.0f) + 1e-6f) * w[t];
    sval[t] = n;
    __syncthreads();
    float rot = (t < 64) ? -sval[t + 64] : sval[t - 64];
    float val = (n * cosp[l * DHEAD + t] + rot * sinp[l * DHEAD + t]) * sc;
    if (isq) {
        __half hh = __float2half_rn(val);
        g_q16h[o + t] = hh;
        g_q16l[o + t] = __float2half_rn(val - __half2float(hh));
    } else {
        g_k16[o + t] = __float2half_rn(val);
    }
}

// ---------------------------------------------------------------------------
// V transpose: g_qkv v cols -> g_vt16 [b][kvh][d][l] (fp16 single)
// ---------------------------------------------------------------------------
__global__ __launch_bounds__(256)
void vtrans()
{
    __shared__ float tile[32][33];
    int tx = threadIdx.x, ty = threadIdx.y;
    int l0 = blockIdx.x * 32, d0 = blockIdx.y * 32, bk = blockIdx.z;
    int b = bk >> 2, kvh = bk & 3;

#pragma unroll
    for (int i = 0; i < 4; i++) {
        int l = l0 + ty + 8 * i;
        tile[ty + 8 * i][tx] =
            g_qkv[((size_t)(b * LSEQ + l)) * QKV_COLS + 2560 + kvh * DHEAD + d0 + tx];
    }
    __syncthreads();
#pragma unroll
    for (int i = 0; i < 4; i++) {
        int d = d0 + ty + 8 * i;
        size_t o = ((size_t)bk * DHEAD + d) * LSEQ + l0 + tx;
        g_vt16[o] = __float2half_rn(tile[tx][ty + 8 * i]);
    }
}

// ---------------------------------------------------------------------------
// fp16 HMMA flash attention (proven R10): QK = Qh*Kh + Ql*Kh; PV = Ph*V + Pl*V
// ---------------------------------------------------------------------------
#define AQT 128
#define AKC 64
#define A_QH 0
#define A_QL 32768
#define A_STG0 65536
#define A_STG_SZ 32768
#define AS_KH 0
#define AS_VH 16384
#define ATT_SMEM2 131072

__global__ __launch_bounds__(256, 1)
void attn_mma()
{
    extern __shared__ __align__(128) char asmem[];
    const uint32_t base = smem_u32(asmem);
    const int tid = threadIdx.x, lane = tid & 31, w = tid >> 5;
    const int qt = blockIdx.x, h = blockIdx.y, b = blockIdx.z;
    const int kvh = h >> 2;
    const int q0 = qt * AQT;

    {
        const __half* qh = g_q16h + ((size_t)(b * H_HEADS + h) * LSEQ + q0) * DHEAD;
        const __half* ql = g_q16l + ((size_t)(b * H_HEADS + h) * LSEQ + q0) * DHEAD;
#pragma unroll
        for (int i = 0; i < 8; i++) {
            int u = tid + 256 * i;
            int r = u >> 4, cu = u & 15;
            uint32_t so = (uint32_t)(cu >> 3) * 16384 + swz((uint32_t)(r * 128 + (cu & 7) * 16));
            cpa16(base + A_QH + so, qh + (size_t)r * DHEAD + cu * 8);
            cpa16(base + A_QL + so, ql + (size_t)r * DHEAD + cu * 8);
        }
        CPA_COMMIT();
    }

    int kstart = q0 - WIN;       if (kstart < 0)  kstart = 0;
    int kend   = q0 + AQT + WIN; if (kend > LSEQ) kend = LSEQ;
    const int nc = (kend - kstart) / AKC;

    const __half* kh  = g_k16  + (size_t)(b * KV_HEADS + kvh) * LSEQ * DHEAD;
    const __half* vth = g_vt16 + (size_t)(b * KV_HEADS + kvh) * DHEAD * LSEQ;

    auto load_kv = [&](int c, int s) {
        const uint32_t sb = base + A_STG0 + (uint32_t)s * A_STG_SZ;
        const int ks = kstart + c * AKC;
#pragma unroll
        for (int i = 0; i < 4; i++) {
            int u = tid + 256 * i;
            int r = u >> 4, cu = u & 15;
            uint32_t so = (uint32_t)(cu >> 3) * 8192 + swz((uint32_t)(r * 128 + (cu & 7) * 16));
            cpa16(sb + AS_KH + so, kh + (size_t)(ks + r) * DHEAD + cu * 8);
        }
#pragma unroll
        for (int i = 0; i < 4; i++) {
            int u = tid + 256 * i;
            int d = u >> 3, cu = u & 7;
            uint32_t so = swz((uint32_t)(d * 128 + cu * 16));
            cpa16(sb + AS_VH + so, vth + (size_t)d * LSEQ + ks + cu * 8);
        }
        CPA_COMMIT();
    };

    load_kv(0, 0);

    const int a_row  = w * 16 + (lane & 15);
    const int a_k    = (lane >> 4) * 8;
    const int b_rowg = (lane >> 4) * 8 + (lane & 7);
    const int b_k    = ((lane >> 3) & 1) * 8;
    const int r0     = lane >> 2, colb = 2 * (lane & 3);
    const int qrow0  = q0 + w * 16 + r0;
    const int qrow1  = qrow0 + 8;

    float out[16][4];
#pragma unroll
    for (int na = 0; na < 16; na++)
#pragma unroll
        for (int q = 0; q < 4; q++) out[na][q] = 0.0f;
    float m0 = -1e30f, m1 = -1e30f, l0s = 0.0f, l1s = 0.0f;

    for (int c = 0; c < nc; c++) {
        if (c + 1 < nc) { load_kv(c + 1, (c + 1) & 1); CPA_WAIT(1); }
        else            { CPA_WAIT(0); }
        __syncthreads();
        const uint32_t sb = base + A_STG0 + (uint32_t)(c & 1) * A_STG_SZ;

        float sacc[8][4];
#pragma unroll
        for (int j = 0; j < 8; j++)
#pragma unroll
            for (int q = 0; q < 4; q++) sacc[j][q] = 0.0f;

#pragma unroll
        for (int ks = 0; ks < 8; ks++) {
            int pnl = ks >> 2, kk = (ks & 3) * 16;
            uint32_t aoff = (uint32_t)pnl * 16384 + swz((uint32_t)(a_row * 128 + (kk + a_k) * 2));
            uint32_t aqh[4], aql[4];
            ldmx4(aqh, base + A_QH + aoff);
            ldmx4(aql, base + A_QL + aoff);
#pragma unroll
            for (int jp = 0; jp < 4; jp++) {
                uint32_t boff = (uint32_t)pnl * 8192 +
                    swz((uint32_t)((jp * 16 + b_rowg) * 128 + (kk + b_k) * 2));
                uint32_t bkh[4];
                ldmx4(bkh, sb + AS_KH + boff);
                mma_f16(sacc[2 * jp],     aqh, &bkh[0]);
                mma_f16(sacc[2 * jp + 1], aqh, &bkh[2]);
                mma_f16(sacc[2 * jp],     aql, &bkh[0]);
                mma_f16(sacc[2 * jp + 1], aql, &bkh[2]);
            }
        }

        const int ks0 = kstart + c * AKC;
        float mx0 = -1e30f, mx1 = -1e30f;
#pragma unroll
        for (int j = 0; j < 8; j++) {
            int k0 = ks0 + j * 8 + colb, k1 = k0 + 1;
            int d00 = qrow0 - k0; if (d00 < 0) d00 = -d00;
            int d01 = qrow0 - k1; if (d01 < 0) d01 = -d01;
            int d10 = qrow1 - k0; if (d10 < 0) d10 = -d10;
            int d11 = qrow1 - k1; if (d11 < 0) d11 = -d11;
            if (d00 > WIN) sacc[j][0] = -1e30f;
            if (d01 > WIN) sacc[j][1] = -1e30f;
            if (d10 > WIN) sacc[j][2] = -1e30f;
            if (d11 > WIN) sacc[j][3] = -1e30f;
            mx0 = fmaxf(mx0, fmaxf(sacc[j][0], sacc[j][1]));
            mx1 = fmaxf(mx1, fmaxf(sacc[j][2], sacc[j][3]));
        }
        mx0 = fmaxf(mx0, __shfl_xor_sync(0xffffffffu, mx0, 1));
        mx0 = fmaxf(mx0, __shfl_xor_sync(0xffffffffu, mx0, 2));
        mx1 = fmaxf(mx1, __shfl_xor_sync(0xffffffffu, mx1, 1));
        mx1 = fmaxf(mx1, __shfl_xor_sync(0xffffffffu, mx1, 2));

        float mn0 = fmaxf(m0, mx0), mn1 = fmaxf(m1, mx1);
        float c0f = __expf(m0 - mn0), c1f = __expf(m1 - mn1);
        m0 = mn0; m1 = mn1;

        float rs0 = 0.0f, rs1 = 0.0f;
        uint32_t ph[8], ph2[8], pl[8], pl2[8];
#pragma unroll
        for (int j = 0; j < 8; j++) {
            float p0 = (sacc[j][0] > -9e29f) ? __expf(sacc[j][0] - mn0) : 0.0f;
            float p1 = (sacc[j][1] > -9e29f) ? __expf(sacc[j][1] - mn0) : 0.0f;
            float p2 = (sacc[j][2] > -9e29f) ? __expf(sacc[j][2] - mn1) : 0.0f;
            float p3 = (sacc[j][3] > -9e29f) ? __expf(sacc[j][3] - mn1) : 0.0f;
            rs0 += p0 + p1; rs1 += p2 + p3;
            __half h0 = __float2half_rn(p0), h1v = __float2half_rn(p1);
            __half h2 = __float2half_rn(p2), h3v = __float2half_rn(p3);
            ph[j]  = pk2h(h0, h1v);
            ph2[j] = pk2h(h2, h3v);
            pl[j]  = pk2h(__float2half_rn(p0 - __half2float(h0)),
                          __float2half_rn(p1 - __half2float(h1v)));
            pl2[j] = pk2h(__float2half_rn(p2 - __half2float(h2)),
                          __float2half_rn(p3 - __half2float(h3v)));
        }
        rs0 += __shfl_xor_sync(0xffffffffu, rs0, 1);
        rs0 += __shfl_xor_sync(0xffffffffu, rs0, 2);
        rs1 += __shfl_xor_sync(0xffffffffu, rs1, 1);
        rs1 += __shfl_xor_sync(0xffffffffu, rs1, 2);
        l0s = l0s * c0f + rs0;
        l1s = l1s * c1f + rs1;
#pragma unroll
        for (int na = 0; na < 16; na++) {
            out[na][0] *= c0f; out[na][1] *= c0f;
            out[na][2] *= c1f; out[na][3] *= c1f;
        }

#pragma unroll
        for (int ks2 = 0; ks2 < 4; ks2++) {
            uint32_t Ahf[4] = { ph[2 * ks2], ph2[2 * ks2], ph[2 * ks2 + 1], ph2[2 * ks2 + 1] };
            uint32_t Alf[4] = { pl[2 * ks2], pl2[2 * ks2], pl[2 * ks2 + 1], pl2[2 * ks2 + 1] };
#pragma unroll
            for (int jp = 0; jp < 8; jp++) {
                uint32_t voff = swz((uint32_t)((jp * 16 + b_rowg) * 128 + (ks2 * 16 + b_k) * 2));
                uint32_t vh[4];
                ldmx4(vh, sb + AS_VH + voff);
                mma_f16(out[2 * jp],     Ahf, &vh[0]);
                mma_f16(out[2 * jp + 1], Ahf, &vh[2]);
                mma_f16(out[2 * jp],     Alf, &vh[0]);
                mma_f16(out[2 * jp + 1], Alf, &vh[2]);
            }
        }
        __syncthreads();
    }

    // epilogue: normalize, split-fp16 store for O-GEMM A operand
    float inv0 = 1.0f / l0s, inv1 = 1.0f / l1s;
    size_t rb0 = ((size_t)b * LSEQ + qrow0) * HIDDEN + h * DHEAD;
    size_t rb1 = rb0 + (size_t)8 * HIDDEN;
#pragma unroll
    for (int na = 0; na < 16; na++) {
        int d = na * 8 + colb;
        float o0 = out[na][0] * inv0, o1 = out[na][1] * inv0;
        float o2 = out[na][2] * inv1, o3 = out[na][3] * inv1;
        __half a0 = __float2half_rn(o0), a1 = __float2half_rn(o1);
        __half a2 = __float2half_rn(o2), a3 = __float2half_rn(o3);
        *(uint32_t*)(g_ah16 + rb0 + d) = pk2h(a0, a1);
        *(uint32_t*)(g_ah16 + rb1 + d) = pk2h(a2, a3);
        *(uint32_t*)(g_al16 + rb0 + d) = pk2h(__float2half_rn(o0 - __half2float(a0)),
                                              __float2half_rn(o1 - __half2float(a1)));
        *(uint32_t*)(g_al16 + rb1 + d) = pk2h(__float2half_rn(o2 - __half2float(a2)),
                                              __float2half_rn(o3 - __half2float(a3)));
    }
}

// ---------------------------------------------------------------------------
// Launch. Inputs: x, cos, sin, Wq, Wk, Wv, Wo, q_norm_w, k_norm_w
// ---------------------------------------------------------------------------
extern "C" void kernel_launch(void* const* d_in, const int* in_sizes, int n_in,
                              void* d_out, int out_size)
{
    const float* x    = (const float*)d_in[0];
    const float* cosp = (const float*)d_in[1];
    const float* sinp = (const float*)d_in[2];
    const float* Wq   = (const float*)d_in[3];
    const float* Wk   = (const float*)d_in[4];
    const float* Wv   = (const float*)d_in[5];
    const float* Wo   = (const float*)d_in[6];
    const float* qw   = (const float*)d_in[7];
    const float* kw   = (const float*)d_in[8];
    float* out = (float*)d_out;

    void *p_qkv, *p_xh, *p_xl, *p_w16, *p_wo16, *p_ah, *p_al;
    cudaGetSymbolAddress(&p_qkv,  g_qkv);
    cudaGetSymbolAddress(&p_xh,   g_x16h); cudaGetSymbolAddress(&p_xl, g_x16l);
    cudaGetSymbolAddress(&p_w16,  g_w16);
    cudaGetSymbolAddress(&p_wo16, g_wo16);
    cudaGetSymbolAddress(&p_ah,   g_ah16); cudaGetSymbolAddress(&p_al, g_al16);

    cudaFuncSetAttribute(gemm_f16, cudaFuncAttributeMaxDynamicSharedMemorySize, GEMMF_SMEM);
    cudaFuncSetAttribute(attn_mma, cudaFuncAttributeMaxDynamicSharedMemorySize, ATT_SMEM2);

    // 1) conversions (uint2 = 4 elements -> element offset / 4)
    {
        int n4 = BATCH * LSEQ * HIDDEN / 4;
        cvt_split_h<<<(n4 + 255) / 256, 256>>>((const float4*)x, (uint2*)p_xh, (uint2*)p_xl, n4);
    }
    {
        int n4 = 2048 * HIDDEN / 4;   // Wq rows 0..2047
        cvt_half<<<(n4 + 255) / 256, 256>>>((const float4*)Wq, (uint2*)p_w16, n4);
    }
    {
        int n4 = 512 * HIDDEN / 4;    // Wk rows 2048..2559
        size_t off = (size_t)2048 * HIDDEN / 4;
        cvt_half<<<(n4 + 255) / 256, 256>>>((const float4*)Wk, (uint2*)p_w16 + off, n4);
    }
    {
        int n4 = 512 * HIDDEN / 4;    // Wv rows 2560..3071
        size_t off = (size_t)2560 * HIDDEN / 4;
        cvt_half<<<(n4 + 255) / 256, 256>>>((const float4*)Wv, (uint2*)p_w16 + off, n4);
    }
    {
        int n4 = HIDDEN * HIDDEN / 4; // Wo
        cvt_half<<<(n4 + 255) / 256, 256>>>((const float4*)Wo, (uint2*)p_wo16, n4);
    }

    // 2) QKV projection (fp16 2-product HMMA) -> g_qkv fp32
    gemm_f16<<<dim3(BATCH * LSEQ / GMT, QKV_COLS / GNT), 256, GEMMF_SMEM>>>(
        (const __half*)p_xh, (const __half*)p_xl,
        (const __half*)p_w16, (float*)p_qkv, QKV_COLS);

    // 3) RMSNorm + RoPE -> fp16 Q split (scaled) / K single
    normrope_split<<<dim3(BATCH * LSEQ, H_HEADS + KV_HEADS), 128>>>(cosp, sinp, qw, kw);

    // 4) V transpose -> fp16 single
    vtrans<<<dim3(LSEQ / 32, DHEAD / 32, BATCH * KV_HEADS), dim3(32, 8)>>>();

    // 5) fp16 HMMA sliding-window flash attention -> g_ah16/g_al16
    attn_mma<<<dim3(LSEQ / AQT, H_HEADS, BATCH), 256, ATT_SMEM2>>>();

    // 6) Output projection (fp16 2-product HMMA) -> d_out
    gemm_f16<<<dim3(BATCH * LSEQ / GMT, HIDDEN / GNT), 256, GEMMF_SMEM>>>(
        (const __half*)p_ah, (const __half*)p_al,
        (const __half*)p_wo16, out, HIDDEN);
}

// round 13
// speedup vs baseline: 5.8148x; 1.3492x over previous
#include <cuda_runtime.h>
#include <cuda_fp16.h>
#include <math.h>
#include <stdint.h>

// Problem constants
#define H_HEADS   16
#define KV_HEADS  4
#define DHEAD     128
#define LSEQ      2048
#define BATCH     2
#define HIDDEN    2048
#define QKV_COLS  3072      // 2048 q + 512 k + 512 v
#define WIN       512
#define KDIM      2048

// ---------------------------------------------------------------------------
// Scratch (device globals; no allocation)
// ---------------------------------------------------------------------------
__device__ float  g_qkv[(size_t)BATCH * LSEQ * QKV_COLS];          // fp32 [B*L, 3072]
__device__ __half g_x16 [(size_t)BATCH * LSEQ * HIDDEN];           // x single fp16
__device__ __half g_w16 [(size_t)QKV_COLS * HIDDEN];               // Wq|Wk|Wv single fp16
__device__ __half g_wo16[(size_t)HIDDEN * HIDDEN];                 // Wo single fp16
__device__ __half g_ah16[(size_t)BATCH * LSEQ * HIDDEN];           // attn out single fp16
__device__ __half g_q16h[(size_t)BATCH * H_HEADS  * LSEQ * DHEAD]; // Q hi (pre-scaled)
__device__ __half g_q16l[(size_t)BATCH * H_HEADS  * LSEQ * DHEAD]; // Q lo
__device__ __half g_k16 [(size_t)BATCH * KV_HEADS * LSEQ * DHEAD]; // K single
__device__ __half g_vt16[(size_t)BATCH * KV_HEADS * DHEAD * LSEQ]; // V^T single [d][l]

// ---------------------------------------------------------------------------
// Base-ISA PTX helpers
// ---------------------------------------------------------------------------
__device__ __forceinline__ uint32_t smem_u32(const void* p) {
    uint32_t r;
    asm("{ .reg .u64 t; cvta.to.shared.u64 t, %1; cvt.u32.u64 %0, t; }" : "=r"(r) : "l"(p));
    return r;
}
__device__ __forceinline__ void cpa16(uint32_t s, const void* g) {
    asm volatile("cp.async.cg.shared.global [%0], [%1], 16;" :: "r"(s), "l"(g));
}
#define CPA_COMMIT() asm volatile("cp.async.commit_group;" ::: "memory")
#define CPA_WAIT(n)  asm volatile("cp.async.wait_group %0;" :: "n"(n) : "memory")

__device__ __forceinline__ uint32_t swz(uint32_t o) { return o ^ ((o >> 3) & 0x70); }

__device__ __forceinline__ void ldmx4(uint32_t* r, uint32_t a) {
    asm volatile("ldmatrix.sync.aligned.m8n8.x4.shared.b16 {%0,%1,%2,%3}, [%4];"
        : "=r"(r[0]), "=r"(r[1]), "=r"(r[2]), "=r"(r[3]) : "r"(a));
}
__device__ __forceinline__ void mma_f16(float* c, const uint32_t* a, const uint32_t* b) {
    asm volatile("mma.sync.aligned.m16n8k16.row.col.f32.f16.f16.f32 "
        "{%0,%1,%2,%3}, {%4,%5,%6,%7}, {%8,%9}, {%0,%1,%2,%3};"
        : "+f"(c[0]), "+f"(c[1]), "+f"(c[2]), "+f"(c[3])
        : "r"(a[0]), "r"(a[1]), "r"(a[2]), "r"(a[3]), "r"(b[0]), "r"(b[1]));
}
__device__ __forceinline__ unsigned pk2h(__half a, __half b) {
    __half2 t = __halves2half2(a, b);
    return *reinterpret_cast<unsigned*>(&t);
}

// ---------------------------------------------------------------------------
// Single-fp16 HMMA GEMM, 128x256 tile: D = A*B^T (fp32 accum)
// Used for BOTH the QKV projection and the O projection.
// ---------------------------------------------------------------------------
#define GMT 128
#define GNT 256
#define GNKC (KDIM / 64)
#define S_OFF_A 0
#define S_OFF_B 16384
#define S_STAGE 49152
#define GEMMS_SMEM (2 * S_STAGE)     // 96 KB

__global__ __launch_bounds__(256, 1)
void gemm_f16s(const __half* __restrict__ A, const __half* __restrict__ B,
               float* __restrict__ C, int ldc)
{
    extern __shared__ __align__(128) char dsm[];
    const uint32_t base = smem_u32(dsm);
    const int tid = threadIdx.x, lane = tid & 31, wid = tid >> 5;
    const int wm = wid & 3, wn = wid >> 2;
    const int m0 = blockIdx.x * GMT, n0 = blockIdx.y * GNT;

    const int a_row  = wm * 32 + (lane & 15);
    const int a_k    = (lane >> 4) * 8;
    const int b_rowg = (lane >> 4) * 8 + (lane & 7);
    const int b_k    = ((lane >> 3) & 1) * 8;

    float acc[2][16][4];
#pragma unroll
    for (int i = 0; i < 2; i++)
#pragma unroll
        for (int j = 0; j < 16; j++)
#pragma unroll
            for (int q = 0; q < 4; q++) acc[i][j][q] = 0.0f;

    auto load_stage = [&](int kc, int s) {
        const uint32_t sb = base + (uint32_t)s * S_STAGE;
#pragma unroll
        for (int i = 0; i < 4; i++) {             // A: 128 rows x 8 units
            int u = tid + 256 * i;
            int r = u >> 3, cu = u & 7;
            uint32_t so = swz((uint32_t)(r * 128 + cu * 16));
            cpa16(sb + S_OFF_A + so, A + ((size_t)(m0 + r) << 11) + (kc << 6) + (cu << 3));
        }
#pragma unroll
        for (int i = 0; i < 8; i++) {             // B: 256 rows x 8 units
            int u = tid + 256 * i;
            int r = u >> 3, cu = u & 7;
            uint32_t so = swz((uint32_t)(r * 128 + cu * 16));
            cpa16(sb + S_OFF_B + so, B + ((size_t)(n0 + r) << 11) + (kc << 6) + (cu << 3));
        }
        CPA_COMMIT();
    };

    load_stage(0, 0);

    for (int kc = 0; kc < GNKC; kc++) {
        if (kc + 1 < GNKC) { load_stage(kc + 1, (kc + 1) & 1); CPA_WAIT(1); }
        else               { CPA_WAIT(0); }
        __syncthreads();

        const uint32_t sb  = base + (uint32_t)(kc & 1) * S_STAGE;
        const uint32_t a_b = sb + S_OFF_A, b_b = sb + S_OFF_B;

#pragma unroll
        for (int ks = 0; ks < 4; ks++) {
            uint32_t af[2][4];
#pragma unroll
            for (int i = 0; i < 2; i++) {
                uint32_t off = swz((uint32_t)((a_row + i * 16) * 128 + (a_k + ks * 16) * 2));
                ldmx4(af[i], a_b + off);
            }
#pragma unroll
            for (int jp = 0; jp < 8; jp++) {
                int nrow = wn * 128 + jp * 16 + b_rowg;
                uint32_t off = swz((uint32_t)(nrow * 128 + (b_k + ks * 16) * 2));
                uint32_t bf[4];
                ldmx4(bf, b_b + off);
#pragma unroll
                for (int i = 0; i < 2; i++) {
                    mma_f16(acc[i][2 * jp],     af[i], &bf[0]);
                    mma_f16(acc[i][2 * jp + 1], af[i], &bf[2]);
                }
            }
        }
        __syncthreads();
    }

#pragma unroll
    for (int i = 0; i < 2; i++) {
        int row = m0 + wm * 32 + i * 16 + (lane >> 2);
#pragma unroll
        for (int j = 0; j < 16; j++) {
            int col = n0 + wn * 128 + j * 8 + 2 * (lane & 3);
            *(float2*)&C[(size_t)row * ldc + col]       = make_float2(acc[i][j][0], acc[i][j][1]);
            *(float2*)&C[(size_t)(row + 8) * ldc + col] = make_float2(acc[i][j][2], acc[i][j][3]);
        }
    }
}

// ---------------------------------------------------------------------------
// Conversion: fp32 -> fp16 single
// ---------------------------------------------------------------------------
__global__ __launch_bounds__(256)
void cvt_half(const float4* __restrict__ src, uint2* __restrict__ dst, int n4)
{
    int i = blockIdx.x * 256 + threadIdx.x;
    if (i >= n4) return;
    float4 v = src[i];
    dst[i] = make_uint2(pk2h(__float2half_rn(v.x), __float2half_rn(v.y)),
                        pk2h(__float2half_rn(v.z), __float2half_rn(v.w)));
}

// ---------------------------------------------------------------------------
// RMSNorm + RoPE -> fp16: Q split hi/lo (pre-scaled), K single
// ---------------------------------------------------------------------------
__global__ __launch_bounds__(128)
void normrope_split(const float* __restrict__ cosp, const float* __restrict__ sinp,
                    const float* __restrict__ qw,  const float* __restrict__ kw)
{
    int m = blockIdx.x;
    int e = blockIdx.y;
    int t = threadIdx.x;
    int l = m & (LSEQ - 1);
    int b = m >> 11;

    const float* p;
    const float* w;
    float sc;
    bool isq = (e < H_HEADS);
    size_t o;
    if (isq) {
        p = g_qkv + (size_t)m * QKV_COLS + e * DHEAD; w = qw;
        o = ((size_t)(b * H_HEADS + e) * LSEQ + l) * DHEAD;
        sc = 0.08838834764831845f;
    } else {
        int kvh = e - H_HEADS;
        p = g_qkv + (size_t)m * QKV_COLS + 2048 + kvh * DHEAD; w = kw;
        o = ((size_t)(b * KV_HEADS + kvh) * LSEQ + l) * DHEAD;
        sc = 1.0f;
    }

    float v = p[t];
    float ss = v * v;
#pragma unroll
    for (int off = 16; off; off >>= 1) ss += __shfl_xor_sync(0xffffffffu, ss, off);

    __shared__ float sred[4];
    __shared__ float sval[128];
    if ((t & 31) == 0) sred[t >> 5] = ss;
    __syncthreads();
    ss = sred[0] + sred[1] + sred[2] + sred[3];

    float n = v * rsqrtf(ss * (1.0f / 128.0f) + 1e-6f) * w[t];
    sval[t] = n;
    __syncthreads();
    float rot = (t < 64) ? -sval[t + 64] : sval[t - 64];
    float val = (n * cosp[l * DHEAD + t] + rot * sinp[l * DHEAD + t]) * sc;
    if (isq) {
        __half hh = __float2half_rn(val);
        g_q16h[o + t] = hh;
        g_q16l[o + t] = __float2half_rn(val - __half2float(hh));
    } else {
        g_k16[o + t] = __float2half_rn(val);
    }
}

// ---------------------------------------------------------------------------
// V transpose: g_qkv v cols -> g_vt16 [b][kvh][d][l] (fp16 single)
// ---------------------------------------------------------------------------
__global__ __launch_bounds__(256)
void vtrans()
{
    __shared__ float tile[32][33];
    int tx = threadIdx.x, ty = threadIdx.y;
    int l0 = blockIdx.x * 32, d0 = blockIdx.y * 32, bk = blockIdx.z;
    int b = bk >> 2, kvh = bk & 3;

#pragma unroll
    for (int i = 0; i < 4; i++) {
        int l = l0 + ty + 8 * i;
        tile[ty + 8 * i][tx] =
            g_qkv[((size_t)(b * LSEQ + l)) * QKV_COLS + 2560 + kvh * DHEAD + d0 + tx];
    }
    __syncthreads();
#pragma unroll
    for (int i = 0; i < 4; i++) {
        int d = d0 + ty + 8 * i;
        size_t o = ((size_t)bk * DHEAD + d) * LSEQ + l0 + tx;
        g_vt16[o] = __float2half_rn(tile[tx][ty + 8 * i]);
    }
}

// ---------------------------------------------------------------------------
// fp16 HMMA flash attention (proven): QK = Qh*K + Ql*K; PV = Ph*V + Pl*V
// Epilogue stores single fp16 (O-GEMM A operand).
// ---------------------------------------------------------------------------
#define AQT 128
#define AKC 64
#define A_QH 0
#define A_QL 32768
#define A_STG0 65536
#define A_STG_SZ 32768
#define AS_KH 0
#define AS_VH 16384
#define ATT_SMEM2 131072

__global__ __launch_bounds__(256, 1)
void attn_mma()
{
    extern __shared__ __align__(128) char asmem[];
    const uint32_t base = smem_u32(asmem);
    const int tid = threadIdx.x, lane = tid & 31, w = tid >> 5;
    const int qt = blockIdx.x, h = blockIdx.y, b = blockIdx.z;
    const int kvh = h >> 2;
    const int q0 = qt * AQT;

    {
        const __half* qh = g_q16h + ((size_t)(b * H_HEADS + h) * LSEQ + q0) * DHEAD;
        const __half* ql = g_q16l + ((size_t)(b * H_HEADS + h) * LSEQ + q0) * DHEAD;
#pragma unroll
        for (int i = 0; i < 8; i++) {
            int u = tid + 256 * i;
            int r = u >> 4, cu = u & 15;
            uint32_t so = (uint32_t)(cu >> 3) * 16384 + swz((uint32_t)(r * 128 + (cu & 7) * 16));
            cpa16(base + A_QH + so, qh + (size_t)r * DHEAD + cu * 8);
            cpa16(base + A_QL + so, ql + (size_t)r * DHEAD + cu * 8);
        }
        CPA_COMMIT();
    }

    int kstart = q0 - WIN;       if (kstart < 0)  kstart = 0;
    int kend   = q0 + AQT + WIN; if (kend > LSEQ) kend = LSEQ;
    const int nc = (kend - kstart) / AKC;

    const __half* kh  = g_k16  + (size_t)(b * KV_HEADS + kvh) * LSEQ * DHEAD;
    const __half* vth = g_vt16 + (size_t)(b * KV_HEADS + kvh) * DHEAD * LSEQ;

    auto load_kv = [&](int c, int s) {
        const uint32_t sb = base + A_STG0 + (uint32_t)s * A_STG_SZ;
        const int ks = kstart + c * AKC;
#pragma unroll
        for (int i = 0; i < 4; i++) {
            int u = tid + 256 * i;
            int r = u >> 4, cu = u & 15;
            uint32_t so = (uint32_t)(cu >> 3) * 8192 + swz((uint32_t)(r * 128 + (cu & 7) * 16));
            cpa16(sb + AS_KH + so, kh + (size_t)(ks + r) * DHEAD + cu * 8);
        }
#pragma unroll
        for (int i = 0; i < 4; i++) {
            int u = tid + 256 * i;
            int d = u >> 3, cu = u & 7;
            uint32_t so = swz((uint32_t)(d * 128 + cu * 16));
            cpa16(sb + AS_VH + so, vth + (size_t)d * LSEQ + ks + cu * 8);
        }
        CPA_COMMIT();
    };

    load_kv(0, 0);

    const int a_row  = w * 16 + (lane & 15);
    const int a_k    = (lane >> 4) * 8;
    const int b_rowg = (lane >> 4) * 8 + (lane & 7);
    const int b_k    = ((lane >> 3) & 1) * 8;
    const int r0     = lane >> 2, colb = 2 * (lane & 3);
    const int qrow0  = q0 + w * 16 + r0;
    const int qrow1  = qrow0 + 8;

    float out[16][4];
#pragma unroll
    for (int na = 0; na < 16; na++)
#pragma unroll
        for (int q = 0; q < 4; q++) out[na][q] = 0.0f;
    float m0 = -1e30f, m1 = -1e30f, l0s = 0.0f, l1s = 0.0f;

    for (int c = 0; c < nc; c++) {
        if (c + 1 < nc) { load_kv(c + 1, (c + 1) & 1); CPA_WAIT(1); }
        else            { CPA_WAIT(0); }
        __syncthreads();
        const uint32_t sb = base + A_STG0 + (uint32_t)(c & 1) * A_STG_SZ;

        float sacc[8][4];
#pragma unroll
        for (int j = 0; j < 8; j++)
#pragma unroll
            for (int q = 0; q < 4; q++) sacc[j][q] = 0.0f;

#pragma unroll
        for (int ks = 0; ks < 8; ks++) {
            int pnl = ks >> 2, kk = (ks & 3) * 16;
            uint32_t aoff = (uint32_t)pnl * 16384 + swz((uint32_t)(a_row * 128 + (kk + a_k) * 2));
            uint32_t aqh[4], aql[4];
            ldmx4(aqh, base + A_QH + aoff);
            ldmx4(aql, base + A_QL + aoff);
#pragma unroll
            for (int jp = 0; jp < 4; jp++) {
                uint32_t boff = (uint32_t)pnl * 8192 +
                    swz((uint32_t)((jp * 16 + b_rowg) * 128 + (kk + b_k) * 2));
                uint32_t bkh[4];
                ldmx4(bkh, sb + AS_KH + boff);
                mma_f16(sacc[2 * jp],     aqh, &bkh[0]);
                mma_f16(sacc[2 * jp + 1], aqh, &bkh[2]);
                mma_f16(sacc[2 * jp],     aql, &bkh[0]);
                mma_f16(sacc[2 * jp + 1], aql, &bkh[2]);
            }
        }

        const int ks0 = kstart + c * AKC;
        float mx0 = -1e30f, mx1 = -1e30f;
#pragma unroll
        for (int j = 0; j < 8; j++) {
            int k0 = ks0 + j * 8 + colb, k1 = k0 + 1;
            int d00 = qrow0 - k0; if (d00 < 0) d00 = -d00;
            int d01 = qrow0 - k1; if (d01 < 0) d01 = -d01;
            int d10 = qrow1 - k0; if (d10 < 0) d10 = -d10;
            int d11 = qrow1 - k1; if (d11 < 0) d11 = -d11;
            if (d00 > WIN) sacc[j][0] = -1e30f;
            if (d01 > WIN) sacc[j][1] = -1e30f;
            if (d10 > WIN) sacc[j][2] = -1e30f;
            if (d11 > WIN) sacc[j][3] = -1e30f;
            mx0 = fmaxf(mx0, fmaxf(sacc[j][0], sacc[j][1]));
            mx1 = fmaxf(mx1, fmaxf(sacc[j][2], sacc[j][3]));
        }
        mx0 = fmaxf(mx0, __shfl_xor_sync(0xffffffffu, mx0, 1));
        mx0 = fmaxf(mx0, __shfl_xor_sync(0xffffffffu, mx0, 2));
        mx1 = fmaxf(mx1, __shfl_xor_sync(0xffffffffu, mx1, 1));
        mx1 = fmaxf(mx1, __shfl_xor_sync(0xffffffffu, mx1, 2));

        float mn0 = fmaxf(m0, mx0), mn1 = fmaxf(m1, mx1);
        float c0f = __expf(m0 - mn0), c1f = __expf(m1 - mn1);
        m0 = mn0; m1 = mn1;

        float rs0 = 0.0f, rs1 = 0.0f;
        uint32_t ph[8], ph2[8], pl[8], pl2[8];
#pragma unroll
        for (int j = 0; j < 8; j++) {
            float p0 = (sacc[j][0] > -9e29f) ? __expf(sacc[j][0] - mn0) : 0.0f;
            float p1 = (sacc[j][1] > -9e29f) ? __expf(sacc[j][1] - mn0) : 0.0f;
            float p2 = (sacc[j][2] > -9e29f) ? __expf(sacc[j][2] - mn1) : 0.0f;
            float p3 = (sacc[j][3] > -9e29f) ? __expf(sacc[j][3] - mn1) : 0.0f;
            rs0 += p0 + p1; rs1 += p2 + p3;
            __half h0 = __float2half_rn(p0), h1v = __float2half_rn(p1);
            __half h2 = __float2half_rn(p2), h3v = __float2half_rn(p3);
            ph[j]  = pk2h(h0, h1v);
            ph2[j] = pk2h(h2, h3v);
            pl[j]  = pk2h(__float2half_rn(p0 - __half2float(h0)),
                          __float2half_rn(p1 - __half2float(h1v)));
            pl2[j] = pk2h(__float2half_rn(p2 - __half2float(h2)),
                          __float2half_rn(p3 - __half2float(h3v)));
        }
        rs0 += __shfl_xor_sync(0xffffffffu, rs0, 1);
        rs0 += __shfl_xor_sync(0xffffffffu, rs0, 2);
        rs1 += __shfl_xor_sync(0xffffffffu, rs1, 1);
        rs1 += __shfl_xor_sync(0xffffffffu, rs1, 2);
        l0s = l0s * c0f + rs0;
        l1s = l1s * c1f + rs1;
#pragma unroll
        for (int na = 0; na < 16; na++) {
            out[na][0] *= c0f; out[na][1] *= c0f;
            out[na][2] *= c1f; out[na][3] *= c1f;
        }

#pragma unroll
        for (int ks2 = 0; ks2 < 4; ks2++) {
            uint32_t Ahf[4] = { ph[2 * ks2], ph2[2 * ks2], ph[2 * ks2 + 1], ph2[2 * ks2 + 1] };
            uint32_t Alf[4] = { pl[2 * ks2], pl2[2 * ks2], pl[2 * ks2 + 1], pl2[2 * ks2 + 1] };
#pragma unroll
            for (int jp = 0; jp < 8; jp++) {
                uint32_t voff = swz((uint32_t)((jp * 16 + b_rowg) * 128 + (ks2 * 16 + b_k) * 2));
                uint32_t vh[4];
                ldmx4(vh, sb + AS_VH + voff);
                mma_f16(out[2 * jp],     Ahf, &vh[0]);
                mma_f16(out[2 * jp + 1], Ahf, &vh[2]);
                mma_f16(out[2 * jp],     Alf, &vh[0]);
                mma_f16(out[2 * jp + 1], Alf, &vh[2]);
            }
        }
        __syncthreads();
    }

    // epilogue: normalize, single-fp16 store (O-GEMM A operand)
    float inv0 = 1.0f / l0s, inv1 = 1.0f / l1s;
    size_t rb0 = ((size_t)b * LSEQ + qrow0) * HIDDEN + h * DHEAD;
    size_t rb1 = rb0 + (size_t)8 * HIDDEN;
#pragma unroll
    for (int na = 0; na < 16; na++) {
        int d = na * 8 + colb;
        *(uint32_t*)(g_ah16 + rb0 + d) = pk2h(__float2half_rn(out[na][0] * inv0),
                                              __float2half_rn(out[na][1] * inv0));
        *(uint32_t*)(g_ah16 + rb1 + d) = pk2h(__float2half_rn(out[na][2] * inv1),
                                              __float2half_rn(out[na][3] * inv1));
    }
}

// ---------------------------------------------------------------------------
// Launch. Inputs: x, cos, sin, Wq, Wk, Wv, Wo, q_norm_w, k_norm_w
// ---------------------------------------------------------------------------
extern "C" void kernel_launch(void* const* d_in, const int* in_sizes, int n_in,
                              void* d_out, int out_size)
{
    const float* x    = (const float*)d_in[0];
    const float* cosp = (const float*)d_in[1];
    const float* sinp = (const float*)d_in[2];
    const float* Wq   = (const float*)d_in[3];
    const float* Wk   = (const float*)d_in[4];
    const float* Wv   = (const float*)d_in[5];
    const float* Wo   = (const float*)d_in[6];
    const float* qw   = (const float*)d_in[7];
    const float* kw   = (const float*)d_in[8];
    float* out = (float*)d_out;

    void *p_qkv, *p_x16, *p_w16, *p_wo16, *p_ah;
    cudaGetSymbolAddress(&p_qkv,  g_qkv);
    cudaGetSymbolAddress(&p_x16,  g_x16);
    cudaGetSymbolAddress(&p_w16,  g_w16);
    cudaGetSymbolAddress(&p_wo16, g_wo16);
    cudaGetSymbolAddress(&p_ah,   g_ah16);

    cudaFuncSetAttribute(gemm_f16s, cudaFuncAttributeMaxDynamicSharedMemorySize, GEMMS_SMEM);
    cudaFuncSetAttribute(attn_mma, cudaFuncAttributeMaxDynamicSharedMemorySize, ATT_SMEM2);

    // 1) conversions (uint2 = 4 elements -> element offset / 4)
    {
        int n4 = BATCH * LSEQ * HIDDEN / 4;
        cvt_half<<<(n4 + 255) / 256, 256>>>((const float4*)x, (uint2*)p_x16, n4);
    }
    {
        int n4 = 2048 * HIDDEN / 4;   // Wq rows 0..2047
        cvt_half<<<(n4 + 255) / 256, 256>>>((const float4*)Wq, (uint2*)p_w16, n4);
    }
    {
        int n4 = 512 * HIDDEN / 4;    // Wk rows 2048..2559
        size_t off = (size_t)2048 * HIDDEN / 4;
        cvt_half<<<(n4 + 255) / 256, 256>>>((const float4*)Wk, (uint2*)p_w16 + off, n4);
    }
    {
        int n4 = 512 * HIDDEN / 4;    // Wv rows 2560..3071
        size_t off = (size_t)2560 * HIDDEN / 4;
        cvt_half<<<(n4 + 255) / 256, 256>>>((const float4*)Wv, (uint2*)p_w16 + off, n4);
    }
    {
        int n4 = HIDDEN * HIDDEN / 4; // Wo
        cvt_half<<<(n4 + 255) / 256, 256>>>((const float4*)Wo, (uint2*)p_wo16, n4);
    }

    // 2) QKV projection (single fp16 HMMA) -> g_qkv fp32
    gemm_f16s<<<dim3(BATCH * LSEQ / GMT, QKV_COLS / GNT), 256, GEMMS_SMEM>>>(
        (const __half*)p_x16, (const __half*)p_w16, (float*)p_qkv, QKV_COLS);

    // 3) RMSNorm + RoPE -> fp16 Q split (scaled) / K single
    normrope_split<<<dim3(BATCH * LSEQ, H_HEADS + KV_HEADS), 128>>>(cosp, sinp, qw, kw);

    // 4) V transpose -> fp16 single
    vtrans<<<dim3(LSEQ / 32, DHEAD / 32, BATCH * KV_HEADS), dim3(32, 8)>>>();

    // 5) fp16 HMMA sliding-window flash attention -> g_ah16
    attn_mma<<<dim3(LSEQ / AQT, H_HEADS, BATCH), 256, ATT_SMEM2>>>();

    // 6) Output projection (single fp16 HMMA) -> d_out
    gemm_f16s<<<dim3(BATCH * LSEQ / GMT, HIDDEN / GNT), 256, GEMMS_SMEM>>>(
        (const __half*)p_ah, (const __half*)p_wo16, out, HIDDEN);
}

// round 14
// speedup vs baseline: 6.0851x; 1.0465x over previous
#include <cuda_runtime.h>
#include <cuda_fp16.h>
#include <math.h>
#include <stdint.h>

// Problem constants
#define H_HEADS   16
#define KV_HEADS  4
#define DHEAD     128
#define LSEQ      2048
#define BATCH     2
#define HIDDEN    2048
#define QKV_COLS  3072      // 2048 q + 512 k + 512 v
#define WIN       512
#define KDIM      2048

// ---------------------------------------------------------------------------
// Scratch (device globals; no allocation)
// ---------------------------------------------------------------------------
__device__ float  g_qkv[(size_t)BATCH * LSEQ * QKV_COLS];          // fp32 [B*L, 3072]
__device__ __half g_x16 [(size_t)BATCH * LSEQ * HIDDEN];           // x single fp16
__device__ __half g_w16 [(size_t)QKV_COLS * HIDDEN];               // Wq|Wk|Wv single fp16
__device__ __half g_wo16[(size_t)HIDDEN * HIDDEN];                 // Wo single fp16
__device__ __half g_ah16[(size_t)BATCH * LSEQ * HIDDEN];           // attn out single fp16
__device__ __half g_q16 [(size_t)BATCH * H_HEADS  * LSEQ * DHEAD]; // Q single (pre-scaled)
__device__ __half g_k16 [(size_t)BATCH * KV_HEADS * LSEQ * DHEAD]; // K single
__device__ __half g_vt16[(size_t)BATCH * KV_HEADS * DHEAD * LSEQ]; // V^T single [d][l]

// ---------------------------------------------------------------------------
// Base-ISA PTX helpers
// ---------------------------------------------------------------------------
__device__ __forceinline__ uint32_t smem_u32(const void* p) {
    uint32_t r;
    asm("{ .reg .u64 t; cvta.to.shared.u64 t, %1; cvt.u32.u64 %0, t; }" : "=r"(r) : "l"(p));
    return r;
}
__device__ __forceinline__ void cpa16(uint32_t s, const void* g) {
    asm volatile("cp.async.cg.shared.global [%0], [%1], 16;" :: "r"(s), "l"(g));
}
#define CPA_COMMIT() asm volatile("cp.async.commit_group;" ::: "memory")
#define CPA_WAIT(n)  asm volatile("cp.async.wait_group %0;" :: "n"(n) : "memory")

__device__ __forceinline__ uint32_t swz(uint32_t o) { return o ^ ((o >> 3) & 0x70); }

__device__ __forceinline__ void ldmx4(uint32_t* r, uint32_t a) {
    asm volatile("ldmatrix.sync.aligned.m8n8.x4.shared.b16 {%0,%1,%2,%3}, [%4];"
        : "=r"(r[0]), "=r"(r[1]), "=r"(r[2]), "=r"(r[3]) : "r"(a));
}
__device__ __forceinline__ void mma_f16(float* c, const uint32_t* a, const uint32_t* b) {
    asm volatile("mma.sync.aligned.m16n8k16.row.col.f32.f16.f16.f32 "
        "{%0,%1,%2,%3}, {%4,%5,%6,%7}, {%8,%9}, {%0,%1,%2,%3};"
        : "+f"(c[0]), "+f"(c[1]), "+f"(c[2]), "+f"(c[3])
        : "r"(a[0]), "r"(a[1]), "r"(a[2]), "r"(a[3]), "r"(b[0]), "r"(b[1]));
}
__device__ __forceinline__ unsigned pk2h(__half a, __half b) {
    __half2 t = __halves2half2(a, b);
    return *reinterpret_cast<unsigned*>(&t);
}

// ---------------------------------------------------------------------------
// Single-fp16 HMMA GEMM, 128x256 tile: D = A*B^T (fp32 accum) — QKV and O proj
// ---------------------------------------------------------------------------
#define GMT 128
#define GNT 256
#define GNKC (KDIM / 64)
#define S_OFF_A 0
#define S_OFF_B 16384
#define S_STAGE 49152
#define GEMMS_SMEM (2 * S_STAGE)     // 96 KB

__global__ __launch_bounds__(256, 1)
void gemm_f16s(const __half* __restrict__ A, const __half* __restrict__ B,
               float* __restrict__ C, int ldc)
{
    extern __shared__ __align__(128) char dsm[];
    const uint32_t base = smem_u32(dsm);
    const int tid = threadIdx.x, lane = tid & 31, wid = tid >> 5;
    const int wm = wid & 3, wn = wid >> 2;
    const int m0 = blockIdx.x * GMT, n0 = blockIdx.y * GNT;

    const int a_row  = wm * 32 + (lane & 15);
    const int a_k    = (lane >> 4) * 8;
    const int b_rowg = (lane >> 4) * 8 + (lane & 7);
    const int b_k    = ((lane >> 3) & 1) * 8;

    float acc[2][16][4];
#pragma unroll
    for (int i = 0; i < 2; i++)
#pragma unroll
        for (int j = 0; j < 16; j++)
#pragma unroll
            for (int q = 0; q < 4; q++) acc[i][j][q] = 0.0f;

    auto load_stage = [&](int kc, int s) {
        const uint32_t sb = base + (uint32_t)s * S_STAGE;
#pragma unroll
        for (int i = 0; i < 4; i++) {
            int u = tid + 256 * i;
            int r = u >> 3, cu = u & 7;
            uint32_t so = swz((uint32_t)(r * 128 + cu * 16));
            cpa16(sb + S_OFF_A + so, A + ((size_t)(m0 + r) << 11) + (kc << 6) + (cu << 3));
        }
#pragma unroll
        for (int i = 0; i < 8; i++) {
            int u = tid + 256 * i;
            int r = u >> 3, cu = u & 7;
            uint32_t so = swz((uint32_t)(r * 128 + cu * 16));
            cpa16(sb + S_OFF_B + so, B + ((size_t)(n0 + r) << 11) + (kc << 6) + (cu << 3));
        }
        CPA_COMMIT();
    };

    load_stage(0, 0);

    for (int kc = 0; kc < GNKC; kc++) {
        if (kc + 1 < GNKC) { load_stage(kc + 1, (kc + 1) & 1); CPA_WAIT(1); }
        else               { CPA_WAIT(0); }
        __syncthreads();

        const uint32_t sb  = base + (uint32_t)(kc & 1) * S_STAGE;
        const uint32_t a_b = sb + S_OFF_A, b_b = sb + S_OFF_B;

#pragma unroll
        for (int ks = 0; ks < 4; ks++) {
            uint32_t af[2][4];
#pragma unroll
            for (int i = 0; i < 2; i++) {
                uint32_t off = swz((uint32_t)((a_row + i * 16) * 128 + (a_k + ks * 16) * 2));
                ldmx4(af[i], a_b + off);
            }
#pragma unroll
            for (int jp = 0; jp < 8; jp++) {
                int nrow = wn * 128 + jp * 16 + b_rowg;
                uint32_t off = swz((uint32_t)(nrow * 128 + (b_k + ks * 16) * 2));
                uint32_t bf[4];
                ldmx4(bf, b_b + off);
#pragma unroll
                for (int i = 0; i < 2; i++) {
                    mma_f16(acc[i][2 * jp],     af[i], &bf[0]);
                    mma_f16(acc[i][2 * jp + 1], af[i], &bf[2]);
                }
            }
        }
        __syncthreads();
    }

#pragma unroll
    for (int i = 0; i < 2; i++) {
        int row = m0 + wm * 32 + i * 16 + (lane >> 2);
#pragma unroll
        for (int j = 0; j < 16; j++) {
            int col = n0 + wn * 128 + j * 8 + 2 * (lane & 3);
            *(float2*)&C[(size_t)row * ldc + col]       = make_float2(acc[i][j][0], acc[i][j][1]);
            *(float2*)&C[(size_t)(row + 8) * ldc + col] = make_float2(acc[i][j][2], acc[i][j][3]);
        }
    }
}

// ---------------------------------------------------------------------------
// Conversion: fp32 -> fp16 single
// ---------------------------------------------------------------------------
__global__ __launch_bounds__(256)
void cvt_half(const float4* __restrict__ src, uint2* __restrict__ dst, int n4)
{
    int i = blockIdx.x * 256 + threadIdx.x;
    if (i >= n4) return;
    float4 v = src[i];
    dst[i] = make_uint2(pk2h(__float2half_rn(v.x), __float2half_rn(v.y)),
                        pk2h(__float2half_rn(v.z), __float2half_rn(v.w)));
}

// ---------------------------------------------------------------------------
// RMSNorm + RoPE -> fp16 single: Q (pre-scaled) and K
// ---------------------------------------------------------------------------
__global__ __launch_bounds__(128)
void normrope_single(const float* __restrict__ cosp, const float* __restrict__ sinp,
                     const float* __restrict__ qw,  const float* __restrict__ kw)
{
    int m = blockIdx.x;
    int e = blockIdx.y;
    int t = threadIdx.x;
    int l = m & (LSEQ - 1);
    int b = m >> 11;

    const float* p;
    const float* w;
    float sc;
    __half* dst;
    if (e < H_HEADS) {
        p = g_qkv + (size_t)m * QKV_COLS + e * DHEAD; w = qw;
        dst = g_q16 + ((size_t)(b * H_HEADS + e) * LSEQ + l) * DHEAD;
        sc = 0.08838834764831845f;
    } else {
        int kvh = e - H_HEADS;
        p = g_qkv + (size_t)m * QKV_COLS + 2048 + kvh * DHEAD; w = kw;
        dst = g_k16 + ((size_t)(b * KV_HEADS + kvh) * LSEQ + l) * DHEAD;
        sc = 1.0f;
    }

    float v = p[t];
    float ss = v * v;
#pragma unroll
    for (int off = 16; off; off >>= 1) ss += __shfl_xor_sync(0xffffffffu, ss, off);

    __shared__ float sred[4];
    __shared__ float sval[128];
    if ((t & 31) == 0) sred[t >> 5] = ss;
    __syncthreads();
    ss = sred[0] + sred[1] + sred[2] + sred[3];

    float n = v * rsqrtf(ss * (1.0f / 128.0f) + 1e-6f) * w[t];
    sval[t] = n;
    __syncthreads();
    float rot = (t < 64) ? -sval[t + 64] : sval[t - 64];
    dst[t] = __float2half_rn((n * cosp[l * DHEAD + t] + rot * sinp[l * DHEAD + t]) * sc);
}

// ---------------------------------------------------------------------------
// V transpose: g_qkv v cols -> g_vt16 [b][kvh][d][l] (fp16 single)
// ---------------------------------------------------------------------------
__global__ __launch_bounds__(256)
void vtrans()
{
    __shared__ float tile[32][33];
    int tx = threadIdx.x, ty = threadIdx.y;
    int l0 = blockIdx.x * 32, d0 = blockIdx.y * 32, bk = blockIdx.z;
    int b = bk >> 2, kvh = bk & 3;

#pragma unroll
    for (int i = 0; i < 4; i++) {
        int l = l0 + ty + 8 * i;
        tile[ty + 8 * i][tx] =
            g_qkv[((size_t)(b * LSEQ + l)) * QKV_COLS + 2560 + kvh * DHEAD + d0 + tx];
    }
    __syncthreads();
#pragma unroll
    for (int i = 0; i < 4; i++) {
        int d = d0 + ty + 8 * i;
        size_t o = ((size_t)bk * DHEAD + d) * LSEQ + l0 + tx;
        g_vt16[o] = __float2half_rn(tile[tx][ty + 8 * i]);
    }
}

// ---------------------------------------------------------------------------
// fp16 HMMA flash attention: QK = Q*K (single); PV = Ph*V + Pl*V
// CTA: 128 q rows x head x batch, 8 warps. KCH=64 keys/chunk, double-buffered.
// ---------------------------------------------------------------------------
#define AQT 128
#define AKC 64
#define A_Q 0
#define A_STG0 32768
#define A_STG_SZ 32768
#define AS_KH 0
#define AS_VH 16384
#define ATT_SMEM2 98304

__global__ __launch_bounds__(256, 1)
void attn_mma()
{
    extern __shared__ __align__(128) char asmem[];
    const uint32_t base = smem_u32(asmem);
    const int tid = threadIdx.x, lane = tid & 31, w = tid >> 5;
    const int qt = blockIdx.x, h = blockIdx.y, b = blockIdx.z;
    const int kvh = h >> 2;
    const int q0 = qt * AQT;

    {
        const __half* qp = g_q16 + ((size_t)(b * H_HEADS + h) * LSEQ + q0) * DHEAD;
#pragma unroll
        for (int i = 0; i < 8; i++) {
            int u = tid + 256 * i;
            int r = u >> 4, cu = u & 15;
            uint32_t so = (uint32_t)(cu >> 3) * 16384 + swz((uint32_t)(r * 128 + (cu & 7) * 16));
            cpa16(base + A_Q + so, qp + (size_t)r * DHEAD + cu * 8);
        }
        CPA_COMMIT();
    }

    int kstart = q0 - WIN;       if (kstart < 0)  kstart = 0;
    int kend   = q0 + AQT + WIN; if (kend > LSEQ) kend = LSEQ;
    const int nc = (kend - kstart) / AKC;

    const __half* kh  = g_k16  + (size_t)(b * KV_HEADS + kvh) * LSEQ * DHEAD;
    const __half* vth = g_vt16 + (size_t)(b * KV_HEADS + kvh) * DHEAD * LSEQ;

    auto load_kv = [&](int c, int s) {
        const uint32_t sb = base + A_STG0 + (uint32_t)s * A_STG_SZ;
        const int ks = kstart + c * AKC;
#pragma unroll
        for (int i = 0; i < 4; i++) {
            int u = tid + 256 * i;
            int r = u >> 4, cu = u & 15;
            uint32_t so = (uint32_t)(cu >> 3) * 8192 + swz((uint32_t)(r * 128 + (cu & 7) * 16));
            cpa16(sb + AS_KH + so, kh + (size_t)(ks + r) * DHEAD + cu * 8);
        }
#pragma unroll
        for (int i = 0; i < 4; i++) {
            int u = tid + 256 * i;
            int d = u >> 3, cu = u & 7;
            uint32_t so = swz((uint32_t)(d * 128 + cu * 16));
            cpa16(sb + AS_VH + so, vth + (size_t)d * LSEQ + ks + cu * 8);
        }
        CPA_COMMIT();
    };

    load_kv(0, 0);

    const int a_row  = w * 16 + (lane & 15);
    const int a_k    = (lane >> 4) * 8;
    const int b_rowg = (lane >> 4) * 8 + (lane & 7);
    const int b_k    = ((lane >> 3) & 1) * 8;
    const int r0     = lane >> 2, colb = 2 * (lane & 3);
    const int qrow0  = q0 + w * 16 + r0;
    const int qrow1  = qrow0 + 8;

    float out[16][4];
#pragma unroll
    for (int na = 0; na < 16; na++)
#pragma unroll
        for (int q = 0; q < 4; q++) out[na][q] = 0.0f;
    float m0 = -1e30f, m1 = -1e30f, l0s = 0.0f, l1s = 0.0f;

    for (int c = 0; c < nc; c++) {
        if (c + 1 < nc) { load_kv(c + 1, (c + 1) & 1); CPA_WAIT(1); }
        else            { CPA_WAIT(0); }
        __syncthreads();
        const uint32_t sb = base + A_STG0 + (uint32_t)(c & 1) * A_STG_SZ;

        float sacc[8][4];
#pragma unroll
        for (int j = 0; j < 8; j++)
#pragma unroll
            for (int q = 0; q < 4; q++) sacc[j][q] = 0.0f;

#pragma unroll
        for (int ks = 0; ks < 8; ks++) {
            int pnl = ks >> 2, kk = (ks & 3) * 16;
            uint32_t aoff = (uint32_t)pnl * 16384 + swz((uint32_t)(a_row * 128 + (kk + a_k) * 2));
            uint32_t aq[4];
            ldmx4(aq, base + A_Q + aoff);
#pragma unroll
            for (int jp = 0; jp < 4; jp++) {
                uint32_t boff = (uint32_t)pnl * 8192 +
                    swz((uint32_t)((jp * 16 + b_rowg) * 128 + (kk + b_k) * 2));
                uint32_t bkh[4];
                ldmx4(bkh, sb + AS_KH + boff);
                mma_f16(sacc[2 * jp],     aq, &bkh[0]);
                mma_f16(sacc[2 * jp + 1], aq, &bkh[2]);
            }
        }

        const int ks0 = kstart + c * AKC;
        float mx0 = -1e30f, mx1 = -1e30f;
#pragma unroll
        for (int j = 0; j < 8; j++) {
            int k0 = ks0 + j * 8 + colb, k1 = k0 + 1;
            int d00 = qrow0 - k0; if (d00 < 0) d00 = -d00;
            int d01 = qrow0 - k1; if (d01 < 0) d01 = -d01;
            int d10 = qrow1 - k0; if (d10 < 0) d10 = -d10;
            int d11 = qrow1 - k1; if (d11 < 0) d11 = -d11;
            if (d00 > WIN) sacc[j][0] = -1e30f;
            if (d01 > WIN) sacc[j][1] = -1e30f;
            if (d10 > WIN) sacc[j][2] = -1e30f;
            if (d11 > WIN) sacc[j][3] = -1e30f;
            mx0 = fmaxf(mx0, fmaxf(sacc[j][0], sacc[j][1]));
            mx1 = fmaxf(mx1, fmaxf(sacc[j][2], sacc[j][3]));
        }
        mx0 = fmaxf(mx0, __shfl_xor_sync(0xffffffffu, mx0, 1));
        mx0 = fmaxf(mx0, __shfl_xor_sync(0xffffffffu, mx0, 2));
        mx1 = fmaxf(mx1, __shfl_xor_sync(0xffffffffu, mx1, 1));
        mx1 = fmaxf(mx1, __shfl_xor_sync(0xffffffffu, mx1, 2));

        float mn0 = fmaxf(m0, mx0), mn1 = fmaxf(m1, mx1);
        float c0f = __expf(m0 - mn0), c1f = __expf(m1 - mn1);
        m0 = mn0; m1 = mn1;

        float rs0 = 0.0f, rs1 = 0.0f;
        uint32_t ph[8], ph2[8], pl[8], pl2[8];
#pragma unroll
        for (int j = 0; j < 8; j++) {
            float p0 = (sacc[j][0] > -9e29f) ? __expf(sacc[j][0] - mn0) : 0.0f;
            float p1 = (sacc[j][1] > -9e29f) ? __expf(sacc[j][1] - mn0) : 0.0f;
            float p2 = (sacc[j][2] > -9e29f) ? __expf(sacc[j][2] - mn1) : 0.0f;
            float p3 = (sacc[j][3] > -9e29f) ? __expf(sacc[j][3] - mn1) : 0.0f;
            rs0 += p0 + p1; rs1 += p2 + p3;
            __half h0 = __float2half_rn(p0), h1v = __float2half_rn(p1);
            __half h2 = __float2half_rn(p2), h3v = __float2half_rn(p3);
            ph[j]  = pk2h(h0, h1v);
            ph2[j] = pk2h(h2, h3v);
            pl[j]  = pk2h(__float2half_rn(p0 - __half2float(h0)),
                          __float2half_rn(p1 - __half2float(h1v)));
            pl2[j] = pk2h(__float2half_rn(p2 - __half2float(h2)),
                          __float2half_rn(p3 - __half2float(h3v)));
        }
        rs0 += __shfl_xor_sync(0xffffffffu, rs0, 1);
        rs0 += __shfl_xor_sync(0xffffffffu, rs0, 2);
        rs1 += __shfl_xor_sync(0xffffffffu, rs1, 1);
        rs1 += __shfl_xor_sync(0xffffffffu, rs1, 2);
        l0s = l0s * c0f + rs0;
        l1s = l1s * c1f + rs1;
#pragma unroll
        for (int na = 0; na < 16; na++) {
            out[na][0] *= c0f; out[na][1] *= c0f;
            out[na][2] *= c1f; out[na][3] *= c1f;
        }

#pragma unroll
        for (int ks2 = 0; ks2 < 4; ks2++) {
            uint32_t Ahf[4] = { ph[2 * ks2], ph2[2 * ks2], ph[2 * ks2 + 1], ph2[2 * ks2 + 1] };
            uint32_t Alf[4] = { pl[2 * ks2], pl2[2 * ks2], pl[2 * ks2 + 1], pl2[2 * ks2 + 1] };
#pragma unroll
            for (int jp = 0; jp < 8; jp++) {
                uint32_t voff = swz((uint32_t)((jp * 16 + b_rowg) * 128 + (ks2 * 16 + b_k) * 2));
                uint32_t vh[4];
                ldmx4(vh, sb + AS_VH + voff);
                mma_f16(out[2 * jp],     Ahf, &vh[0]);
                mma_f16(out[2 * jp + 1], Ahf, &vh[2]);
                mma_f16(out[2 * jp],     Alf, &vh[0]);
                mma_f16(out[2 * jp + 1], Alf, &vh[2]);
            }
        }
        __syncthreads();
    }

    // epilogue: normalize, single-fp16 store (O-GEMM A operand)
    float inv0 = 1.0f / l0s, inv1 = 1.0f / l1s;
    size_t rb0 = ((size_t)b * LSEQ + qrow0) * HIDDEN + h * DHEAD;
    size_t rb1 = rb0 + (size_t)8 * HIDDEN;
#pragma unroll
    for (int na = 0; na < 16; na++) {
        int d = na * 8 + colb;
        *(uint32_t*)(g_ah16 + rb0 + d) = pk2h(__float2half_rn(out[na][0] * inv0),
                                              __float2half_rn(out[na][1] * inv0));
        *(uint32_t*)(g_ah16 + rb1 + d) = pk2h(__float2half_rn(out[na][2] * inv1),
                                              __float2half_rn(out[na][3] * inv1));
    }
}

// ---------------------------------------------------------------------------
// Launch. Inputs: x, cos, sin, Wq, Wk, Wv, Wo, q_norm_w, k_norm_w
// ---------------------------------------------------------------------------
extern "C" void kernel_launch(void* const* d_in, const int* in_sizes, int n_in,
                              void* d_out, int out_size)
{
    const float* x    = (const float*)d_in[0];
    const float* cosp = (const float*)d_in[1];
    const float* sinp = (const float*)d_in[2];
    const float* Wq   = (const float*)d_in[3];
    const float* Wk   = (const float*)d_in[4];
    const float* Wv   = (const float*)d_in[5];
    const float* Wo   = (const float*)d_in[6];
    const float* qw   = (const float*)d_in[7];
    const float* kw   = (const float*)d_in[8];
    float* out = (float*)d_out;

    void *p_qkv, *p_x16, *p_w16, *p_wo16, *p_ah;
    cudaGetSymbolAddress(&p_qkv,  g_qkv);
    cudaGetSymbolAddress(&p_x16,  g_x16);
    cudaGetSymbolAddress(&p_w16,  g_w16);
    cudaGetSymbolAddress(&p_wo16, g_wo16);
    cudaGetSymbolAddress(&p_ah,   g_ah16);

    cudaFuncSetAttribute(gemm_f16s, cudaFuncAttributeMaxDynamicSharedMemorySize, GEMMS_SMEM);
    cudaFuncSetAttribute(attn_mma, cudaFuncAttributeMaxDynamicSharedMemorySize, ATT_SMEM2);

    // 1) conversions (uint2 = 4 elements -> element offset / 4)
    {
        int n4 = BATCH * LSEQ * HIDDEN / 4;
        cvt_half<<<(n4 + 255) / 256, 256>>>((const float4*)x, (uint2*)p_x16, n4);
    }
    {
        int n4 = 2048 * HIDDEN / 4;   // Wq rows 0..2047
        cvt_half<<<(n4 + 255) / 256, 256>>>((const float4*)Wq, (uint2*)p_w16, n4);
    }
    {
        int n4 = 512 * HIDDEN / 4;    // Wk rows 2048..2559
        size_t off = (size_t)2048 * HIDDEN / 4;
        cvt_half<<<(n4 + 255) / 256, 256>>>((const float4*)Wk, (uint2*)p_w16 + off, n4);
    }
    {
        int n4 = 512 * HIDDEN / 4;    // Wv rows 2560..3071
        size_t off = (size_t)2560 * HIDDEN / 4;
        cvt_half<<<(n4 + 255) / 256, 256>>>((const float4*)Wv, (uint2*)p_w16 + off, n4);
    }
    {
        int n4 = HIDDEN * HIDDEN / 4; // Wo
        cvt_half<<<(n4 + 255) / 256, 256>>>((const float4*)Wo, (uint2*)p_wo16, n4);
    }

    // 2) QKV projection (single fp16 HMMA) -> g_qkv fp32
    gemm_f16s<<<dim3(BATCH * LSEQ / GMT, QKV_COLS / GNT), 256, GEMMS_SMEM>>>(
        (const __half*)p_x16, (const __half*)p_w16, (float*)p_qkv, QKV_COLS);

    // 3) RMSNorm + RoPE -> fp16 single Q (scaled) / K
    normrope_single<<<dim3(BATCH * LSEQ, H_HEADS + KV_HEADS), 128>>>(cosp, sinp, qw, kw);

    // 4) V transpose -> fp16 single
    vtrans<<<dim3(LSEQ / 32, DHEAD / 32, BATCH * KV_HEADS), dim3(32, 8)>>>();

    // 5) fp16 HMMA sliding-window flash attention -> g_ah16
    attn_mma<<<dim3(LSEQ / AQT, H_HEADS, BATCH), 256, ATT_SMEM2>>>();

    // 6) Output projection (single fp16 HMMA) -> d_out
    gemm_f16s<<<dim3(BATCH * LSEQ / GMT, HIDDEN / GNT), 256, GEMMS_SMEM>>>(
        (const __half*)p_ah, (const __half*)p_wo16, out, HIDDEN);
}

// round 15
// speedup vs baseline: 6.5641x; 1.0787x over previous
#include <cuda_runtime.h>
#include <cuda_fp16.h>
#include <math.h>
#include <stdint.h>

// Problem constants
#define H_HEADS   16
#define KV_HEADS  4
#define DHEAD     128
#define LSEQ      2048
#define BATCH     2
#define HIDDEN    2048
#define QKV_COLS  3072      // 2048 q + 512 k + 512 v
#define WIN       512
#define KDIM      2048

// ---------------------------------------------------------------------------
// Scratch (device globals; no allocation)
// ---------------------------------------------------------------------------
__device__ float  g_qkv[(size_t)BATCH * LSEQ * QKV_COLS];          // fp32 [B*L, 3072]
__device__ __half g_x16 [(size_t)BATCH * LSEQ * HIDDEN];           // x single fp16
__device__ __half g_w16 [(size_t)QKV_COLS * HIDDEN];               // Wq|Wk|Wv single fp16
__device__ __half g_wo16[(size_t)HIDDEN * HIDDEN];                 // Wo single fp16
__device__ __half g_ah16[(size_t)BATCH * LSEQ * HIDDEN];           // attn out single fp16
__device__ __half g_q16 [(size_t)BATCH * H_HEADS  * LSEQ * DHEAD]; // Q single (pre-scaled)
__device__ __half g_k16 [(size_t)BATCH * KV_HEADS * LSEQ * DHEAD]; // K single
__device__ __half g_vt16[(size_t)BATCH * KV_HEADS * DHEAD * LSEQ]; // V^T single [d][l]

// ---------------------------------------------------------------------------
// Base-ISA PTX helpers
// ---------------------------------------------------------------------------
__device__ __forceinline__ uint32_t smem_u32(const void* p) {
    uint32_t r;
    asm("{ .reg .u64 t; cvta.to.shared.u64 t, %1; cvt.u32.u64 %0, t; }" : "=r"(r) : "l"(p));
    return r;
}
__device__ __forceinline__ void cpa16(uint32_t s, const void* g) {
    asm volatile("cp.async.cg.shared.global [%0], [%1], 16;" :: "r"(s), "l"(g));
}
#define CPA_COMMIT() asm volatile("cp.async.commit_group;" ::: "memory")
#define CPA_WAIT(n)  asm volatile("cp.async.wait_group %0;" :: "n"(n) : "memory")

__device__ __forceinline__ uint32_t swz(uint32_t o) { return o ^ ((o >> 3) & 0x70); }

__device__ __forceinline__ void ldmx4(uint32_t* r, uint32_t a) {
    asm volatile("ldmatrix.sync.aligned.m8n8.x4.shared.b16 {%0,%1,%2,%3}, [%4];"
        : "=r"(r[0]), "=r"(r[1]), "=r"(r[2]), "=r"(r[3]) : "r"(a));
}
__device__ __forceinline__ void mma_f16(float* c, const uint32_t* a, const uint32_t* b) {
    asm volatile("mma.sync.aligned.m16n8k16.row.col.f32.f16.f16.f32 "
        "{%0,%1,%2,%3}, {%4,%5,%6,%7}, {%8,%9}, {%0,%1,%2,%3};"
        : "+f"(c[0]), "+f"(c[1]), "+f"(c[2]), "+f"(c[3])
        : "r"(a[0]), "r"(a[1]), "r"(a[2]), "r"(a[3]), "r"(b[0]), "r"(b[1]));
}
__device__ __forceinline__ unsigned pk2h(__half a, __half b) {
    __half2 t = __halves2half2(a, b);
    return *reinterpret_cast<unsigned*>(&t);
}

// ---------------------------------------------------------------------------
// Single-fp16 HMMA GEMM, 128x256 tile: D = A*B^T (fp32 accum) — QKV and O proj
// ---------------------------------------------------------------------------
#define GMT 128
#define GNT 256
#define GNKC (KDIM / 64)
#define S_OFF_A 0
#define S_OFF_B 16384
#define S_STAGE 49152
#define GEMMS_SMEM (2 * S_STAGE)     // 96 KB

__global__ __launch_bounds__(256, 1)
void gemm_f16s(const __half* __restrict__ A, const __half* __restrict__ B,
               float* __restrict__ C, int ldc)
{
    extern __shared__ __align__(128) char dsm[];
    const uint32_t base = smem_u32(dsm);
    const int tid = threadIdx.x, lane = tid & 31, wid = tid >> 5;
    const int wm = wid & 3, wn = wid >> 2;
    const int m0 = blockIdx.x * GMT, n0 = blockIdx.y * GNT;

    const int a_row  = wm * 32 + (lane & 15);
    const int a_k    = (lane >> 4) * 8;
    const int b_rowg = (lane >> 4) * 8 + (lane & 7);
    const int b_k    = ((lane >> 3) & 1) * 8;

    float acc[2][16][4];
#pragma unroll
    for (int i = 0; i < 2; i++)
#pragma unroll
        for (int j = 0; j < 16; j++)
#pragma unroll
            for (int q = 0; q < 4; q++) acc[i][j][q] = 0.0f;

    auto load_stage = [&](int kc, int s) {
        const uint32_t sb = base + (uint32_t)s * S_STAGE;
#pragma unroll
        for (int i = 0; i < 4; i++) {
            int u = tid + 256 * i;
            int r = u >> 3, cu = u & 7;
            uint32_t so = swz((uint32_t)(r * 128 + cu * 16));
            cpa16(sb + S_OFF_A + so, A + ((size_t)(m0 + r) << 11) + (kc << 6) + (cu << 3));
        }
#pragma unroll
        for (int i = 0; i < 8; i++) {
            int u = tid + 256 * i;
            int r = u >> 3, cu = u & 7;
            uint32_t so = swz((uint32_t)(r * 128 + cu * 16));
            cpa16(sb + S_OFF_B + so, B + ((size_t)(n0 + r) << 11) + (kc << 6) + (cu << 3));
        }
        CPA_COMMIT();
    };

    load_stage(0, 0);

    for (int kc = 0; kc < GNKC; kc++) {
        if (kc + 1 < GNKC) { load_stage(kc + 1, (kc + 1) & 1); CPA_WAIT(1); }
        else               { CPA_WAIT(0); }
        __syncthreads();

        const uint32_t sb  = base + (uint32_t)(kc & 1) * S_STAGE;
        const uint32_t a_b = sb + S_OFF_A, b_b = sb + S_OFF_B;

#pragma unroll
        for (int ks = 0; ks < 4; ks++) {
            uint32_t af[2][4];
#pragma unroll
            for (int i = 0; i < 2; i++) {
                uint32_t off = swz((uint32_t)((a_row + i * 16) * 128 + (a_k + ks * 16) * 2));
                ldmx4(af[i], a_b + off);
            }
#pragma unroll
            for (int jp = 0; jp < 8; jp++) {
                int nrow = wn * 128 + jp * 16 + b_rowg;
                uint32_t off = swz((uint32_t)(nrow * 128 + (b_k + ks * 16) * 2));
                uint32_t bf[4];
                ldmx4(bf, b_b + off);
#pragma unroll
                for (int i = 0; i < 2; i++) {
                    mma_f16(acc[i][2 * jp],     af[i], &bf[0]);
                    mma_f16(acc[i][2 * jp + 1], af[i], &bf[2]);
                }
            }
        }
        __syncthreads();
    }

#pragma unroll
    for (int i = 0; i < 2; i++) {
        int row = m0 + wm * 32 + i * 16 + (lane >> 2);
#pragma unroll
        for (int j = 0; j < 16; j++) {
            int col = n0 + wn * 128 + j * 8 + 2 * (lane & 3);
            *(float2*)&C[(size_t)row * ldc + col]       = make_float2(acc[i][j][0], acc[i][j][1]);
            *(float2*)&C[(size_t)(row + 8) * ldc + col] = make_float2(acc[i][j][2], acc[i][j][3]);
        }
    }
}

// ---------------------------------------------------------------------------
// Conversion: fp32 -> fp16 single
// ---------------------------------------------------------------------------
__global__ __launch_bounds__(256)
void cvt_half(const float4* __restrict__ src, uint2* __restrict__ dst, int n4)
{
    int i = blockIdx.x * 256 + threadIdx.x;
    if (i >= n4) return;
    float4 v = src[i];
    dst[i] = make_uint2(pk2h(__float2half_rn(v.x), __float2half_rn(v.y)),
                        pk2h(__float2half_rn(v.z), __float2half_rn(v.w)));
}

// ---------------------------------------------------------------------------
// RMSNorm + RoPE -> fp16 single: Q (pre-scaled) and K
// ---------------------------------------------------------------------------
__global__ __launch_bounds__(128)
void normrope_single(const float* __restrict__ cosp, const float* __restrict__ sinp,
                     const float* __restrict__ qw,  const float* __restrict__ kw)
{
    int m = blockIdx.x;
    int e = blockIdx.y;
    int t = threadIdx.x;
    int l = m & (LSEQ - 1);
    int b = m >> 11;

    const float* p;
    const float* w;
    float sc;
    __half* dst;
    if (e < H_HEADS) {
        p = g_qkv + (size_t)m * QKV_COLS + e * DHEAD; w = qw;
        dst = g_q16 + ((size_t)(b * H_HEADS + e) * LSEQ + l) * DHEAD;
        sc = 0.08838834764831845f;
    } else {
        int kvh = e - H_HEADS;
        p = g_qkv + (size_t)m * QKV_COLS + 2048 + kvh * DHEAD; w = kw;
        dst = g_k16 + ((size_t)(b * KV_HEADS + kvh) * LSEQ + l) * DHEAD;
        sc = 1.0f;
    }

    float v = p[t];
    float ss = v * v;
#pragma unroll
    for (int off = 16; off; off >>= 1) ss += __shfl_xor_sync(0xffffffffu, ss, off);

    __shared__ float sred[4];
    __shared__ float sval[128];
    if ((t & 31) == 0) sred[t >> 5] = ss;
    __syncthreads();
    ss = sred[0] + sred[1] + sred[2] + sred[3];

    float n = v * rsqrtf(ss * (1.0f / 128.0f) + 1e-6f) * w[t];
    sval[t] = n;
    __syncthreads();
    float rot = (t < 64) ? -sval[t + 64] : sval[t - 64];
    dst[t] = __float2half_rn((n * cosp[l * DHEAD + t] + rot * sinp[l * DHEAD + t]) * sc);
}

// ---------------------------------------------------------------------------
// V transpose: g_qkv v cols -> g_vt16 [b][kvh][d][l] (fp16 single)
// ---------------------------------------------------------------------------
__global__ __launch_bounds__(256)
void vtrans()
{
    __shared__ float tile[32][33];
    int tx = threadIdx.x, ty = threadIdx.y;
    int l0 = blockIdx.x * 32, d0 = blockIdx.y * 32, bk = blockIdx.z;
    int b = bk >> 2, kvh = bk & 3;

#pragma unroll
    for (int i = 0; i < 4; i++) {
        int l = l0 + ty + 8 * i;
        tile[ty + 8 * i][tx] =
            g_qkv[((size_t)(b * LSEQ + l)) * QKV_COLS + 2560 + kvh * DHEAD + d0 + tx];
    }
    __syncthreads();
#pragma unroll
    for (int i = 0; i < 4; i++) {
        int d = d0 + ty + 8 * i;
        size_t o = ((size_t)bk * DHEAD + d) * LSEQ + l0 + tx;
        g_vt16[o] = __float2half_rn(tile[tx][ty + 8 * i]);
    }
}

// ---------------------------------------------------------------------------
// fp16 HMMA flash attention: QK = Q*K (single); PV = P*V (single)
// CTA: 128 q rows x head x batch, 8 warps. KCH=64 keys/chunk, double-buffered.
// ---------------------------------------------------------------------------
#define AQT 128
#define AKC 64
#define A_Q 0
#define A_STG0 32768
#define A_STG_SZ 32768
#define AS_KH 0
#define AS_VH 16384
#define ATT_SMEM2 98304

__global__ __launch_bounds__(256, 1)
void attn_mma()
{
    extern __shared__ __align__(128) char asmem[];
    const uint32_t base = smem_u32(asmem);
    const int tid = threadIdx.x, lane = tid & 31, w = tid >> 5;
    const int qt = blockIdx.x, h = blockIdx.y, b = blockIdx.z;
    const int kvh = h >> 2;
    const int q0 = qt * AQT;

    {
        const __half* qp = g_q16 + ((size_t)(b * H_HEADS + h) * LSEQ + q0) * DHEAD;
#pragma unroll
        for (int i = 0; i < 8; i++) {
            int u = tid + 256 * i;
            int r = u >> 4, cu = u & 15;
            uint32_t so = (uint32_t)(cu >> 3) * 16384 + swz((uint32_t)(r * 128 + (cu & 7) * 16));
            cpa16(base + A_Q + so, qp + (size_t)r * DHEAD + cu * 8);
        }
        CPA_COMMIT();
    }

    int kstart = q0 - WIN;       if (kstart < 0)  kstart = 0;
    int kend   = q0 + AQT + WIN; if (kend > LSEQ) kend = LSEQ;
    const int nc = (kend - kstart) / AKC;

    const __half* kh  = g_k16  + (size_t)(b * KV_HEADS + kvh) * LSEQ * DHEAD;
    const __half* vth = g_vt16 + (size_t)(b * KV_HEADS + kvh) * DHEAD * LSEQ;

    auto load_kv = [&](int c, int s) {
        const uint32_t sb = base + A_STG0 + (uint32_t)s * A_STG_SZ;
        const int ks = kstart + c * AKC;
#pragma unroll
        for (int i = 0; i < 4; i++) {
            int u = tid + 256 * i;
            int r = u >> 4, cu = u & 15;
            uint32_t so = (uint32_t)(cu >> 3) * 8192 + swz((uint32_t)(r * 128 + (cu & 7) * 16));
            cpa16(sb + AS_KH + so, kh + (size_t)(ks + r) * DHEAD + cu * 8);
        }
#pragma unroll
        for (int i = 0; i < 4; i++) {
            int u = tid + 256 * i;
            int d = u >> 3, cu = u & 7;
            uint32_t so = swz((uint32_t)(d * 128 + cu * 16));
            cpa16(sb + AS_VH + so, vth + (size_t)d * LSEQ + ks + cu * 8);
        }
        CPA_COMMIT();
    };

    load_kv(0, 0);

    const int a_row  = w * 16 + (lane & 15);
    const int a_k    = (lane >> 4) * 8;
    const int b_rowg = (lane >> 4) * 8 + (lane & 7);
    const int b_k    = ((lane >> 3) & 1) * 8;
    const int r0     = lane >> 2, colb = 2 * (lane & 3);
    const int qrow0  = q0 + w * 16 + r0;
    const int qrow1  = qrow0 + 8;

    float out[16][4];
#pragma unroll
    for (int na = 0; na < 16; na++)
#pragma unroll
        for (int q = 0; q < 4; q++) out[na][q] = 0.0f;
    float m0 = -1e30f, m1 = -1e30f, l0s = 0.0f, l1s = 0.0f;

    for (int c = 0; c < nc; c++) {
        if (c + 1 < nc) { load_kv(c + 1, (c + 1) & 1); CPA_WAIT(1); }
        else            { CPA_WAIT(0); }
        __syncthreads();
        const uint32_t sb = base + A_STG0 + (uint32_t)(c & 1) * A_STG_SZ;

        float sacc[8][4];
#pragma unroll
        for (int j = 0; j < 8; j++)
#pragma unroll
            for (int q = 0; q < 4; q++) sacc[j][q] = 0.0f;

#pragma unroll
        for (int ks = 0; ks < 8; ks++) {
            int pnl = ks >> 2, kk = (ks & 3) * 16;
            uint32_t aoff = (uint32_t)pnl * 16384 + swz((uint32_t)(a_row * 128 + (kk + a_k) * 2));
            uint32_t aq[4];
            ldmx4(aq, base + A_Q + aoff);
#pragma unroll
            for (int jp = 0; jp < 4; jp++) {
                uint32_t boff = (uint32_t)pnl * 8192 +
                    swz((uint32_t)((jp * 16 + b_rowg) * 128 + (kk + b_k) * 2));
                uint32_t bkh[4];
                ldmx4(bkh, sb + AS_KH + boff);
                mma_f16(sacc[2 * jp],     aq, &bkh[0]);
                mma_f16(sacc[2 * jp + 1], aq, &bkh[2]);
            }
        }

        const int ks0 = kstart + c * AKC;
        float mx0 = -1e30f, mx1 = -1e30f;
#pragma unroll
        for (int j = 0; j < 8; j++) {
            int k0 = ks0 + j * 8 + colb, k1 = k0 + 1;
            int d00 = qrow0 - k0; if (d00 < 0) d00 = -d00;
            int d01 = qrow0 - k1; if (d01 < 0) d01 = -d01;
            int d10 = qrow1 - k0; if (d10 < 0) d10 = -d10;
            int d11 = qrow1 - k1; if (d11 < 0) d11 = -d11;
            if (d00 > WIN) sacc[j][0] = -1e30f;
            if (d01 > WIN) sacc[j][1] = -1e30f;
            if (d10 > WIN) sacc[j][2] = -1e30f;
            if (d11 > WIN) sacc[j][3] = -1e30f;
            mx0 = fmaxf(mx0, fmaxf(sacc[j][0], sacc[j][1]));
            mx1 = fmaxf(mx1, fmaxf(sacc[j][2], sacc[j][3]));
        }
        mx0 = fmaxf(mx0, __shfl_xor_sync(0xffffffffu, mx0, 1));
        mx0 = fmaxf(mx0, __shfl_xor_sync(0xffffffffu, mx0, 2));
        mx1 = fmaxf(mx1, __shfl_xor_sync(0xffffffffu, mx1, 1));
        mx1 = fmaxf(mx1, __shfl_xor_sync(0xffffffffu, mx1, 2));

        float mn0 = fmaxf(m0, mx0), mn1 = fmaxf(m1, mx1);
        float c0f = __expf(m0 - mn0), c1f = __expf(m1 - mn1);
        m0 = mn0; m1 = mn1;

        float rs0 = 0.0f, rs1 = 0.0f;
        uint32_t ph[8], ph2[8];
#pragma unroll
        for (int j = 0; j < 8; j++) {
            float p0 = (sacc[j][0] > -9e29f) ? __expf(sacc[j][0] - mn0) : 0.0f;
            float p1 = (sacc[j][1] > -9e29f) ? __expf(sacc[j][1] - mn0) : 0.0f;
            float p2 = (sacc[j][2] > -9e29f) ? __expf(sacc[j][2] - mn1) : 0.0f;
            float p3 = (sacc[j][3] > -9e29f) ? __expf(sacc[j][3] - mn1) : 0.0f;
            rs0 += p0 + p1; rs1 += p2 + p3;
            ph[j]  = pk2h(__float2half_rn(p0), __float2half_rn(p1));
            ph2[j] = pk2h(__float2half_rn(p2), __float2half_rn(p3));
        }
        rs0 += __shfl_xor_sync(0xffffffffu, rs0, 1);
        rs0 += __shfl_xor_sync(0xffffffffu, rs0, 2);
        rs1 += __shfl_xor_sync(0xffffffffu, rs1, 1);
        rs1 += __shfl_xor_sync(0xffffffffu, rs1, 2);
        l0s = l0s * c0f + rs0;
        l1s = l1s * c1f + rs1;
#pragma unroll
        for (int na = 0; na < 16; na++) {
            out[na][0] *= c0f; out[na][1] *= c0f;
            out[na][2] *= c1f; out[na][3] *= c1f;
        }

#pragma unroll
        for (int ks2 = 0; ks2 < 4; ks2++) {
            uint32_t Ahf[4] = { ph[2 * ks2], ph2[2 * ks2], ph[2 * ks2 + 1], ph2[2 * ks2 + 1] };
#pragma unroll
            for (int jp = 0; jp < 8; jp++) {
                uint32_t voff = swz((uint32_t)((jp * 16 + b_rowg) * 128 + (ks2 * 16 + b_k) * 2));
                uint32_t vh[4];
                ldmx4(vh, sb + AS_VH + voff);
                mma_f16(out[2 * jp],     Ahf, &vh[0]);
                mma_f16(out[2 * jp + 1], Ahf, &vh[2]);
            }
        }
        __syncthreads();
    }

    // epilogue: normalize, single-fp16 store (O-GEMM A operand)
    float inv0 = 1.0f / l0s, inv1 = 1.0f / l1s;
    size_t rb0 = ((size_t)b * LSEQ + qrow0) * HIDDEN + h * DHEAD;
    size_t rb1 = rb0 + (size_t)8 * HIDDEN;
#pragma unroll
    for (int na = 0; na < 16; na++) {
        int d = na * 8 + colb;
        *(uint32_t*)(g_ah16 + rb0 + d) = pk2h(__float2half_rn(out[na][0] * inv0),
                                              __float2half_rn(out[na][1] * inv0));
        *(uint32_t*)(g_ah16 + rb1 + d) = pk2h(__float2half_rn(out[na][2] * inv1),
                                              __float2half_rn(out[na][3] * inv1));
    }
}

// ---------------------------------------------------------------------------
// Launch. Inputs: x, cos, sin, Wq, Wk, Wv, Wo, q_norm_w, k_norm_w
// ---------------------------------------------------------------------------
extern "C" void kernel_launch(void* const* d_in, const int* in_sizes, int n_in,
                              void* d_out, int out_size)
{
    const float* x    = (const float*)d_in[0];
    const float* cosp = (const float*)d_in[1];
    const float* sinp = (const float*)d_in[2];
    const float* Wq   = (const float*)d_in[3];
    const float* Wk   = (const float*)d_in[4];
    const float* Wv   = (const float*)d_in[5];
    const float* Wo   = (const float*)d_in[6];
    const float* qw   = (const float*)d_in[7];
    const float* kw   = (const float*)d_in[8];
    float* out = (float*)d_out;

    void *p_qkv, *p_x16, *p_w16, *p_wo16, *p_ah;
    cudaGetSymbolAddress(&p_qkv,  g_qkv);
    cudaGetSymbolAddress(&p_x16,  g_x16);
    cudaGetSymbolAddress(&p_w16,  g_w16);
    cudaGetSymbolAddress(&p_wo16, g_wo16);
    cudaGetSymbolAddress(&p_ah,   g_ah16);

    cudaFuncSetAttribute(gemm_f16s, cudaFuncAttributeMaxDynamicSharedMemorySize, GEMMS_SMEM);
    cudaFuncSetAttribute(attn_mma, cudaFuncAttributeMaxDynamicSharedMemorySize, ATT_SMEM2);

    // 1) conversions (uint2 = 4 elements -> element offset / 4)
    {
        int n4 = BATCH * LSEQ * HIDDEN / 4;
        cvt_half<<<(n4 + 255) / 256, 256>>>((const float4*)x, (uint2*)p_x16, n4);
    }
    {
        int n4 = 2048 * HIDDEN / 4;   // Wq rows 0..2047
        cvt_half<<<(n4 + 255) / 256, 256>>>((const float4*)Wq, (uint2*)p_w16, n4);
    }
    {
        int n4 = 512 * HIDDEN / 4;    // Wk rows 2048..2559
        size_t off = (size_t)2048 * HIDDEN / 4;
        cvt_half<<<(n4 + 255) / 256, 256>>>((const float4*)Wk, (uint2*)p_w16 + off, n4);
    }
    {
        int n4 = 512 * HIDDEN / 4;    // Wv rows 2560..3071
        size_t off = (size_t)2560 * HIDDEN / 4;
        cvt_half<<<(n4 + 255) / 256, 256>>>((const float4*)Wv, (uint2*)p_w16 + off, n4);
    }
    {
        int n4 = HIDDEN * HIDDEN / 4; // Wo
        cvt_half<<<(n4 + 255) / 256, 256>>>((const float4*)Wo, (uint2*)p_wo16, n4);
    }

    // 2) QKV projection (single fp16 HMMA) -> g_qkv fp32
    gemm_f16s<<<dim3(BATCH * LSEQ / GMT, QKV_COLS / GNT), 256, GEMMS_SMEM>>>(
        (const __half*)p_x16, (const __half*)p_w16, (float*)p_qkv, QKV_COLS);

    // 3) RMSNorm + RoPE -> fp16 single Q (scaled) / K
    normrope_single<<<dim3(BATCH * LSEQ, H_HEADS + KV_HEADS), 128>>>(cosp, sinp, qw, kw);

    // 4) V transpose -> fp16 single
    vtrans<<<dim3(LSEQ / 32, DHEAD / 32, BATCH * KV_HEADS), dim3(32, 8)>>>();

    // 5) fp16 HMMA sliding-window flash attention -> g_ah16
    attn_mma<<<dim3(LSEQ / AQT, H_HEADS, BATCH), 256, ATT_SMEM2>>>();

    // 6) Output projection (single fp16 HMMA) -> d_out
    gemm_f16s<<<dim3(BATCH * LSEQ / GMT, HIDDEN / GNT), 256, GEMMS_SMEM>>>(
        (const __half*)p_ah, (const __half*)p_wo16, out, HIDDEN);
}

// round 16
// speedup vs baseline: 7.0211x; 1.0696x over previous
#include <cuda_runtime.h>
#include <cuda_fp16.h>
#include <math.h>
#include <stdint.h>

// Problem constants
#define H_HEADS   16
#define KV_HEADS  4
#define DHEAD     128
#define LSEQ      2048
#define BATCH     2
#define HIDDEN    2048
#define QKV_COLS  3072      // 2048 q + 512 k + 512 v
#define WIN       512
#define KDIM      2048

// ---------------------------------------------------------------------------
// Scratch (device globals; no allocation)
// ---------------------------------------------------------------------------
__device__ __half g_x16 [(size_t)BATCH * LSEQ * HIDDEN];           // x single fp16
__device__ __half g_w16 [(size_t)QKV_COLS * HIDDEN];               // Wq|Wk|Wv single fp16
__device__ __half g_wo16[(size_t)HIDDEN * HIDDEN];                 // Wo single fp16
__device__ __half g_ah16[(size_t)BATCH * LSEQ * HIDDEN];           // attn out single fp16
__device__ __half g_q16 [(size_t)BATCH * H_HEADS  * LSEQ * DHEAD]; // Q single (pre-scaled)
__device__ __half g_k16 [(size_t)BATCH * KV_HEADS * LSEQ * DHEAD]; // K single
__device__ __half g_vt16[(size_t)BATCH * KV_HEADS * DHEAD * LSEQ]; // V^T single [d][l]

// ---------------------------------------------------------------------------
// Base-ISA PTX helpers
// ---------------------------------------------------------------------------
__device__ __forceinline__ uint32_t smem_u32(const void* p) {
    uint32_t r;
    asm("{ .reg .u64 t; cvta.to.shared.u64 t, %1; cvt.u32.u64 %0, t; }" : "=r"(r) : "l"(p));
    return r;
}
__device__ __forceinline__ void cpa16(uint32_t s, const void* g) {
    asm volatile("cp.async.cg.shared.global [%0], [%1], 16;" :: "r"(s), "l"(g));
}
#define CPA_COMMIT() asm volatile("cp.async.commit_group;" ::: "memory")
#define CPA_WAIT(n)  asm volatile("cp.async.wait_group %0;" :: "n"(n) : "memory")

__device__ __forceinline__ uint32_t swz(uint32_t o) { return o ^ ((o >> 3) & 0x70); }

__device__ __forceinline__ void ldmx4(uint32_t* r, uint32_t a) {
    asm volatile("ldmatrix.sync.aligned.m8n8.x4.shared.b16 {%0,%1,%2,%3}, [%4];"
        : "=r"(r[0]), "=r"(r[1]), "=r"(r[2]), "=r"(r[3]) : "r"(a));
}
__device__ __forceinline__ void mma_f16(float* c, const uint32_t* a, const uint32_t* b) {
    asm volatile("mma.sync.aligned.m16n8k16.row.col.f32.f16.f16.f32 "
        "{%0,%1,%2,%3}, {%4,%5,%6,%7}, {%8,%9}, {%0,%1,%2,%3};"
        : "+f"(c[0]), "+f"(c[1]), "+f"(c[2]), "+f"(c[3])
        : "r"(a[0]), "r"(a[1]), "r"(a[2]), "r"(a[3]), "r"(b[0]), "r"(b[1]));
}
__device__ __forceinline__ unsigned pk2h(__half a, __half b) {
    __half2 t = __halves2half2(a, b);
    return *reinterpret_cast<unsigned*>(&t);
}

// ---------------------------------------------------------------------------
// Shared GEMM mainloop config (128x256 tile, single fp16, fp32 accum)
// ---------------------------------------------------------------------------
#define GMT 128
#define GNT 256
#define GNKC (KDIM / 64)
#define S_OFF_A 0
#define S_OFF_B 16384
#define S_STAGE 49152
#define GEMMS_SMEM (2 * S_STAGE)     // 96 KB

// Mainloop macro body shared by both GEMMs (identical proven code path)
#define GEMM_MAINLOOP(Aptr, Bptr)                                                  \
    const uint32_t base = smem_u32(dsm);                                           \
    const int tid = threadIdx.x, lane = tid & 31, wid = tid >> 5;                  \
    const int wm = wid & 3, wn = wid >> 2;                                         \
    const int m0 = blockIdx.x * GMT, n0 = blockIdx.y * GNT;                        \
    const int a_row  = wm * 32 + (lane & 15);                                      \
    const int a_k    = (lane >> 4) * 8;                                            \
    const int b_rowg = (lane >> 4) * 8 + (lane & 7);                               \
    const int b_k    = ((lane >> 3) & 1) * 8;                                      \
    float acc[2][16][4];                                                           \
    _Pragma("unroll")                                                              \
    for (int i = 0; i < 2; i++)                                                    \
        _Pragma("unroll")                                                          \
        for (int j = 0; j < 16; j++)                                               \
            _Pragma("unroll")                                                      \
            for (int q = 0; q < 4; q++) acc[i][j][q] = 0.0f;                       \
    auto load_stage = [&](int kc, int s) {                                         \
        const uint32_t sb = base + (uint32_t)s * S_STAGE;                          \
        _Pragma("unroll")                                                          \
        for (int i = 0; i < 4; i++) {                                              \
            int u = tid + 256 * i;                                                 \
            int r = u >> 3, cu = u & 7;                                            \
            uint32_t so = swz((uint32_t)(r * 128 + cu * 16));                      \
            cpa16(sb + S_OFF_A + so, Aptr + ((size_t)(m0 + r) << 11) + (kc << 6) + (cu << 3)); \
        }                                                                          \
        _Pragma("unroll")                                                          \
        for (int i = 0; i < 8; i++) {                                              \
            int u = tid + 256 * i;                                                 \
            int r = u >> 3, cu = u & 7;                                            \
            uint32_t so = swz((uint32_t)(r * 128 + cu * 16));                      \
            cpa16(sb + S_OFF_B + so, Bptr + ((size_t)(n0 + r) << 11) + (kc << 6) + (cu << 3)); \
        }                                                                          \
        CPA_COMMIT();                                                              \
    };                                                                             \
    load_stage(0, 0);                                                              \
    for (int kc = 0; kc < GNKC; kc++) {                                            \
        if (kc + 1 < GNKC) { load_stage(kc + 1, (kc + 1) & 1); CPA_WAIT(1); }      \
        else               { CPA_WAIT(0); }                                        \
        __syncthreads();                                                           \
        const uint32_t sb  = base + (uint32_t)(kc & 1) * S_STAGE;                  \
        const uint32_t a_b = sb + S_OFF_A, b_b = sb + S_OFF_B;                     \
        _Pragma("unroll")                                                          \
        for (int ks = 0; ks < 4; ks++) {                                           \
            uint32_t af[2][4];                                                     \
            _Pragma("unroll")                                                      \
            for (int i = 0; i < 2; i++) {                                          \
                uint32_t off = swz((uint32_t)((a_row + i * 16) * 128 + (a_k + ks * 16) * 2)); \
                ldmx4(af[i], a_b + off);                                           \
            }                                                                      \
            _Pragma("unroll")                                                      \
            for (int jp = 0; jp < 8; jp++) {                                       \
                int nrow = wn * 128 + jp * 16 + b_rowg;                            \
                uint32_t off = swz((uint32_t)(nrow * 128 + (b_k + ks * 16) * 2));  \
                uint32_t bf[4];                                                    \
                ldmx4(bf, b_b + off);                                              \
                _Pragma("unroll")                                                  \
                for (int i = 0; i < 2; i++) {                                      \
                    mma_f16(acc[i][2 * jp],     af[i], &bf[0]);                    \
                    mma_f16(acc[i][2 * jp + 1], af[i], &bf[2]);                    \
                }                                                                  \
            }                                                                      \
        }                                                                          \
        __syncthreads();                                                           \
    }

// ---------------------------------------------------------------------------
// Plain GEMM (O projection): fp32 output
// ---------------------------------------------------------------------------
__global__ __launch_bounds__(256, 1)
void gemm_f16s(const __half* __restrict__ A, const __half* __restrict__ B,
               float* __restrict__ C, int ldc)
{
    extern __shared__ __align__(128) char dsm[];
    GEMM_MAINLOOP(A, B)

#pragma unroll
    for (int i = 0; i < 2; i++) {
        int row = m0 + wm * 32 + i * 16 + (lane >> 2);
#pragma unroll
        for (int j = 0; j < 16; j++) {
            int col = n0 + wn * 128 + j * 8 + 2 * (lane & 3);
            *(float2*)&C[(size_t)row * ldc + col]       = make_float2(acc[i][j][0], acc[i][j][1]);
            *(float2*)&C[(size_t)(row + 8) * ldc + col] = make_float2(acc[i][j][2], acc[i][j][3]);
        }
    }
}

// ---------------------------------------------------------------------------
// Fused QKV GEMM: epilogue applies RMSNorm+RoPE (q,k) or transpose (v),
// writes fp16 directly to g_q16 / g_k16 / g_vt16. No fp32 intermediate.
// Each warp's 128-col half-tile = exactly one head.
// ---------------------------------------------------------------------------
__global__ __launch_bounds__(256, 1)
void gemm_qkv_fused(const __half* __restrict__ A, const __half* __restrict__ B,
                    const float* __restrict__ cosp, const float* __restrict__ sinp,
                    const float* __restrict__ qw,  const float* __restrict__ kw)
{
    extern __shared__ __align__(128) char dsm[];
    GEMM_MAINLOOP(A, B)

    const int nh = n0 + wn * 128;          // head-aligned column base (warp-uniform)
    const int dq = 2 * (lane & 3);         // in-head col base for q=0; d = j*8 + dq + q

    if (nh < 2560) {
        // ---- Q or K: RMSNorm + RoPE ----
        const bool isq = (nh < 2048);
        const float* w = isq ? qw : kw;
        const float sc = isq ? 0.08838834764831845f : 1.0f;
        __half* dbase;
        if (isq) {
            int e = nh >> 7;
            dbase = g_q16 + (size_t)e * LSEQ * DHEAD;          // + b*H*L*D later via row
        } else {
            int kvh = (nh - 2048) >> 7;
            dbase = g_k16 + (size_t)kvh * LSEQ * DHEAD;
        }
        const int nheads = isq ? H_HEADS : KV_HEADS;

        // preload weight pairs (w[d], w[d+1]) for the 16 j's
        float2 wv[16];
#pragma unroll
        for (int j = 0; j < 16; j++)
            wv[j] = *(const float2*)&w[j * 8 + dq];

#pragma unroll
        for (int i = 0; i < 2; i++) {
#pragma unroll
            for (int half = 0; half < 2; half++) {
                int row = m0 + wm * 32 + i * 16 + (lane >> 2) + half * 8;
                int b = row >> 11, l = row & (LSEQ - 1);
                // gather this row's 32 values
                float v[16][2];
                float ss = 0.0f;
#pragma unroll
                for (int j = 0; j < 16; j++) {
                    v[j][0] = acc[i][j][half * 2 + 0];
                    v[j][1] = acc[i][j][half * 2 + 1];
                    ss += v[j][0] * v[j][0] + v[j][1] * v[j][1];
                }
                ss += __shfl_xor_sync(0xffffffffu, ss, 1);
                ss += __shfl_xor_sync(0xffffffffu, ss, 2);
                float inv = rsqrtf(ss * (1.0f / 128.0f) + 1e-6f);
                // normalize
#pragma unroll
                for (int j = 0; j < 16; j++) {
                    v[j][0] *= inv * wv[j].x;
                    v[j][1] *= inv * wv[j].y;
                }
                // RoPE + store (d and d+64 are j and j+8, same thread)
                __half* drow = dbase + ((size_t)b * nheads * LSEQ + l) * DHEAD;
#pragma unroll
                for (int j = 0; j < 16; j++) {
                    int d = j * 8 + dq;
                    float2 cs = *(const float2*)&cosp[l * DHEAD + d];
                    float2 sn = *(const float2*)&sinp[l * DHEAD + d];
                    float r0 = (j < 8) ? -v[j + 8][0] : v[j - 8][0];
                    float r1 = (j < 8) ? -v[j + 8][1] : v[j - 8][1];
                    float o0 = (v[j][0] * cs.x + r0 * sn.x) * sc;
                    float o1 = (v[j][1] * cs.y + r1 * sn.y) * sc;
                    *(uint32_t*)(drow + d) = pk2h(__float2half_rn(o0), __float2half_rn(o1));
                }
            }
        }
    } else {
        // ---- V: direct transposed fp16 store to g_vt16[b][kvh][d][l] ----
        int kvh = (nh - 2560) >> 7;
#pragma unroll
        for (int i = 0; i < 2; i++) {
#pragma unroll
            for (int half = 0; half < 2; half++) {
                int row = m0 + wm * 32 + i * 16 + (lane >> 2) + half * 8;
                int b = row >> 11, l = row & (LSEQ - 1);
                __half* vbase = g_vt16 + (size_t)(b * KV_HEADS + kvh) * DHEAD * LSEQ;
#pragma unroll
                for (int j = 0; j < 16; j++) {
                    int d = j * 8 + dq;
                    vbase[(size_t)d * LSEQ + l]       = __float2half_rn(acc[i][j][half * 2 + 0]);
                    vbase[(size_t)(d + 1) * LSEQ + l] = __float2half_rn(acc[i][j][half * 2 + 1]);
                }
            }
        }
    }
}

// ---------------------------------------------------------------------------
// Conversion: fp32 -> fp16 single
// ---------------------------------------------------------------------------
__global__ __launch_bounds__(256)
void cvt_half(const float4* __restrict__ src, uint2* __restrict__ dst, int n4)
{
    int i = blockIdx.x * 256 + threadIdx.x;
    if (i >= n4) return;
    float4 v = src[i];
    dst[i] = make_uint2(pk2h(__float2half_rn(v.x), __float2half_rn(v.y)),
                        pk2h(__float2half_rn(v.z), __float2half_rn(v.w)));
}

// ---------------------------------------------------------------------------
// fp16 HMMA flash attention (proven R15): QK = Q*K; PV = P*V (all single)
// ---------------------------------------------------------------------------
#define AQT 128
#define AKC 64
#define A_Q 0
#define A_STG0 32768
#define A_STG_SZ 32768
#define AS_KH 0
#define AS_VH 16384
#define ATT_SMEM2 98304

__global__ __launch_bounds__(256, 1)
void attn_mma()
{
    extern __shared__ __align__(128) char asmem[];
    const uint32_t base = smem_u32(asmem);
    const int tid = threadIdx.x, lane = tid & 31, w = tid >> 5;
    const int qt = blockIdx.x, h = blockIdx.y, b = blockIdx.z;
    const int kvh = h >> 2;
    const int q0 = qt * AQT;

    {
        const __half* qp = g_q16 + ((size_t)(b * H_HEADS + h) * LSEQ + q0) * DHEAD;
#pragma unroll
        for (int i = 0; i < 8; i++) {
            int u = tid + 256 * i;
            int r = u >> 4, cu = u & 15;
            uint32_t so = (uint32_t)(cu >> 3) * 16384 + swz((uint32_t)(r * 128 + (cu & 7) * 16));
            cpa16(base + A_Q + so, qp + (size_t)r * DHEAD + cu * 8);
        }
        CPA_COMMIT();
    }

    int kstart = q0 - WIN;       if (kstart < 0)  kstart = 0;
    int kend   = q0 + AQT + WIN; if (kend > LSEQ) kend = LSEQ;
    const int nc = (kend - kstart) / AKC;

    const __half* kh  = g_k16  + (size_t)(b * KV_HEADS + kvh) * LSEQ * DHEAD;
    const __half* vth = g_vt16 + (size_t)(b * KV_HEADS + kvh) * DHEAD * LSEQ;

    auto load_kv = [&](int c, int s) {
        const uint32_t sb = base + A_STG0 + (uint32_t)s * A_STG_SZ;
        const int ks = kstart + c * AKC;
#pragma unroll
        for (int i = 0; i < 4; i++) {
            int u = tid + 256 * i;
            int r = u >> 4, cu = u & 15;
            uint32_t so = (uint32_t)(cu >> 3) * 8192 + swz((uint32_t)(r * 128 + (cu & 7) * 16));
            cpa16(sb + AS_KH + so, kh + (size_t)(ks + r) * DHEAD + cu * 8);
        }
#pragma unroll
        for (int i = 0; i < 4; i++) {
            int u = tid + 256 * i;
            int d = u >> 3, cu = u & 7;
            uint32_t so = swz((uint32_t)(d * 128 + cu * 16));
            cpa16(sb + AS_VH + so, vth + (size_t)d * LSEQ + ks + cu * 8);
        }
        CPA_COMMIT();
    };

    load_kv(0, 0);

    const int a_row  = w * 16 + (lane & 15);
    const int a_k    = (lane >> 4) * 8;
    const int b_rowg = (lane >> 4) * 8 + (lane & 7);
    const int b_k    = ((lane >> 3) & 1) * 8;
    const int r0     = lane >> 2, colb = 2 * (lane & 3);
    const int qrow0  = q0 + w * 16 + r0;
    const int qrow1  = qrow0 + 8;

    float out[16][4];
#pragma unroll
    for (int na = 0; na < 16; na++)
#pragma unroll
        for (int q = 0; q < 4; q++) out[na][q] = 0.0f;
    float m0 = -1e30f, m1 = -1e30f, l0s = 0.0f, l1s = 0.0f;

    for (int c = 0; c < nc; c++) {
        if (c + 1 < nc) { load_kv(c + 1, (c + 1) & 1); CPA_WAIT(1); }
        else            { CPA_WAIT(0); }
        __syncthreads();
        const uint32_t sb = base + A_STG0 + (uint32_t)(c & 1) * A_STG_SZ;

        float sacc[8][4];
#pragma unroll
        for (int j = 0; j < 8; j++)
#pragma unroll
            for (int q = 0; q < 4; q++) sacc[j][q] = 0.0f;

#pragma unroll
        for (int ks = 0; ks < 8; ks++) {
            int pnl = ks >> 2, kk = (ks & 3) * 16;
            uint32_t aoff = (uint32_t)pnl * 16384 + swz((uint32_t)(a_row * 128 + (kk + a_k) * 2));
            uint32_t aq[4];
            ldmx4(aq, base + A_Q + aoff);
#pragma unroll
            for (int jp = 0; jp < 4; jp++) {
                uint32_t boff = (uint32_t)pnl * 8192 +
                    swz((uint32_t)((jp * 16 + b_rowg) * 128 + (kk + b_k) * 2));
                uint32_t bkh[4];
                ldmx4(bkh, sb + AS_KH + boff);
                mma_f16(sacc[2 * jp],     aq, &bkh[0]);
                mma_f16(sacc[2 * jp + 1], aq, &bkh[2]);
            }
        }

        const int ks0 = kstart + c * AKC;
        float mx0 = -1e30f, mx1 = -1e30f;
#pragma unroll
        for (int j = 0; j < 8; j++) {
            int k0 = ks0 + j * 8 + colb, k1 = k0 + 1;
            int d00 = qrow0 - k0; if (d00 < 0) d00 = -d00;
            int d01 = qrow0 - k1; if (d01 < 0) d01 = -d01;
            int d10 = qrow1 - k0; if (d10 < 0) d10 = -d10;
            int d11 = qrow1 - k1; if (d11 < 0) d11 = -d11;
            if (d00 > WIN) sacc[j][0] = -1e30f;
            if (d01 > WIN) sacc[j][1] = -1e30f;
            if (d10 > WIN) sacc[j][2] = -1e30f;
            if (d11 > WIN) sacc[j][3] = -1e30f;
            mx0 = fmaxf(mx0, fmaxf(sacc[j][0], sacc[j][1]));
            mx1 = fmaxf(mx1, fmaxf(sacc[j][2], sacc[j][3]));
        }
        mx0 = fmaxf(mx0, __shfl_xor_sync(0xffffffffu, mx0, 1));
        mx0 = fmaxf(mx0, __shfl_xor_sync(0xffffffffu, mx0, 2));
        mx1 = fmaxf(mx1, __shfl_xor_sync(0xffffffffu, mx1, 1));
        mx1 = fmaxf(mx1, __shfl_xor_sync(0xffffffffu, mx1, 2));

        float mn0 = fmaxf(m0, mx0), mn1 = fmaxf(m1, mx1);
        float c0f = __expf(m0 - mn0), c1f = __expf(m1 - mn1);
        m0 = mn0; m1 = mn1;

        float rs0 = 0.0f, rs1 = 0.0f;
        uint32_t ph[8], ph2[8];
#pragma unroll
        for (int j = 0; j < 8; j++) {
            float p0 = (sacc[j][0] > -9e29f) ? __expf(sacc[j][0] - mn0) : 0.0f;
            float p1 = (sacc[j][1] > -9e29f) ? __expf(sacc[j][1] - mn0) : 0.0f;
            float p2 = (sacc[j][2] > -9e29f) ? __expf(sacc[j][2] - mn1) : 0.0f;
            float p3 = (sacc[j][3] > -9e29f) ? __expf(sacc[j][3] - mn1) : 0.0f;
            rs0 += p0 + p1; rs1 += p2 + p3;
            ph[j]  = pk2h(__float2half_rn(p0), __float2half_rn(p1));
            ph2[j] = pk2h(__float2half_rn(p2), __float2half_rn(p3));
        }
        rs0 += __shfl_xor_sync(0xffffffffu, rs0, 1);
        rs0 += __shfl_xor_sync(0xffffffffu, rs0, 2);
        rs1 += __shfl_xor_sync(0xffffffffu, rs1, 1);
        rs1 += __shfl_xor_sync(0xffffffffu, rs1, 2);
        l0s = l0s * c0f + rs0;
        l1s = l1s * c1f + rs1;
#pragma unroll
        for (int na = 0; na < 16; na++) {
            out[na][0] *= c0f; out[na][1] *= c0f;
            out[na][2] *= c1f; out[na][3] *= c1f;
        }

#pragma unroll
        for (int ks2 = 0; ks2 < 4; ks2++) {
            uint32_t Ahf[4] = { ph[2 * ks2], ph2[2 * ks2], ph[2 * ks2 + 1], ph2[2 * ks2 + 1] };
#pragma unroll
            for (int jp = 0; jp < 8; jp++) {
                uint32_t voff = swz((uint32_t)((jp * 16 + b_rowg) * 128 + (ks2 * 16 + b_k) * 2));
                uint32_t vh[4];
                ldmx4(vh, sb + AS_VH + voff);
                mma_f16(out[2 * jp],     Ahf, &vh[0]);
                mma_f16(out[2 * jp + 1], Ahf, &vh[2]);
            }
        }
        __syncthreads();
    }

    // epilogue: normalize, single-fp16 store (O-GEMM A operand)
    float inv0 = 1.0f / l0s, inv1 = 1.0f / l1s;
    size_t rb0 = ((size_t)b * LSEQ + qrow0) * HIDDEN + h * DHEAD;
    size_t rb1 = rb0 + (size_t)8 * HIDDEN;
#pragma unroll
    for (int na = 0; na < 16; na++) {
        int d = na * 8 + colb;
        *(uint32_t*)(g_ah16 + rb0 + d) = pk2h(__float2half_rn(out[na][0] * inv0),
                                              __float2half_rn(out[na][1] * inv0));
        *(uint32_t*)(g_ah16 + rb1 + d) = pk2h(__float2half_rn(out[na][2] * inv1),
                                              __float2half_rn(out[na][3] * inv1));
    }
}

// ---------------------------------------------------------------------------
// Launch. Inputs: x, cos, sin, Wq, Wk, Wv, Wo, q_norm_w, k_norm_w
// ---------------------------------------------------------------------------
extern "C" void kernel_launch(void* const* d_in, const int* in_sizes, int n_in,
                              void* d_out, int out_size)
{
    const float* x    = (const float*)d_in[0];
    const float* cosp = (const float*)d_in[1];
    const float* sinp = (const float*)d_in[2];
    const float* Wq   = (const float*)d_in[3];
    const float* Wk   = (const float*)d_in[4];
    const float* Wv   = (const float*)d_in[5];
    const float* Wo   = (const float*)d_in[6];
    const float* qw   = (const float*)d_in[7];
    const float* kw   = (const float*)d_in[8];
    float* out = (float*)d_out;

    void *p_x16, *p_w16, *p_wo16, *p_ah;
    cudaGetSymbolAddress(&p_x16,  g_x16);
    cudaGetSymbolAddress(&p_w16,  g_w16);
    cudaGetSymbolAddress(&p_wo16, g_wo16);
    cudaGetSymbolAddress(&p_ah,   g_ah16);

    cudaFuncSetAttribute(gemm_f16s, cudaFuncAttributeMaxDynamicSharedMemorySize, GEMMS_SMEM);
    cudaFuncSetAttribute(gemm_qkv_fused, cudaFuncAttributeMaxDynamicSharedMemorySize, GEMMS_SMEM);
    cudaFuncSetAttribute(attn_mma, cudaFuncAttributeMaxDynamicSharedMemorySize, ATT_SMEM2);

    // 1) conversions (uint2 = 4 elements -> element offset / 4)
    {
        int n4 = BATCH * LSEQ * HIDDEN / 4;
        cvt_half<<<(n4 + 255) / 256, 256>>>((const float4*)x, (uint2*)p_x16, n4);
    }
    {
        int n4 = 2048 * HIDDEN / 4;   // Wq rows 0..2047
        cvt_half<<<(n4 + 255) / 256, 256>>>((const float4*)Wq, (uint2*)p_w16, n4);
    }
    {
        int n4 = 512 * HIDDEN / 4;    // Wk rows 2048..2559
        size_t off = (size_t)2048 * HIDDEN / 4;
        cvt_half<<<(n4 + 255) / 256, 256>>>((const float4*)Wk, (uint2*)p_w16 + off, n4);
    }
    {
        int n4 = 512 * HIDDEN / 4;    // Wv rows 2560..3071
        size_t off = (size_t)2560 * HIDDEN / 4;
        cvt_half<<<(n4 + 255) / 256, 256>>>((const float4*)Wv, (uint2*)p_w16 + off, n4);
    }
    {
        int n4 = HIDDEN * HIDDEN / 4; // Wo
        cvt_half<<<(n4 + 255) / 256, 256>>>((const float4*)Wo, (uint2*)p_wo16, n4);
    }

    // 2) Fused QKV projection + RMSNorm + RoPE + V-transpose (all fp16 out)
    gemm_qkv_fused<<<dim3(BATCH * LSEQ / GMT, QKV_COLS / GNT), 256, GEMMS_SMEM>>>(
        (const __half*)p_x16, (const __half*)p_w16, cosp, sinp, qw, kw);

    // 3) fp16 HMMA sliding-window flash attention -> g_ah16
    attn_mma<<<dim3(LSEQ / AQT, H_HEADS, BATCH), 256, ATT_SMEM2>>>();

    // 4) Output projection (single fp16 HMMA) -> d_out
    gemm_f16s<<<dim3(BATCH * LSEQ / GMT, HIDDEN / GNT), 256, GEMMS_SMEM>>>(
        (const __half*)p_ah, (const __half*)p_wo16, out, HIDDEN);
}

// round 17
// speedup vs baseline: 7.2583x; 1.0338x over previous
#include <cuda_runtime.h>
#include <cuda_fp16.h>
#include <math.h>
#include <stdint.h>

// Problem constants
#define H_HEADS   16
#define KV_HEADS  4
#define DHEAD     128
#define LSEQ      2048
#define BATCH     2
#define HIDDEN    2048
#define QKV_COLS  3072      // 2048 q + 512 k + 512 v
#define WIN       512
#define KDIM      2048

// ---------------------------------------------------------------------------
// Scratch (device globals; no allocation)
// ---------------------------------------------------------------------------
__device__ __half g_x16 [(size_t)BATCH * LSEQ * HIDDEN];           // x single fp16
__device__ __half g_w16 [(size_t)QKV_COLS * HIDDEN];               // Wq|Wk|Wv single fp16
__device__ __half g_wo16[(size_t)HIDDEN * HIDDEN];                 // Wo single fp16
__device__ __half g_ah16[(size_t)BATCH * LSEQ * HIDDEN];           // attn out single fp16
__device__ __half g_q16 [(size_t)BATCH * H_HEADS  * LSEQ * DHEAD]; // Q single (pre-scaled)
__device__ __half g_k16 [(size_t)BATCH * KV_HEADS * LSEQ * DHEAD]; // K single
__device__ __half g_vt16[(size_t)BATCH * KV_HEADS * DHEAD * LSEQ]; // V^T single [d][l]

// ---------------------------------------------------------------------------
// Base-ISA PTX helpers
// ---------------------------------------------------------------------------
__device__ __forceinline__ uint32_t smem_u32(const void* p) {
    uint32_t r;
    asm("{ .reg .u64 t; cvta.to.shared.u64 t, %1; cvt.u32.u64 %0, t; }" : "=r"(r) : "l"(p));
    return r;
}
__device__ __forceinline__ void cpa16(uint32_t s, const void* g) {
    asm volatile("cp.async.cg.shared.global [%0], [%1], 16;" :: "r"(s), "l"(g));
}
#define CPA_COMMIT() asm volatile("cp.async.commit_group;" ::: "memory")
#define CPA_WAIT(n)  asm volatile("cp.async.wait_group %0;" :: "n"(n) : "memory")

__device__ __forceinline__ uint32_t swz(uint32_t o) { return o ^ ((o >> 3) & 0x70); }

__device__ __forceinline__ void ldmx4(uint32_t* r, uint32_t a) {
    asm volatile("ldmatrix.sync.aligned.m8n8.x4.shared.b16 {%0,%1,%2,%3}, [%4];"
        : "=r"(r[0]), "=r"(r[1]), "=r"(r[2]), "=r"(r[3]) : "r"(a));
}
__device__ __forceinline__ void mma_f16(float* c, const uint32_t* a, const uint32_t* b) {
    asm volatile("mma.sync.aligned.m16n8k16.row.col.f32.f16.f16.f32 "
        "{%0,%1,%2,%3}, {%4,%5,%6,%7}, {%8,%9}, {%0,%1,%2,%3};"
        : "+f"(c[0]), "+f"(c[1]), "+f"(c[2]), "+f"(c[3])
        : "r"(a[0]), "r"(a[1]), "r"(a[2]), "r"(a[3]), "r"(b[0]), "r"(b[1]));
}
__device__ __forceinline__ unsigned pk2h(__half a, __half b) {
    __half2 t = __halves2half2(a, b);
    return *reinterpret_cast<unsigned*>(&t);
}

// ---------------------------------------------------------------------------
// Shared GEMM mainloop config (128x256 tile, single fp16, fp32 accum)
// ---------------------------------------------------------------------------
#define GMT 128
#define GNT 256
#define GNKC (KDIM / 64)
#define S_OFF_A 0
#define S_OFF_B 16384
#define S_STAGE 49152
#define GEMMS_SMEM (2 * S_STAGE)     // 96 KB

#define GEMM_MAINLOOP(Aptr, Bptr)                                                  \
    const uint32_t base = smem_u32(dsm);                                           \
    const int tid = threadIdx.x, lane = tid & 31, wid = tid >> 5;                  \
    const int wm = wid & 3, wn = wid >> 2;                                         \
    const int m0 = blockIdx.x * GMT, n0 = blockIdx.y * GNT;                        \
    const int a_row  = wm * 32 + (lane & 15);                                      \
    const int a_k    = (lane >> 4) * 8;                                            \
    const int b_rowg = (lane >> 4) * 8 + (lane & 7);                               \
    const int b_k    = ((lane >> 3) & 1) * 8;                                      \
    float acc[2][16][4];                                                           \
    _Pragma("unroll")                                                              \
    for (int i = 0; i < 2; i++)                                                    \
        _Pragma("unroll")                                                          \
        for (int j = 0; j < 16; j++)                                               \
            _Pragma("unroll")                                                      \
            for (int q = 0; q < 4; q++) acc[i][j][q] = 0.0f;                       \
    auto load_stage = [&](int kc, int s) {                                         \
        const uint32_t sb = base + (uint32_t)s * S_STAGE;                          \
        _Pragma("unroll")                                                          \
        for (int i = 0; i < 4; i++) {                                              \
            int u = tid + 256 * i;                                                 \
            int r = u >> 3, cu = u & 7;                                            \
            uint32_t so = swz((uint32_t)(r * 128 + cu * 16));                      \
            cpa16(sb + S_OFF_A + so, Aptr + ((size_t)(m0 + r) << 11) + (kc << 6) + (cu << 3)); \
        }                                                                          \
        _Pragma("unroll")                                                          \
        for (int i = 0; i < 8; i++) {                                              \
            int u = tid + 256 * i;                                                 \
            int r = u >> 3, cu = u & 7;                                            \
            uint32_t so = swz((uint32_t)(r * 128 + cu * 16));                      \
            cpa16(sb + S_OFF_B + so, Bptr + ((size_t)(n0 + r) << 11) + (kc << 6) + (cu << 3)); \
        }                                                                          \
        CPA_COMMIT();                                                              \
    };                                                                             \
    load_stage(0, 0);                                                              \
    for (int kc = 0; kc < GNKC; kc++) {                                            \
        if (kc + 1 < GNKC) { load_stage(kc + 1, (kc + 1) & 1); CPA_WAIT(1); }      \
        else               { CPA_WAIT(0); }                                        \
        __syncthreads();                                                           \
        const uint32_t sb  = base + (uint32_t)(kc & 1) * S_STAGE;                  \
        const uint32_t a_b = sb + S_OFF_A, b_b = sb + S_OFF_B;                     \
        _Pragma("unroll")                                                          \
        for (int ks = 0; ks < 4; ks++) {                                           \
            uint32_t af[2][4];                                                     \
            _Pragma("unroll")                                                      \
            for (int i = 0; i < 2; i++) {                                          \
                uint32_t off = swz((uint32_t)((a_row + i * 16) * 128 + (a_k + ks * 16) * 2)); \
                ldmx4(af[i], a_b + off);                                           \
            }                                                                      \
            _Pragma("unroll")                                                      \
            for (int jp = 0; jp < 8; jp++) {                                       \
                int nrow = wn * 128 + jp * 16 + b_rowg;                            \
                uint32_t off = swz((uint32_t)(nrow * 128 + (b_k + ks * 16) * 2));  \
                uint32_t bf[4];                                                    \
                ldmx4(bf, b_b + off);                                              \
                _Pragma("unroll")                                                  \
                for (int i = 0; i < 2; i++) {                                      \
                    mma_f16(acc[i][2 * jp],     af[i], &bf[0]);                    \
                    mma_f16(acc[i][2 * jp + 1], af[i], &bf[2]);                    \
                }                                                                  \
            }                                                                      \
        }                                                                          \
        __syncthreads();                                                           \
    }

// ---------------------------------------------------------------------------
// Plain GEMM (O projection): fp32 output
// ---------------------------------------------------------------------------
__global__ __launch_bounds__(256, 1)
void gemm_f16s(const __half* __restrict__ A, const __half* __restrict__ B,
               float* __restrict__ C, int ldc)
{
    extern __shared__ __align__(128) char dsm[];
    GEMM_MAINLOOP(A, B)

#pragma unroll
    for (int i = 0; i < 2; i++) {
        int row = m0 + wm * 32 + i * 16 + (lane >> 2);
#pragma unroll
        for (int j = 0; j < 16; j++) {
            int col = n0 + wn * 128 + j * 8 + 2 * (lane & 3);
            *(float2*)&C[(size_t)row * ldc + col]       = make_float2(acc[i][j][0], acc[i][j][1]);
            *(float2*)&C[(size_t)(row + 8) * ldc + col] = make_float2(acc[i][j][2], acc[i][j][3]);
        }
    }
}

// ---------------------------------------------------------------------------
// Fused QKV GEMM: epilogue RMSNorm+RoPE (q,k) / transpose (v), fp16 out.
// Stores staged through per-warp 8KB smem regions for coalescing.
// Each warp's 128-col half-tile = exactly one head; warp rows are 32 tokens.
// ---------------------------------------------------------------------------
__global__ __launch_bounds__(256, 1)
void gemm_qkv_fused(const __half* __restrict__ A, const __half* __restrict__ B,
                    const float* __restrict__ cosp, const float* __restrict__ sinp,
                    const float* __restrict__ qw,  const float* __restrict__ kw)
{
    extern __shared__ __align__(128) char dsm[];
    GEMM_MAINLOOP(A, B)

    // After the final __syncthreads() the stage buffers are dead: each warp
    // takes a private 8 KB region for store staging.
    char* wsm = dsm + (size_t)wid * 8192;

    const int nh = n0 + wn * 128;          // head-aligned column base (warp-uniform)
    const int dq = 2 * (lane & 3);         // in-head col base; d = j*8 + dq (+1)
    const int rowg0 = m0 + wm * 32;        // warp's first token row (32 contiguous)

    if (nh < 2560) {
        // ---- Q or K: RMSNorm + RoPE, staged as [row_local][d] (256B rows) ----
        const bool isq = (nh < 2048);
        const float* w = isq ? qw : kw;
        const float sc = isq ? 0.08838834764831845f : 1.0f;
        __half* dbase;
        if (isq) dbase = g_q16 + (size_t)(nh >> 7) * LSEQ * DHEAD;
        else     dbase = g_k16 + (size_t)((nh - 2048) >> 7) * LSEQ * DHEAD;
        const int nheads = isq ? H_HEADS : KV_HEADS;

        float2 wv[16];
#pragma unroll
        for (int j = 0; j < 16; j++)
            wv[j] = *(const float2*)&w[j * 8 + dq];

#pragma unroll
        for (int i = 0; i < 2; i++) {
#pragma unroll
            for (int half = 0; half < 2; half++) {
                int rl  = i * 16 + half * 8 + (lane >> 2);   // 0..31
                int row = rowg0 + rl;
                int l = row & (LSEQ - 1);
                float v[16][2];
                float ss = 0.0f;
#pragma unroll
                for (int j = 0; j < 16; j++) {
                    v[j][0] = acc[i][j][half * 2 + 0];
                    v[j][1] = acc[i][j][half * 2 + 1];
                    ss += v[j][0] * v[j][0] + v[j][1] * v[j][1];
                }
                ss += __shfl_xor_sync(0xffffffffu, ss, 1);
                ss += __shfl_xor_sync(0xffffffffu, ss, 2);
                float inv = rsqrtf(ss * (1.0f / 128.0f) + 1e-6f);
#pragma unroll
                for (int j = 0; j < 16; j++) {
                    v[j][0] *= inv * wv[j].x;
                    v[j][1] *= inv * wv[j].y;
                }
#pragma unroll
                for (int j = 0; j < 16; j++) {
                    int d = j * 8 + dq;
                    float2 cs = *(const float2*)&cosp[l * DHEAD + d];
                    float2 sn = *(const float2*)&sinp[l * DHEAD + d];
                    float r0 = (j < 8) ? -v[j + 8][0] : v[j - 8][0];
                    float r1 = (j < 8) ? -v[j + 8][1] : v[j - 8][1];
                    float o0 = (v[j][0] * cs.x + r0 * sn.x) * sc;
                    float o1 = (v[j][1] * cs.y + r1 * sn.y) * sc;
                    *(uint32_t*)(wsm + rl * 256 + d * 2) =
                        pk2h(__float2half_rn(o0), __float2half_rn(o1));
                }
            }
        }
        __syncwarp();
        // stream out: one 256B row per iteration, 8B per lane
#pragma unroll 4
        for (int r = 0; r < 32; r++) {
            int row = rowg0 + r;
            int b = row >> 11, l = row & (LSEQ - 1);
            __half* drow = dbase + ((size_t)b * nheads * LSEQ + l) * DHEAD;
            *(uint2*)(drow + lane * 4) = *(const uint2*)(wsm + r * 256 + lane * 8);
        }
    } else {
        // ---- V: stage as [d][l_local] (64B per d), store transposed ----
        int kvh = (nh - 2560) >> 7;
#pragma unroll
        for (int i = 0; i < 2; i++) {
#pragma unroll
            for (int half = 0; half < 2; half++) {
                int rl = i * 16 + half * 8 + (lane >> 2);    // l_local 0..31
#pragma unroll
                for (int j = 0; j < 16; j++) {
                    int d = j * 8 + dq;
                    *(__half*)(wsm + d * 64 + rl * 2) =
                        __float2half_rn(acc[i][j][half * 2 + 0]);
                    *(__half*)(wsm + (d + 1) * 64 + rl * 2) =
                        __float2half_rn(acc[i][j][half * 2 + 1]);
                }
            }
        }
        __syncwarp();
        int b  = rowg0 >> 11;
        int l0 = rowg0 & (LSEQ - 1);
        __half* vb = g_vt16 + (size_t)(b * KV_HEADS + kvh) * DHEAD * LSEQ;
        // 4 d-rows per iteration, 8B per lane, 64B contiguous per d
#pragma unroll 4
        for (int it = 0; it < 32; it++) {
            int dd = it * 4 + (lane >> 3);
            *(uint2*)(vb + (size_t)dd * LSEQ + l0 + (lane & 7) * 4) =
                *(const uint2*)(wsm + dd * 64 + (lane & 7) * 8);
        }
    }
}

// ---------------------------------------------------------------------------
// Single fused conversion: x, Wq, Wk, Wv, Wo -> fp16 device globals
// Flat uint2-unit index with range dispatch.
// ---------------------------------------------------------------------------
#define XU  (BATCH * LSEQ * HIDDEN / 4)            // 2097152
#define WQU (2048 * HIDDEN / 4)                    // 1048576
#define WKU (512 * HIDDEN / 4)                     // 262144
#define WVU (512 * HIDDEN / 4)                     // 262144
#define WOU (HIDDEN * HIDDEN / 4)                  // 1048576
#define CVT_TOTAL (XU + WQU + WKU + WVU + WOU)

__global__ __launch_bounds__(256)
void cvt_all(const float4* __restrict__ x,  const float4* __restrict__ wq,
             const float4* __restrict__ wk, const float4* __restrict__ wv,
             const float4* __restrict__ wo)
{
    int i = blockIdx.x * 256 + threadIdx.x;
    if (i >= CVT_TOTAL) return;
    const float4* src;
    uint2* dst;
    if (i < XU)                   { src = x  + i;                    dst = (uint2*)g_x16  + i; }
    else if (i < XU + WQU)        { int j = i - XU;                  src = wq + j; dst = (uint2*)g_w16 + j; }
    else if (i < XU + WQU + WKU)  { int j = i - XU - WQU;            src = wk + j; dst = (uint2*)g_w16 + WQU + j; }
    else if (i < XU + WQU + WKU + WVU) { int j = i - XU - WQU - WKU; src = wv + j; dst = (uint2*)g_w16 + WQU + WKU + j; }
    else                          { int j = i - XU - WQU - WKU - WVU; src = wo + j; dst = (uint2*)g_wo16 + j; }
    float4 v = *src;
    *dst = make_uint2(pk2h(__float2half_rn(v.x), __float2half_rn(v.y)),
                      pk2h(__float2half_rn(v.z), __float2half_rn(v.w)));
}

// ---------------------------------------------------------------------------
// fp16 HMMA flash attention (proven R15): QK = Q*K; PV = P*V (all single)
// ---------------------------------------------------------------------------
#define AQT 128
#define AKC 64
#define A_Q 0
#define A_STG0 32768
#define A_STG_SZ 32768
#define AS_KH 0
#define AS_VH 16384
#define ATT_SMEM2 98304

__global__ __launch_bounds__(256, 1)
void attn_mma()
{
    extern __shared__ __align__(128) char asmem[];
    const uint32_t base = smem_u32(asmem);
    const int tid = threadIdx.x, lane = tid & 31, w = tid >> 5;
    const int qt = blockIdx.x, h = blockIdx.y, b = blockIdx.z;
    const int kvh = h >> 2;
    const int q0 = qt * AQT;

    {
        const __half* qp = g_q16 + ((size_t)(b * H_HEADS + h) * LSEQ + q0) * DHEAD;
#pragma unroll
        for (int i = 0; i < 8; i++) {
            int u = tid + 256 * i;
            int r = u >> 4, cu = u & 15;
            uint32_t so = (uint32_t)(cu >> 3) * 16384 + swz((uint32_t)(r * 128 + (cu & 7) * 16));
            cpa16(base + A_Q + so, qp + (size_t)r * DHEAD + cu * 8);
        }
        CPA_COMMIT();
    }

    int kstart = q0 - WIN;       if (kstart < 0)  kstart = 0;
    int kend   = q0 + AQT + WIN; if (kend > LSEQ) kend = LSEQ;
    const int nc = (kend - kstart) / AKC;

    const __half* kh  = g_k16  + (size_t)(b * KV_HEADS + kvh) * LSEQ * DHEAD;
    const __half* vth = g_vt16 + (size_t)(b * KV_HEADS + kvh) * DHEAD * LSEQ;

    auto load_kv = [&](int c, int s) {
        const uint32_t sb = base + A_STG0 + (uint32_t)s * A_STG_SZ;
        const int ks = kstart + c * AKC;
#pragma unroll
        for (int i = 0; i < 4; i++) {
            int u = tid + 256 * i;
            int r = u >> 4, cu = u & 15;
            uint32_t so = (uint32_t)(cu >> 3) * 8192 + swz((uint32_t)(r * 128 + (cu & 7) * 16));
            cpa16(sb + AS_KH + so, kh + (size_t)(ks + r) * DHEAD + cu * 8);
        }
#pragma unroll
        for (int i = 0; i < 4; i++) {
            int u = tid + 256 * i;
            int d = u >> 3, cu = u & 7;
            uint32_t so = swz((uint32_t)(d * 128 + cu * 16));
            cpa16(sb + AS_VH + so, vth + (size_t)d * LSEQ + ks + cu * 8);
        }
        CPA_COMMIT();
    };

    load_kv(0, 0);

    const int a_row  = w * 16 + (lane & 15);
    const int a_k    = (lane >> 4) * 8;
    const int b_rowg = (lane >> 4) * 8 + (lane & 7);
    const int b_k    = ((lane >> 3) & 1) * 8;
    const int r0     = lane >> 2, colb = 2 * (lane & 3);
    const int qrow0  = q0 + w * 16 + r0;
    const int qrow1  = qrow0 + 8;

    float out[16][4];
#pragma unroll
    for (int na = 0; na < 16; na++)
#pragma unroll
        for (int q = 0; q < 4; q++) out[na][q] = 0.0f;
    float m0 = -1e30f, m1 = -1e30f, l0s = 0.0f, l1s = 0.0f;

    for (int c = 0; c < nc; c++) {
        if (c + 1 < nc) { load_kv(c + 1, (c + 1) & 1); CPA_WAIT(1); }
        else            { CPA_WAIT(0); }
        __syncthreads();
        const uint32_t sb = base + A_STG0 + (uint32_t)(c & 1) * A_STG_SZ;

        float sacc[8][4];
#pragma unroll
        for (int j = 0; j < 8; j++)
#pragma unroll
            for (int q = 0; q < 4; q++) sacc[j][q] = 0.0f;

#pragma unroll
        for (int ks = 0; ks < 8; ks++) {
            int pnl = ks >> 2, kk = (ks & 3) * 16;
            uint32_t aoff = (uint32_t)pnl * 16384 + swz((uint32_t)(a_row * 128 + (kk + a_k) * 2));
            uint32_t aq[4];
            ldmx4(aq, base + A_Q + aoff);
#pragma unroll
            for (int jp = 0; jp < 4; jp++) {
                uint32_t boff = (uint32_t)pnl * 8192 +
                    swz((uint32_t)((jp * 16 + b_rowg) * 128 + (kk + b_k) * 2));
                uint32_t bkh[4];
                ldmx4(bkh, sb + AS_KH + boff);
                mma_f16(sacc[2 * jp],     aq, &bkh[0]);
                mma_f16(sacc[2 * jp + 1], aq, &bkh[2]);
            }
        }

        const int ks0 = kstart + c * AKC;
        float mx0 = -1e30f, mx1 = -1e30f;
#pragma unroll
        for (int j = 0; j < 8; j++) {
            int k0 = ks0 + j * 8 + colb, k1 = k0 + 1;
            int d00 = qrow0 - k0; if (d00 < 0) d00 = -d00;
            int d01 = qrow0 - k1; if (d01 < 0) d01 = -d01;
            int d10 = qrow1 - k0; if (d10 < 0) d10 = -d10;
            int d11 = qrow1 - k1; if (d11 < 0) d11 = -d11;
            if (d00 > WIN) sacc[j][0] = -1e30f;
            if (d01 > WIN) sacc[j][1] = -1e30f;
            if (d10 > WIN) sacc[j][2] = -1e30f;
            if (d11 > WIN) sacc[j][3] = -1e30f;
            mx0 = fmaxf(mx0, fmaxf(sacc[j][0], sacc[j][1]));
            mx1 = fmaxf(mx1, fmaxf(sacc[j][2], sacc[j][3]));
        }
        mx0 = fmaxf(mx0, __shfl_xor_sync(0xffffffffu, mx0, 1));
        mx0 = fmaxf(mx0, __shfl_xor_sync(0xffffffffu, mx0, 2));
        mx1 = fmaxf(mx1, __shfl_xor_sync(0xffffffffu, mx1, 1));
        mx1 = fmaxf(mx1, __shfl_xor_sync(0xffffffffu, mx1, 2));

        float mn0 = fmaxf(m0, mx0), mn1 = fmaxf(m1, mx1);
        float c0f = __expf(m0 - mn0), c1f = __expf(m1 - mn1);
        m0 = mn0; m1 = mn1;

        float rs0 = 0.0f, rs1 = 0.0f;
        uint32_t ph[8], ph2[8];
#pragma unroll
        for (int j = 0; j < 8; j++) {
            float p0 = (sacc[j][0] > -9e29f) ? __expf(sacc[j][0] - mn0) : 0.0f;
            float p1 = (sacc[j][1] > -9e29f) ? __expf(sacc[j][1] - mn0) : 0.0f;
            float p2 = (sacc[j][2] > -9e29f) ? __expf(sacc[j][2] - mn1) : 0.0f;
            float p3 = (sacc[j][3] > -9e29f) ? __expf(sacc[j][3] - mn1) : 0.0f;
            rs0 += p0 + p1; rs1 += p2 + p3;
            ph[j]  = pk2h(__float2half_rn(p0), __float2half_rn(p1));
            ph2[j] = pk2h(__float2half_rn(p2), __float2half_rn(p3));
        }
        rs0 += __shfl_xor_sync(0xffffffffu, rs0, 1);
        rs0 += __shfl_xor_sync(0xffffffffu, rs0, 2);
        rs1 += __shfl_xor_sync(0xffffffffu, rs1, 1);
        rs1 += __shfl_xor_sync(0xffffffffu, rs1, 2);
        l0s = l0s * c0f + rs0;
        l1s = l1s * c1f + rs1;
#pragma unroll
        for (int na = 0; na < 16; na++) {
            out[na][0] *= c0f; out[na][1] *= c0f;
            out[na][2] *= c1f; out[na][3] *= c1f;
        }

#pragma unroll
        for (int ks2 = 0; ks2 < 4; ks2++) {
            uint32_t Ahf[4] = { ph[2 * ks2], ph2[2 * ks2], ph[2 * ks2 + 1], ph2[2 * ks2 + 1] };
#pragma unroll
            for (int jp = 0; jp < 8; jp++) {
                uint32_t voff = swz((uint32_t)((jp * 16 + b_rowg) * 128 + (ks2 * 16 + b_k) * 2));
                uint32_t vh[4];
                ldmx4(vh, sb + AS_VH + voff);
                mma_f16(out[2 * jp],     Ahf, &vh[0]);
                mma_f16(out[2 * jp + 1], Ahf, &vh[2]);
            }
        }
        __syncthreads();
    }

    // epilogue: normalize, single-fp16 store (O-GEMM A operand)
    float inv0 = 1.0f / l0s, inv1 = 1.0f / l1s;
    size_t rb0 = ((size_t)b * LSEQ + qrow0) * HIDDEN + h * DHEAD;
    size_t rb1 = rb0 + (size_t)8 * HIDDEN;
#pragma unroll
    for (int na = 0; na < 16; na++) {
        int d = na * 8 + colb;
        *(uint32_t*)(g_ah16 + rb0 + d) = pk2h(__float2half_rn(out[na][0] * inv0),
                                              __float2half_rn(out[na][1] * inv0));
        *(uint32_t*)(g_ah16 + rb1 + d) = pk2h(__float2half_rn(out[na][2] * inv1),
                                              __float2half_rn(out[na][3] * inv1));
    }
}

// ---------------------------------------------------------------------------
// Launch. Inputs: x, cos, sin, Wq, Wk, Wv, Wo, q_norm_w, k_norm_w
// ---------------------------------------------------------------------------
extern "C" void kernel_launch(void* const* d_in, const int* in_sizes, int n_in,
                              void* d_out, int out_size)
{
    const float* x    = (const float*)d_in[0];
    const float* cosp = (const float*)d_in[1];
    const float* sinp = (const float*)d_in[2];
    const float* Wq   = (const float*)d_in[3];
    const float* Wk   = (const float*)d_in[4];
    const float* Wv   = (const float*)d_in[5];
    const float* Wo   = (const float*)d_in[6];
    const float* qw   = (const float*)d_in[7];
    const float* kw   = (const float*)d_in[8];
    float* out = (float*)d_out;

    void *p_x16, *p_w16, *p_wo16, *p_ah;
    cudaGetSymbolAddress(&p_x16,  g_x16);
    cudaGetSymbolAddress(&p_w16,  g_w16);
    cudaGetSymbolAddress(&p_wo16, g_wo16);
    cudaGetSymbolAddress(&p_ah,   g_ah16);

    cudaFuncSetAttribute(gemm_f16s, cudaFuncAttributeMaxDynamicSharedMemorySize, GEMMS_SMEM);
    cudaFuncSetAttribute(gemm_qkv_fused, cudaFuncAttributeMaxDynamicSharedMemorySize, GEMMS_SMEM);
    cudaFuncSetAttribute(attn_mma, cudaFuncAttributeMaxDynamicSharedMemorySize, ATT_SMEM2);

    // 1) single fused conversion launch (x + all weights -> fp16 globals)
    cvt_all<<<(CVT_TOTAL + 255) / 256, 256>>>(
        (const float4*)x, (const float4*)Wq, (const float4*)Wk,
        (const float4*)Wv, (const float4*)Wo);

    // 2) Fused QKV projection + RMSNorm + RoPE + V-transpose (fp16 out, staged)
    gemm_qkv_fused<<<dim3(BATCH * LSEQ / GMT, QKV_COLS / GNT), 256, GEMMS_SMEM>>>(
        (const __half*)p_x16, (const __half*)p_w16, cosp, sinp, qw, kw);

    // 3) fp16 HMMA sliding-window flash attention -> g_ah16
    attn_mma<<<dim3(LSEQ / AQT, H_HEADS, BATCH), 256, ATT_SMEM2>>>();

    // 4) Output projection (single fp16 HMMA) -> d_out
    gemm_f16s<<<dim3(BATCH * LSEQ / GMT, HIDDEN / GNT), 256, GEMMS_SMEM>>>(
        (const __half*)p_ah, (const __half*)p_wo16, out, HIDDEN);
}